// round 10
// baseline (speedup 1.0000x reference)
#include <cuda_runtime.h>
#include <cuda_bf16.h>
#include <math.h>
#include <stdint.h>

#define B    64
#define T    32
#define D    4096
#define C    50
#define A_   300
#define H    256
#define GI_W 1536

// ---------------------------------------------------------------------------
// Scratch
// ---------------------------------------------------------------------------
__device__ float g_GI[B * T * GI_W];
__device__ float g_feats[B * T * 512];
__device__ float g_attr1[C * 4096];
__device__ float g_attr2[C * 512];
__device__ float g_logits[B * C * T];
__device__ float g_cmax[T];
__device__ float g_csum[T];
__device__ float g_hbuf[2 * 2 * B * H];
__device__ float g_wih_pack[GI_W * D];
__device__ float g_bih_pack[GI_W];
__device__ __nv_bfloat16 g_w3hi[256 * 512];
__device__ __nv_bfloat16 g_w3lo[256 * 512];
__device__ float g_fc2part[4 * 64 * 512];
__device__ int   g_rmin[B * T];
__device__ int   g_rmout[B * T];
__device__ int   g_count[B];
__device__ int   g_mnz[1];
__device__ int          g_bar_count;
__device__ unsigned int g_bar_gen;

// ---------------------------------------------------------------------------
// tf32 / bf16 / sync helpers (proven)
// ---------------------------------------------------------------------------
__device__ __forceinline__ void mma8(float* c, const uint32_t* a, const uint32_t* b)
{
    asm volatile(
        "mma.sync.aligned.m16n8k8.row.col.f32.tf32.tf32.f32 "
        "{%0,%1,%2,%3},{%4,%5,%6,%7},{%8,%9},{%0,%1,%2,%3};"
        : "+f"(c[0]), "+f"(c[1]), "+f"(c[2]), "+f"(c[3])
        : "r"(a[0]), "r"(a[1]), "r"(a[2]), "r"(a[3]), "r"(b[0]), "r"(b[1]));
}

__device__ __forceinline__ void mma16(float* c, const uint32_t* a, const uint32_t* b)
{
    asm volatile(
        "mma.sync.aligned.m16n8k16.row.col.f32.bf16.bf16.f32 "
        "{%0,%1,%2,%3},{%4,%5,%6,%7},{%8,%9},{%0,%1,%2,%3};"
        : "+f"(c[0]), "+f"(c[1]), "+f"(c[2]), "+f"(c[3])
        : "r"(a[0]), "r"(a[1]), "r"(a[2]), "r"(a[3]), "r"(b[0]), "r"(b[1]));
}

__device__ __forceinline__ void split1(float v, float& h, float& l)
{
    uint32_t u;
    asm("cvt.rna.tf32.f32 %0, %1;" : "=r"(u) : "f"(v));
    h = __uint_as_float(u);
    l = v - h;
}
__device__ __forceinline__ void split4(float4 v, float4& h, float4& l)
{
    split1(v.x, h.x, l.x); split1(v.y, h.y, l.y);
    split1(v.z, h.z, l.z); split1(v.w, h.w, l.w);
}

__device__ __forceinline__ void bsplit2(float x, float y, uint32_t& hw, uint32_t& lw)
{
    __nv_bfloat16 hx = __float2bfloat16(x);
    __nv_bfloat16 hy = __float2bfloat16(y);
    float rx = x - __bfloat162float(hx);
    float ry = y - __bfloat162float(hy);
    __nv_bfloat162 hp; hp.x = hx; hp.y = hy;
    __nv_bfloat162 lp; lp.x = __float2bfloat16(rx); lp.y = __float2bfloat16(ry);
    hw = *reinterpret_cast<uint32_t*>(&hp);
    lw = *reinterpret_cast<uint32_t*>(&lp);
}

__device__ __forceinline__ unsigned ld_acq(const unsigned* p)
{
    unsigned v;
    asm volatile("ld.acquire.gpu.u32 %0,[%1];" : "=r"(v) : "l"(p) : "memory");
    return v;
}
__device__ __forceinline__ void st_rel(unsigned* p, unsigned v)
{
    asm volatile("st.release.gpu.u32 [%0],%1;" :: "l"(p), "r"(v) : "memory");
}

// ---------------------------------------------------------------------------
// 0a) Pack GRU input weights/biases (fp32, proven)
// ---------------------------------------------------------------------------
__global__ __launch_bounds__(256) void pack_wih(
    const float* __restrict__ wf, const float* __restrict__ wb,
    const float* __restrict__ bf, const float* __restrict__ bb,
    float* __restrict__ wp, float* __restrict__ bp)
{
    int i = blockIdx.x * 256 + threadIdx.x;
    const int TOT4 = GI_W * D / 4;
    if (i < TOT4) {
        int row = (i * 4) / D;
        float4 v;
        if (row < 768) v = ((const float4*)wf)[i];
        else           v = ((const float4*)wb)[i - 768 * (D / 4)];
        ((float4*)wp)[i] = v;
    }
    if (i < GI_W) bp[i] = (i < 768) ? bf[i] : bb[i - 768];
}

// 0b) Pre-split w3 to bf16 hi/lo (proven)
__global__ __launch_bounds__(256) void split_w3_bf16(
    const float* __restrict__ w3,
    __nv_bfloat16* __restrict__ hh, __nv_bfloat16* __restrict__ ll)
{
    int i = blockIdx.x * 256 + threadIdx.x;
    if (i < 256 * 512 / 2) {
        float2 v = ((const float2*)w3)[i];
        uint32_t h, l;
        bsplit2(v.x, v.y, h, l);
        ((uint32_t*)hh)[i] = h;
        ((uint32_t*)ll)[i] = l;
    }
}

// ---------------------------------------------------------------------------
// 1) Bookkeeping (proven)
// ---------------------------------------------------------------------------
__global__ void build_maps(
    const float* __restrict__ att,
    int* __restrict__ rmin, int* __restrict__ rmout,
    int* __restrict__ count, int* __restrict__ mnz)
{
    __shared__ int cnts[B], offs[B];
    int b = threadIdx.x;   // 64 threads
    float a[T];
    float s = 0.f;
#pragma unroll
    for (int t = 0; t < T; t++) { a[t] = att[b * T + t]; s += a[t]; }
    float thr = s / (float)T;
    int ord[T];
    int c = 0;
#pragma unroll
    for (int t = 0; t < T; t++) if (a[t] >= thr) ord[c++] = t;
    cnts[b] = c;
    __syncthreads();
    if (b == 0) {
        int acc = 0;
        for (int i = 0; i < B; i++) { offs[i] = acc; acc += cnts[i]; }
        *mnz = acc;
    }
    __syncthreads();
    int o = offs[b];
    for (int s2 = 0; s2 < c; s2++) {
        rmin[o + s2]  = b * T + ord[s2];
        rmout[o + s2] = b * T + s2;
    }
    count[b] = c;
}

// ---------------------------------------------------------------------------
// 2) GI projection, tensor cores, 3xTF32, 128x128 block tile.
//    Proven load->sync->compute->sync skeleton; warp tile 32x64
//    (wm 0-3, wn 0-1) — the fragment layout proven in relation_bf16.
// ---------------------------------------------------------------------------
__global__ __launch_bounds__(256, 2) void gemm_mma_gi(
    const float* __restrict__ A,
    const float* __restrict__ W,
    const float* __restrict__ bias,
    float* __restrict__ Cg,
    const int* __restrict__ rmin,
    const int* __restrict__ rmout,
    const int* __restrict__ mnzp)
{
    int Mnz = *mnzp;
    int row0 = blockIdx.y * 128, col0 = blockIdx.x * 128;
    if (row0 >= Mnz) return;

    __shared__ float Ah[128][20], Al[128][20], Wh[128][20], Wl[128][20];
    int tid  = threadIdx.x;
    int lane = tid & 31, warp = tid >> 5;
    int wm = warp >> 1, wn = warp & 1;     // wm 0..3, wn 0..1
    int g  = lane >> 2, tg = lane & 3;

    float c[2][8][4];
#pragma unroll
    for (int mt = 0; mt < 2; mt++)
#pragma unroll
        for (int nt = 0; nt < 8; nt++)
#pragma unroll
            for (int r = 0; r < 4; r++) c[mt][nt][r] = 0.f;

    int lr = tid >> 1;            // 0..127
    int lk = (tid & 1) * 8;
    int m  = row0 + lr;
    bool av = (m < Mnz);
    const float* asrc = A + (size_t)(av ? rmin[m] : 0) * D;
    const float* wsrc = W + (size_t)(col0 + lr) * D;

    for (int k0 = 0; k0 < D; k0 += 16) {
        {
            float4 v0 = make_float4(0.f, 0.f, 0.f, 0.f), v1 = v0;
            if (av) {
                v0 = *(const float4*)(asrc + k0 + lk);
                v1 = *(const float4*)(asrc + k0 + lk + 4);
            }
            float4 h, l;
            split4(v0, h, l);
            *(float4*)&Ah[lr][lk] = h; *(float4*)&Al[lr][lk] = l;
            split4(v1, h, l);
            *(float4*)&Ah[lr][lk + 4] = h; *(float4*)&Al[lr][lk + 4] = l;
        }
        {
            float4 v0 = *(const float4*)(wsrc + k0 + lk);
            float4 v1 = *(const float4*)(wsrc + k0 + lk + 4);
            float4 h, l;
            split4(v0, h, l);
            *(float4*)&Wh[lr][lk] = h; *(float4*)&Wl[lr][lk] = l;
            split4(v1, h, l);
            *(float4*)&Wh[lr][lk + 4] = h; *(float4*)&Wl[lr][lk + 4] = l;
        }
        __syncthreads();

#pragma unroll
        for (int ks = 0; ks < 2; ks++) {
            int kb = ks * 8;
            uint32_t ah[2][4], al[2][4];
#pragma unroll
            for (int mt = 0; mt < 2; mt++) {
                int m0 = wm * 32 + mt * 16;
                ah[mt][0] = __float_as_uint(Ah[m0 + g][kb + tg]);
                ah[mt][1] = __float_as_uint(Ah[m0 + g + 8][kb + tg]);
                ah[mt][2] = __float_as_uint(Ah[m0 + g][kb + tg + 4]);
                ah[mt][3] = __float_as_uint(Ah[m0 + g + 8][kb + tg + 4]);
                al[mt][0] = __float_as_uint(Al[m0 + g][kb + tg]);
                al[mt][1] = __float_as_uint(Al[m0 + g + 8][kb + tg]);
                al[mt][2] = __float_as_uint(Al[m0 + g][kb + tg + 4]);
                al[mt][3] = __float_as_uint(Al[m0 + g + 8][kb + tg + 4]);
            }
#pragma unroll
            for (int nt = 0; nt < 8; nt++) {
                int n0 = wn * 64 + nt * 8;
                uint32_t bh[2], bl[2];
                bh[0] = __float_as_uint(Wh[n0 + g][kb + tg]);
                bh[1] = __float_as_uint(Wh[n0 + g][kb + tg + 4]);
                bl[0] = __float_as_uint(Wl[n0 + g][kb + tg]);
                bl[1] = __float_as_uint(Wl[n0 + g][kb + tg + 4]);
#pragma unroll
                for (int mt = 0; mt < 2; mt++) {
                    mma8(c[mt][nt], ah[mt], bh);
                    mma8(c[mt][nt], al[mt], bh);
                    mma8(c[mt][nt], ah[mt], bl);
                }
            }
        }
        __syncthreads();
    }

#pragma unroll
    for (int mt = 0; mt < 2; mt++) {
        int mrow1 = row0 + wm * 32 + mt * 16 + g;
        int mrow2 = mrow1 + 8;
        int ro1 = (mrow1 < Mnz) ? rmout[mrow1] : -1;
        int ro2 = (mrow2 < Mnz) ? rmout[mrow2] : -1;
#pragma unroll
        for (int nt = 0; nt < 8; nt++) {
            int col = col0 + wn * 64 + nt * 8 + 2 * tg;
            float b0 = bias[col], b1 = bias[col + 1];
            if (ro1 >= 0)
                *(float2*)(Cg + (size_t)ro1 * GI_W + col) =
                    make_float2(c[mt][nt][0] + b0, c[mt][nt][1] + b1);
            if (ro2 >= 0)
                *(float2*)(Cg + (size_t)ro2 * GI_W + col) =
                    make_float2(c[mt][nt][2] + b0, c[mt][nt][3] + b1);
        }
    }
}

// ---------------------------------------------------------------------------
// 2b) Small-M GEMM (fc1) and fc2 K-split (proven)
// ---------------------------------------------------------------------------
template <bool RELU>
__global__ __launch_bounds__(256) void gemm_tn(
    const float* __restrict__ Ag, int lda,
    const float* __restrict__ Wg, int ldw,
    const float* __restrict__ bias,
    float* __restrict__ Cg, int ldc,
    int M, int N, int K)
{
    __shared__ float As[16][65];
    __shared__ float Ws[16][65];
    int tid  = threadIdx.x;
    int row0 = blockIdx.y * 64;
    int col0 = blockIdx.x * 64;
    int lm = tid >> 2;
    int lk = (tid & 3) * 4;
    int ty = tid >> 4;
    int tx = tid & 15;
    float acc[4][4];
#pragma unroll
    for (int i = 0; i < 4; i++)
#pragma unroll
        for (int j = 0; j < 4; j++) acc[i][j] = 0.f;

    for (int k0 = 0; k0 < K; k0 += 16) {
        int r = row0 + lm;
        int cc = col0 + lm;
#pragma unroll
        for (int i = 0; i < 4; i++) {
            int k = k0 + lk + i;
            As[lk + i][lm] = (r < M && k < K) ? Ag[(size_t)r * lda + k] : 0.f;
            Ws[lk + i][lm] = (cc < N && k < K) ? Wg[(size_t)cc * ldw + k] : 0.f;
        }
        __syncthreads();
#pragma unroll
        for (int kk = 0; kk < 16; kk++) {
            float a[4], w[4];
#pragma unroll
            for (int i = 0; i < 4; i++) a[i] = As[kk][ty + 16 * i];
#pragma unroll
            for (int j = 0; j < 4; j++) w[j] = Ws[kk][tx + 16 * j];
#pragma unroll
            for (int i = 0; i < 4; i++)
#pragma unroll
                for (int j = 0; j < 4; j++)
                    acc[i][j] = fmaf(a[i], w[j], acc[i][j]);
        }
        __syncthreads();
    }

#pragma unroll
    for (int i = 0; i < 4; i++) {
        int r = row0 + ty + 16 * i;
        if (r >= M) continue;
#pragma unroll
        for (int j = 0; j < 4; j++) {
            int cc = col0 + tx + 16 * j;
            if (cc >= N) continue;
            float v = acc[i][j] + bias[cc];
            if (RELU) v = fmaxf(v, 0.f);
            Cg[(size_t)r * ldc + cc] = v;
        }
    }
}

__global__ __launch_bounds__(256) void fc2_part(
    const float* __restrict__ Ag,
    const float* __restrict__ Wg,
    float* __restrict__ Pout)
{
    __shared__ float As[16][65];
    __shared__ float Ws[16][65];
    int tid  = threadIdx.x;
    int col0 = blockIdx.x * 64;
    int kbeg = blockIdx.y * 1024;
    int lm = tid >> 2;
    int lk = (tid & 3) * 4;
    int ty = tid >> 4;
    int tx = tid & 15;
    float acc[4][4];
#pragma unroll
    for (int i = 0; i < 4; i++)
#pragma unroll
        for (int j = 0; j < 4; j++) acc[i][j] = 0.f;

    for (int k0 = kbeg; k0 < kbeg + 1024; k0 += 16) {
        int cc = col0 + lm;
#pragma unroll
        for (int i = 0; i < 4; i++) {
            int k = k0 + lk + i;
            As[lk + i][lm] = (lm < C) ? Ag[(size_t)lm * 4096 + k] : 0.f;
            Ws[lk + i][lm] = Wg[(size_t)cc * 4096 + k];
        }
        __syncthreads();
#pragma unroll
        for (int kk = 0; kk < 16; kk++) {
            float a[4], w[4];
#pragma unroll
            for (int i = 0; i < 4; i++) a[i] = As[kk][ty + 16 * i];
#pragma unroll
            for (int j = 0; j < 4; j++) w[j] = Ws[kk][tx + 16 * j];
#pragma unroll
            for (int i = 0; i < 4; i++)
#pragma unroll
                for (int j = 0; j < 4; j++)
                    acc[i][j] = fmaf(a[i], w[j], acc[i][j]);
        }
        __syncthreads();
    }

    float* base = Pout + (size_t)blockIdx.y * (64 * 512);
#pragma unroll
    for (int i = 0; i < 4; i++) {
        int r = ty + 16 * i;
        if (r >= C) continue;
#pragma unroll
        for (int j = 0; j < 4; j++) {
            int cc = col0 + tx + 16 * j;
            base[(size_t)r * 512 + cc] = acc[i][j];
        }
    }
}

__global__ __launch_bounds__(256) void fc2_reduce(
    const float* __restrict__ P, const float* __restrict__ bias,
    float* __restrict__ attr2)
{
    int idx = blockIdx.x * 256 + threadIdx.x;
    if (idx < C * 512) {
        int r = idx >> 9, cc = idx & 511;
        float v = bias[cc];
#pragma unroll
        for (int kc = 0; kc < 4; kc++)
            v += P[(size_t)kc * (64 * 512) + r * 512 + cc];
        attr2[idx] = fmaxf(v, 0.f);
    }
}

// ---------------------------------------------------------------------------
// 3) GRU recurrence (proven, byte-identical)
// ---------------------------------------------------------------------------
#define GRU_BLOCKS 128

__device__ __forceinline__ void grid_barrier()
{
    __syncthreads();
    if (threadIdx.x == 0) {
        __threadfence();
        unsigned g = ld_acq(&g_bar_gen);
        if (atomicAdd(&g_bar_count, 1) == GRU_BLOCKS - 1) {
            g_bar_count = 0;
            st_rel(&g_bar_gen, g + 1);
        } else {
            while (ld_acq(&g_bar_gen) == g) { __nanosleep(16); }
        }
    }
    __syncthreads();
}

__global__ __launch_bounds__(256) void gru_kernel(
    const float* __restrict__ GI,
    const float* __restrict__ whh_f, const float* __restrict__ whh_b,
    const float* __restrict__ bhh_f, const float* __restrict__ bhh_b,
    const float* __restrict__ bpack,
    const int*   __restrict__ count,
    float* __restrict__ feats)
{
    extern __shared__ float4 sm4[];
    float4* sW4 = sm4;
    float4* hS4 = sm4 + 12 * 65;

    int d  = blockIdx.x >> 6;
    int hc = blockIdx.x & 63;
    int tid = threadIdx.x;
    int b = tid >> 2;
    int u = tid & 3;
    int i = hc * 4 + u;

    const float* whh = d ? whh_b : whh_f;
    const float* bhh = d ? bhh_b : bhh_f;

    for (int t = tid; t < 12 * 64; t += 256) {
        int rr = t >> 6;
        int k4 = t & 63;
        int g  = rr >> 2, uu = rr & 3;
        int row = g * H + hc * 4 + uu;
        sW4[rr * 65 + k4] = ((const float4*)(whh + (size_t)row * H))[k4];
    }
    float br = bhh[i], bz = bhh[H + i], bn = bhh[2 * H + i];
    float ir0 = bpack[d * 768 + i];
    float iz0 = bpack[d * 768 + 256 + i];
    float in0 = bpack[d * 768 + 512 + i];
    int cnt_b = count[b];
    __syncthreads();

    float h = 0.f;

    for (int t = 0; t < T; t++) {
        float ar = 0.f, az = 0.f, an = 0.f;
        if (t > 0) {
            int p = t & 1;
            const float4* hp4 = (const float4*)(g_hbuf + p * (2 * B * H) + d * (B * H));
            for (int idx = tid; idx < B * (H / 4); idx += 256)
                hS4[(idx >> 6) * 65 + (idx & 63)] = __ldcg(&hp4[idx]);
            __syncthreads();

            const float4* hb = &hS4[b * 65];
            const float4* wr = &sW4[(0 + u) * 65];
            const float4* wz = &sW4[(4 + u) * 65];
            const float4* wn = &sW4[(8 + u) * 65];
#pragma unroll 16
            for (int k4 = 0; k4 < 64; k4++) {
                float4 hv = hb[k4];
                float4 a  = wr[k4];
                ar = fmaf(hv.x, a.x, fmaf(hv.y, a.y, fmaf(hv.z, a.z, fmaf(hv.w, a.w, ar))));
                float4 zz = wz[k4];
                az = fmaf(hv.x, zz.x, fmaf(hv.y, zz.y, fmaf(hv.z, zz.z, fmaf(hv.w, zz.w, az))));
                float4 nn = wn[k4];
                an = fmaf(hv.x, nn.x, fmaf(hv.y, nn.y, fmaf(hv.z, nn.z, fmaf(hv.w, nn.w, an))));
            }
        }

        int s = d ? (T - 1 - t) : t;
        float ir = ir0, iz = iz0, in_ = in0;
        if (s < cnt_b) {
            const float* gi = GI + ((size_t)b * T + s) * GI_W + d * 768;
            ir  = gi[i];
            iz  = gi[H + i];
            in_ = gi[2 * H + i];
        }

        float r = 1.f / (1.f + expf(-(ir + ar + br)));
        float z = 1.f / (1.f + expf(-(iz + az + bz)));
        float n = tanhf(in_ + r * (an + bn));
        h = (1.f - z) * n + z * h;

        feats[((size_t)b * T + s) * 512 + d * H + i] = h;
        if (t < T - 1) {
            g_hbuf[((t & 1) ^ 1) * (2 * B * H) + d * (B * H) + b * H + i] = h;
            grid_barrier();
        }
    }
}

// ---------------------------------------------------------------------------
// 4) Relation head, bf16 3-split tensor cores (proven, byte-identical)
// ---------------------------------------------------------------------------
__global__ __launch_bounds__(256, 2) void relation_bf16(
    const float* __restrict__ feats,
    const float* __restrict__ attr2,
    const __nv_bfloat16* __restrict__ w3hi,
    const __nv_bfloat16* __restrict__ w3lo,
    const float* __restrict__ b3,
    const float* __restrict__ w4,
    const float* __restrict__ b4,
    float* __restrict__ logits)
{
    __shared__ uint32_t Dh_s[64 * 12], Dl_s[64 * 12];
    __shared__ uint32_t Wh_s[256 * 12], Wl_s[256 * 12];
    __shared__ float aS[2 * 512];
    __shared__ float part[64][5];

    int c0 = blockIdx.x * 2;
    int b  = blockIdx.y;
    int tid  = threadIdx.x;
    int lane = tid & 31, warp = tid >> 5;
    int wm = warp >> 2, wn = warp & 3;
    int g  = lane >> 2, tg = lane & 3;

    for (int t = tid; t < 1024; t += 256)
        aS[t] = attr2[(size_t)(c0 + (t >> 9)) * 512 + (t & 511)];
    __syncthreads();

    float c[2][8][4];
#pragma unroll
    for (int mt = 0; mt < 2; mt++)
#pragma unroll
        for (int nt = 0; nt < 8; nt++)
#pragma unroll
            for (int r = 0; r < 4; r++) c[mt][nt][r] = 0.f;

    int dm = tid >> 2;
    int dk = (tid & 3) * 4;
    int ds = dm & 31, dc = dm >> 5;
    const float* frow = feats + ((size_t)b * T + ds) * 512;
    const __nv_bfloat16* w3h_row = w3hi + (size_t)tid * 512;
    const __nv_bfloat16* w3l_row = w3lo + (size_t)tid * 512;

    for (int k0 = 0; k0 < 512; k0 += 16) {
        {
            float4 f = *(const float4*)(frow + k0 + dk);
            float4 a = *(const float4*)(aS + dc * 512 + k0 + dk);
            float d0 = f.x - a.x, d1 = f.y - a.y;
            float d2 = f.z - a.z, d3 = f.w - a.w;
            uint32_t h0, l0, h1, l1;
            bsplit2(d0 * d0, d1 * d1, h0, l0);
            bsplit2(d2 * d2, d3 * d3, h1, l1);
            int w = (tid & 3) * 2;
            Dh_s[dm * 12 + w]     = h0;
            Dh_s[dm * 12 + w + 1] = h1;
            Dl_s[dm * 12 + w]     = l0;
            Dl_s[dm * 12 + w + 1] = l1;
        }
        {
            uint4 wh0 = ((const uint4*)(w3h_row + k0))[0];
            uint4 wh1 = ((const uint4*)(w3h_row + k0))[1];
            uint4 wl0 = ((const uint4*)(w3l_row + k0))[0];
            uint4 wl1 = ((const uint4*)(w3l_row + k0))[1];
            *(uint4*)&Wh_s[tid * 12 + 0] = wh0;
            *(uint4*)&Wh_s[tid * 12 + 4] = wh1;
            *(uint4*)&Wl_s[tid * 12 + 0] = wl0;
            *(uint4*)&Wl_s[tid * 12 + 4] = wl1;
        }
        __syncthreads();

        uint32_t a_h[2][4], a_l[2][4];
#pragma unroll
        for (int mt = 0; mt < 2; mt++) {
            int m0 = wm * 32 + mt * 16;
            a_h[mt][0] = Dh_s[(m0 + g) * 12 + tg];
            a_h[mt][1] = Dh_s[(m0 + g + 8) * 12 + tg];
            a_h[mt][2] = Dh_s[(m0 + g) * 12 + tg + 4];
            a_h[mt][3] = Dh_s[(m0 + g + 8) * 12 + tg + 4];
            a_l[mt][0] = Dl_s[(m0 + g) * 12 + tg];
            a_l[mt][1] = Dl_s[(m0 + g + 8) * 12 + tg];
            a_l[mt][2] = Dl_s[(m0 + g) * 12 + tg + 4];
            a_l[mt][3] = Dl_s[(m0 + g + 8) * 12 + tg + 4];
        }
#pragma unroll
        for (int nt = 0; nt < 8; nt++) {
            int n0 = wn * 64 + nt * 8;
            uint32_t bh[2], bl[2];
            bh[0] = Wh_s[(n0 + g) * 12 + tg];
            bh[1] = Wh_s[(n0 + g) * 12 + tg + 4];
            bl[0] = Wl_s[(n0 + g) * 12 + tg];
            bl[1] = Wl_s[(n0 + g) * 12 + tg + 4];
#pragma unroll
            for (int mt = 0; mt < 2; mt++) {
                mma16(c[mt][nt], a_h[mt], bh);
                mma16(c[mt][nt], a_l[mt], bh);
                mma16(c[mt][nt], a_h[mt], bl);
            }
        }
        __syncthreads();
    }

    float rs[2][2] = {{0.f, 0.f}, {0.f, 0.f}};
#pragma unroll
    for (int nt = 0; nt < 8; nt++) {
        int col = wn * 64 + nt * 8 + 2 * tg;
        float w40 = w4[col], w41 = w4[col + 1];
        float b30 = b3[col], b31 = b3[col + 1];
#pragma unroll
        for (int mt = 0; mt < 2; mt++) {
            rs[mt][0] += fmaxf(c[mt][nt][0] + b30, 0.f) * w40
                       + fmaxf(c[mt][nt][1] + b31, 0.f) * w41;
            rs[mt][1] += fmaxf(c[mt][nt][2] + b30, 0.f) * w40
                       + fmaxf(c[mt][nt][3] + b31, 0.f) * w41;
        }
    }
#pragma unroll
    for (int mt = 0; mt < 2; mt++)
#pragma unroll
        for (int hf2 = 0; hf2 < 2; hf2++) {
            float v = rs[mt][hf2];
            v += __shfl_xor_sync(0xffffffffu, v, 1);
            v += __shfl_xor_sync(0xffffffffu, v, 2);
            if (tg == 0)
                part[wm * 32 + mt * 16 + g + hf2 * 8][wn] = v;
        }
    __syncthreads();
    if (tid < 64) {
        float s = b4[0] + part[tid][0] + part[tid][1] + part[tid][2] + part[tid][3];
        int cc = c0 + (tid >> 5), ss = tid & 31;
        logits[((size_t)b * C + cc) * T + ss] = s;
    }
}

// ---------------------------------------------------------------------------
// 5) Softmax over dim-0 per column, mean over columns (proven)
// ---------------------------------------------------------------------------
__global__ __launch_bounds__(256) void softmax_colreduce(
    const float* __restrict__ logits, float* __restrict__ cmax, float* __restrict__ csum)
{
    int t = blockIdx.x;
    int tid = threadIdx.x;
    __shared__ float red[256];
    float m = -1e30f;
    for (int i = tid; i < B * C; i += 256) m = fmaxf(m, logits[(size_t)i * T + t]);
    red[tid] = m; __syncthreads();
    for (int s = 128; s > 0; s >>= 1) {
        if (tid < s) red[tid] = fmaxf(red[tid], red[tid + s]);
        __syncthreads();
    }
    float mx = red[0];
    __syncthreads();
    float sum = 0.f;
    for (int i = tid; i < B * C; i += 256) sum += expf(logits[(size_t)i * T + t] - mx);
    red[tid] = sum; __syncthreads();
    for (int s = 128; s > 0; s >>= 1) {
        if (tid < s) red[tid] += red[tid + s];
        __syncthreads();
    }
    if (tid == 0) { cmax[t] = mx; csum[t] = red[0]; }
}

__global__ __launch_bounds__(256) void softmax_out(
    const float* __restrict__ logits, const float* __restrict__ cmax,
    const float* __restrict__ csum, float* __restrict__ out)
{
    __shared__ float mS[T], sS[T];
    int tid = threadIdx.x;
    if (tid < T) { mS[tid] = cmax[tid]; sS[tid] = csum[tid]; }
    __syncthreads();
    int i = blockIdx.x * 256 + tid;
    if (i < B * C) {
        float a = 0.f;
        const float* row = logits + (size_t)i * T;
#pragma unroll
        for (int t = 0; t < T; t++) a += expf(row[t] - mS[t]) / sS[t];
        out[i] = a * (1.f / (float)T);
    }
}

// ---------------------------------------------------------------------------
// Launch
// ---------------------------------------------------------------------------
extern "C" void kernel_launch(void* const* d_in, const int* in_sizes, int n_in,
                              void* d_out, int out_size)
{
    const float* batch_features  = (const float*)d_in[0];
    const float* batch_att       = (const float*)d_in[1];
    const float* batch_attrs     = (const float*)d_in[2];
    const float* fc1_w = (const float*)d_in[3];
    const float* fc1_b = (const float*)d_in[4];
    const float* fc2_w = (const float*)d_in[5];
    const float* fc2_b = (const float*)d_in[6];
    const float* fc3_w = (const float*)d_in[7];
    const float* fc3_b = (const float*)d_in[8];
    const float* fc4_w = (const float*)d_in[9];
    const float* fc4_b = (const float*)d_in[10];
    const float* gru_wih_f = (const float*)d_in[11];
    const float* gru_whh_f = (const float*)d_in[12];
    const float* gru_bih_f = (const float*)d_in[13];
    const float* gru_bhh_f = (const float*)d_in[14];
    const float* gru_wih_b = (const float*)d_in[15];
    const float* gru_whh_b = (const float*)d_in[16];
    const float* gru_bih_b = (const float*)d_in[17];
    const float* gru_bhh_b = (const float*)d_in[18];
    float* out = (float*)d_out;

    float* GI;     cudaGetSymbolAddress((void**)&GI,     g_GI);
    float* feats;  cudaGetSymbolAddress((void**)&feats,  g_feats);
    float* attr1;  cudaGetSymbolAddress((void**)&attr1,  g_attr1);
    float* attr2;  cudaGetSymbolAddress((void**)&attr2,  g_attr2);
    float* logits; cudaGetSymbolAddress((void**)&logits, g_logits);
    float* cmax;   cudaGetSymbolAddress((void**)&cmax,   g_cmax);
    float* csum;   cudaGetSymbolAddress((void**)&csum,   g_csum);
    float* wpack;  cudaGetSymbolAddress((void**)&wpack,  g_wih_pack);
    float* bpack;  cudaGetSymbolAddress((void**)&bpack,  g_bih_pack);
    __nv_bfloat16* w3hi; cudaGetSymbolAddress((void**)&w3hi, g_w3hi);
    __nv_bfloat16* w3lo; cudaGetSymbolAddress((void**)&w3lo, g_w3lo);
    float* fc2p;   cudaGetSymbolAddress((void**)&fc2p,   g_fc2part);
    int* rmin;     cudaGetSymbolAddress((void**)&rmin,   g_rmin);
    int* rmout;    cudaGetSymbolAddress((void**)&rmout,  g_rmout);
    int* cnt;      cudaGetSymbolAddress((void**)&cnt,    g_count);
    int* mnz;      cudaGetSymbolAddress((void**)&mnz,    g_mnz);

    build_maps<<<1, 64>>>(batch_att, rmin, rmout, cnt, mnz);
    pack_wih<<<(GI_W * D / 4 + 255) / 256, 256>>>(gru_wih_f, gru_wih_b,
                                                  gru_bih_f, gru_bih_b, wpack, bpack);
    split_w3_bf16<<<(256 * 512 / 2 + 255) / 256, 256>>>(fc3_w, w3hi, w3lo);

    // GI projection (tensor cores, 3xTF32, 128x128 tiles, compacted rows)
    {
        dim3 grid(GI_W / 128, (B * T) / 128);   // (12, 16); ~half exit early
        gemm_mma_gi<<<grid, 256>>>(batch_features, wpack, bpack, GI, rmin, rmout, mnz);
    }

    // GRU recurrence
    {
        int smem = (12 * 65 + 64 * 65) * (int)sizeof(float4);
        cudaFuncSetAttribute(gru_kernel, cudaFuncAttributeMaxDynamicSharedMemorySize, smem);
        gru_kernel<<<GRU_BLOCKS, 256, smem>>>(GI, gru_whh_f, gru_whh_b,
                                              gru_bhh_f, gru_bhh_b, bpack, cnt, feats);
    }

    // semantic net
    gemm_tn<true><<<dim3(4096 / 64, 1), 256>>>(batch_attrs, A_, fc1_w, A_, fc1_b,
                                               attr1, 4096, C, 4096, A_);
    fc2_part<<<dim3(8, 4), 256>>>(attr1, fc2_w, fc2p);
    fc2_reduce<<<(C * 512 + 255) / 256, 256>>>(fc2p, fc2_b, attr2);

    // relation head (bf16 3-split, proven)
    relation_bf16<<<dim3(C / 2, B), 256>>>(feats, attr2, w3hi, w3lo,
                                           fc3_b, fc4_w, fc4_b, logits);

    softmax_colreduce<<<T, 256>>>(logits, cmax, csum);
    softmax_out<<<(B * C + 255) / 256, 256>>>(logits, cmax, csum, out);
}

// round 11
// speedup vs baseline: 1.1193x; 1.1193x over previous
#include <cuda_runtime.h>
#include <cuda_bf16.h>
#include <math.h>
#include <stdint.h>

#define B    64
#define T    32
#define D    4096
#define C    50
#define A_   300
#define H    256
#define GI_W 1536

// ---------------------------------------------------------------------------
// Scratch
// ---------------------------------------------------------------------------
__device__ float g_GI[B * T * GI_W];
__device__ float g_feats[B * T * 512];
__device__ float g_attr1[C * 4096];
__device__ float g_attr2[C * 512];
__device__ float g_logits[B * C * T];
__device__ float g_cmax[T];
__device__ float g_csum[T];
__device__ float g_hbuf[2 * 2 * B * H];
__device__ float g_wih_pack[GI_W * D];
__device__ float g_bih_pack[GI_W];
__device__ __nv_bfloat16 g_w3hi[256 * 512];
__device__ __nv_bfloat16 g_w3lo[256 * 512];
__device__ float g_fc2part[4 * 64 * 512];
__device__ int   g_rmin[B * T];
__device__ int   g_rmout[B * T];
__device__ int   g_count[B];
__device__ int   g_mnz[1];
__device__ int          g_bar_count;
__device__ unsigned int g_bar_gen;

// ---------------------------------------------------------------------------
// bf16 / sync helpers (proven)
// ---------------------------------------------------------------------------
__device__ __forceinline__ void mma16(float* c, const uint32_t* a, const uint32_t* b)
{
    asm volatile(
        "mma.sync.aligned.m16n8k16.row.col.f32.bf16.bf16.f32 "
        "{%0,%1,%2,%3},{%4,%5,%6,%7},{%8,%9},{%0,%1,%2,%3};"
        : "+f"(c[0]), "+f"(c[1]), "+f"(c[2]), "+f"(c[3])
        : "r"(a[0]), "r"(a[1]), "r"(a[2]), "r"(a[3]), "r"(b[0]), "r"(b[1]));
}

__device__ __forceinline__ void bsplit2(float x, float y, uint32_t& hw, uint32_t& lw)
{
    __nv_bfloat16 hx = __float2bfloat16(x);
    __nv_bfloat16 hy = __float2bfloat16(y);
    float rx = x - __bfloat162float(hx);
    float ry = y - __bfloat162float(hy);
    __nv_bfloat162 hp; hp.x = hx; hp.y = hy;
    __nv_bfloat162 lp; lp.x = __float2bfloat16(rx); lp.y = __float2bfloat16(ry);
    hw = *reinterpret_cast<uint32_t*>(&hp);
    lw = *reinterpret_cast<uint32_t*>(&lp);
}

__device__ __forceinline__ unsigned ld_acq(const unsigned* p)
{
    unsigned v;
    asm volatile("ld.acquire.gpu.u32 %0,[%1];" : "=r"(v) : "l"(p) : "memory");
    return v;
}
__device__ __forceinline__ void st_rel(unsigned* p, unsigned v)
{
    asm volatile("st.release.gpu.u32 [%0],%1;" :: "l"(p), "r"(v) : "memory");
}

// ---------------------------------------------------------------------------
// 0a) Pack GRU input weights/biases (fp32, proven)
// ---------------------------------------------------------------------------
__global__ __launch_bounds__(256) void pack_wih(
    const float* __restrict__ wf, const float* __restrict__ wb,
    const float* __restrict__ bf, const float* __restrict__ bb,
    float* __restrict__ wp, float* __restrict__ bp)
{
    int i = blockIdx.x * 256 + threadIdx.x;
    const int TOT4 = GI_W * D / 4;
    if (i < TOT4) {
        int row = (i * 4) / D;
        float4 v;
        if (row < 768) v = ((const float4*)wf)[i];
        else           v = ((const float4*)wb)[i - 768 * (D / 4)];
        ((float4*)wp)[i] = v;
    }
    if (i < GI_W) bp[i] = (i < 768) ? bf[i] : bb[i - 768];
}

// 0b) Pre-split w3 to bf16 hi/lo (proven)
__global__ __launch_bounds__(256) void split_w3_bf16(
    const float* __restrict__ w3,
    __nv_bfloat16* __restrict__ hh, __nv_bfloat16* __restrict__ ll)
{
    int i = blockIdx.x * 256 + threadIdx.x;
    if (i < 256 * 512 / 2) {
        float2 v = ((const float2*)w3)[i];
        uint32_t h, l;
        bsplit2(v.x, v.y, h, l);
        ((uint32_t*)hh)[i] = h;
        ((uint32_t*)ll)[i] = l;
    }
}

// ---------------------------------------------------------------------------
// 1) Bookkeeping (proven)
// ---------------------------------------------------------------------------
__global__ void build_maps(
    const float* __restrict__ att,
    int* __restrict__ rmin, int* __restrict__ rmout,
    int* __restrict__ count, int* __restrict__ mnz)
{
    __shared__ int cnts[B], offs[B];
    int b = threadIdx.x;   // 64 threads
    float a[T];
    float s = 0.f;
#pragma unroll
    for (int t = 0; t < T; t++) { a[t] = att[b * T + t]; s += a[t]; }
    float thr = s / (float)T;
    int ord[T];
    int c = 0;
#pragma unroll
    for (int t = 0; t < T; t++) if (a[t] >= thr) ord[c++] = t;
    cnts[b] = c;
    __syncthreads();
    if (b == 0) {
        int acc = 0;
        for (int i = 0; i < B; i++) { offs[i] = acc; acc += cnts[i]; }
        *mnz = acc;
    }
    __syncthreads();
    int o = offs[b];
    for (int s2 = 0; s2 < c; s2++) {
        rmin[o + s2]  = b * T + ord[s2];
        rmout[o + s2] = b * T + s2;
    }
    count[b] = c;
}

// ---------------------------------------------------------------------------
// 2) GI projection: bf16 3-split, NO prefetch, loads in-loop — the exact
//    skeleton of the round-7-passing tf32 kernel with only the smem format
//    (packed bf16, pitch-12) and MMA core (mma16) changed. Block 128x64.
// ---------------------------------------------------------------------------
__global__ __launch_bounds__(256, 2) void gemm_bf16_gi(
    const float* __restrict__ A,
    const float* __restrict__ W,
    const float* __restrict__ bias,
    float* __restrict__ Cg,
    const int* __restrict__ rmin,
    const int* __restrict__ rmout,
    const int* __restrict__ mnzp)
{
    int Mnz = *mnzp;
    int row0 = blockIdx.y * 128, col0 = blockIdx.x * 64;
    if (row0 >= Mnz) return;

    __shared__ uint32_t Ah_s[128 * 12], Al_s[128 * 12];
    __shared__ uint32_t Wh_s[64 * 12],  Wl_s[64 * 12];

    int tid  = threadIdx.x;
    int lane = tid & 31, warp = tid >> 5;
    int wm = warp >> 1, wn = warp & 1;
    int g  = lane >> 2, tg = lane & 3;

    float c[2][4][4];
#pragma unroll
    for (int mt = 0; mt < 2; mt++)
#pragma unroll
        for (int nt = 0; nt < 4; nt++)
#pragma unroll
            for (int r = 0; r < 4; r++) c[mt][nt][r] = 0.f;

    int lr = tid >> 1;            // 0..127
    int hf = tid & 1;             // k half (8 floats)
    int lk = hf * 8;
    int m  = row0 + lr;
    bool av = (m < Mnz);
    const float* asrc = A + (size_t)(av ? rmin[m] : 0) * D;
    int wr = (tid < 128) ? (tid >> 1) : 0;
    const float* wsrc = W + (size_t)(col0 + wr) * D;

    for (int k0 = 0; k0 < D; k0 += 16) {
        {
            float4 v0 = make_float4(0.f, 0.f, 0.f, 0.f), v1 = v0;
            if (av) {
                v0 = *(const float4*)(asrc + k0 + lk);
                v1 = *(const float4*)(asrc + k0 + lk + 4);
            }
            uint32_t h0, l0, h1, l1, h2, l2, h3, l3;
            bsplit2(v0.x, v0.y, h0, l0); bsplit2(v0.z, v0.w, h1, l1);
            bsplit2(v1.x, v1.y, h2, l2); bsplit2(v1.z, v1.w, h3, l3);
            int off = lr * 12 + hf * 4;
            *(uint4*)&Ah_s[off] = make_uint4(h0, h1, h2, h3);
            *(uint4*)&Al_s[off] = make_uint4(l0, l1, l2, l3);
        }
        if (tid < 128) {
            float4 v0 = *(const float4*)(wsrc + k0 + lk);
            float4 v1 = *(const float4*)(wsrc + k0 + lk + 4);
            uint32_t h0, l0, h1, l1, h2, l2, h3, l3;
            bsplit2(v0.x, v0.y, h0, l0); bsplit2(v0.z, v0.w, h1, l1);
            bsplit2(v1.x, v1.y, h2, l2); bsplit2(v1.z, v1.w, h3, l3);
            int woff = wr * 12 + hf * 4;
            *(uint4*)&Wh_s[woff] = make_uint4(h0, h1, h2, h3);
            *(uint4*)&Wl_s[woff] = make_uint4(l0, l1, l2, l3);
        }
        __syncthreads();

        uint32_t a_h[2][4], a_l[2][4];
#pragma unroll
        for (int mt = 0; mt < 2; mt++) {
            int m0 = wm * 32 + mt * 16;
            a_h[mt][0] = Ah_s[(m0 + g) * 12 + tg];
            a_h[mt][1] = Ah_s[(m0 + g + 8) * 12 + tg];
            a_h[mt][2] = Ah_s[(m0 + g) * 12 + tg + 4];
            a_h[mt][3] = Ah_s[(m0 + g + 8) * 12 + tg + 4];
            a_l[mt][0] = Al_s[(m0 + g) * 12 + tg];
            a_l[mt][1] = Al_s[(m0 + g + 8) * 12 + tg];
            a_l[mt][2] = Al_s[(m0 + g) * 12 + tg + 4];
            a_l[mt][3] = Al_s[(m0 + g + 8) * 12 + tg + 4];
        }
#pragma unroll
        for (int nt = 0; nt < 4; nt++) {
            int n0 = wn * 32 + nt * 8;
            uint32_t bh[2], bl[2];
            bh[0] = Wh_s[(n0 + g) * 12 + tg];
            bh[1] = Wh_s[(n0 + g) * 12 + tg + 4];
            bl[0] = Wl_s[(n0 + g) * 12 + tg];
            bl[1] = Wl_s[(n0 + g) * 12 + tg + 4];
#pragma unroll
            for (int mt = 0; mt < 2; mt++) {
                mma16(c[mt][nt], a_h[mt], bh);
                mma16(c[mt][nt], a_l[mt], bh);
                mma16(c[mt][nt], a_h[mt], bl);
            }
        }
        __syncthreads();
    }

#pragma unroll
    for (int mt = 0; mt < 2; mt++) {
        int mrow1 = row0 + wm * 32 + mt * 16 + g;
        int mrow2 = mrow1 + 8;
        int ro1 = (mrow1 < Mnz) ? rmout[mrow1] : -1;
        int ro2 = (mrow2 < Mnz) ? rmout[mrow2] : -1;
#pragma unroll
        for (int nt = 0; nt < 4; nt++) {
            int col = col0 + wn * 32 + nt * 8 + 2 * tg;
            float b0 = bias[col], b1 = bias[col + 1];
            if (ro1 >= 0)
                *(float2*)(Cg + (size_t)ro1 * GI_W + col) =
                    make_float2(c[mt][nt][0] + b0, c[mt][nt][1] + b1);
            if (ro2 >= 0)
                *(float2*)(Cg + (size_t)ro2 * GI_W + col) =
                    make_float2(c[mt][nt][2] + b0, c[mt][nt][3] + b1);
        }
    }
}

// ---------------------------------------------------------------------------
// 2b) Small-M GEMM (fc1) and fc2 K-split (proven)
// ---------------------------------------------------------------------------
template <bool RELU>
__global__ __launch_bounds__(256) void gemm_tn(
    const float* __restrict__ Ag, int lda,
    const float* __restrict__ Wg, int ldw,
    const float* __restrict__ bias,
    float* __restrict__ Cg, int ldc,
    int M, int N, int K)
{
    __shared__ float As[16][65];
    __shared__ float Ws[16][65];
    int tid  = threadIdx.x;
    int row0 = blockIdx.y * 64;
    int col0 = blockIdx.x * 64;
    int lm = tid >> 2;
    int lk = (tid & 3) * 4;
    int ty = tid >> 4;
    int tx = tid & 15;
    float acc[4][4];
#pragma unroll
    for (int i = 0; i < 4; i++)
#pragma unroll
        for (int j = 0; j < 4; j++) acc[i][j] = 0.f;

    for (int k0 = 0; k0 < K; k0 += 16) {
        int r = row0 + lm;
        int cc = col0 + lm;
#pragma unroll
        for (int i = 0; i < 4; i++) {
            int k = k0 + lk + i;
            As[lk + i][lm] = (r < M && k < K) ? Ag[(size_t)r * lda + k] : 0.f;
            Ws[lk + i][lm] = (cc < N && k < K) ? Wg[(size_t)cc * ldw + k] : 0.f;
        }
        __syncthreads();
#pragma unroll
        for (int kk = 0; kk < 16; kk++) {
            float a[4], w[4];
#pragma unroll
            for (int i = 0; i < 4; i++) a[i] = As[kk][ty + 16 * i];
#pragma unroll
            for (int j = 0; j < 4; j++) w[j] = Ws[kk][tx + 16 * j];
#pragma unroll
            for (int i = 0; i < 4; i++)
#pragma unroll
                for (int j = 0; j < 4; j++)
                    acc[i][j] = fmaf(a[i], w[j], acc[i][j]);
        }
        __syncthreads();
    }

#pragma unroll
    for (int i = 0; i < 4; i++) {
        int r = row0 + ty + 16 * i;
        if (r >= M) continue;
#pragma unroll
        for (int j = 0; j < 4; j++) {
            int cc = col0 + tx + 16 * j;
            if (cc >= N) continue;
            float v = acc[i][j] + bias[cc];
            if (RELU) v = fmaxf(v, 0.f);
            Cg[(size_t)r * ldc + cc] = v;
        }
    }
}

__global__ __launch_bounds__(256) void fc2_part(
    const float* __restrict__ Ag,
    const float* __restrict__ Wg,
    float* __restrict__ Pout)
{
    __shared__ float As[16][65];
    __shared__ float Ws[16][65];
    int tid  = threadIdx.x;
    int col0 = blockIdx.x * 64;
    int kbeg = blockIdx.y * 1024;
    int lm = tid >> 2;
    int lk = (tid & 3) * 4;
    int ty = tid >> 4;
    int tx = tid & 15;
    float acc[4][4];
#pragma unroll
    for (int i = 0; i < 4; i++)
#pragma unroll
        for (int j = 0; j < 4; j++) acc[i][j] = 0.f;

    for (int k0 = kbeg; k0 < kbeg + 1024; k0 += 16) {
        int cc = col0 + lm;
#pragma unroll
        for (int i = 0; i < 4; i++) {
            int k = k0 + lk + i;
            As[lk + i][lm] = (lm < C) ? Ag[(size_t)lm * 4096 + k] : 0.f;
            Ws[lk + i][lm] = Wg[(size_t)cc * 4096 + k];
        }
        __syncthreads();
#pragma unroll
        for (int kk = 0; kk < 16; kk++) {
            float a[4], w[4];
#pragma unroll
            for (int i = 0; i < 4; i++) a[i] = As[kk][ty + 16 * i];
#pragma unroll
            for (int j = 0; j < 4; j++) w[j] = Ws[kk][tx + 16 * j];
#pragma unroll
            for (int i = 0; i < 4; i++)
#pragma unroll
                for (int j = 0; j < 4; j++)
                    acc[i][j] = fmaf(a[i], w[j], acc[i][j]);
        }
        __syncthreads();
    }

    float* base = Pout + (size_t)blockIdx.y * (64 * 512);
#pragma unroll
    for (int i = 0; i < 4; i++) {
        int r = ty + 16 * i;
        if (r >= C) continue;
#pragma unroll
        for (int j = 0; j < 4; j++) {
            int cc = col0 + tx + 16 * j;
            base[(size_t)r * 512 + cc] = acc[i][j];
        }
    }
}

__global__ __launch_bounds__(256) void fc2_reduce(
    const float* __restrict__ P, const float* __restrict__ bias,
    float* __restrict__ attr2)
{
    int idx = blockIdx.x * 256 + threadIdx.x;
    if (idx < C * 512) {
        int r = idx >> 9, cc = idx & 511;
        float v = bias[cc];
#pragma unroll
        for (int kc = 0; kc < 4; kc++)
            v += P[(size_t)kc * (64 * 512) + r * 512 + cc];
        attr2[idx] = fmaxf(v, 0.f);
    }
}

// ---------------------------------------------------------------------------
// 3) GRU recurrence (proven, byte-identical)
// ---------------------------------------------------------------------------
#define GRU_BLOCKS 128

__device__ __forceinline__ void grid_barrier()
{
    __syncthreads();
    if (threadIdx.x == 0) {
        __threadfence();
        unsigned g = ld_acq(&g_bar_gen);
        if (atomicAdd(&g_bar_count, 1) == GRU_BLOCKS - 1) {
            g_bar_count = 0;
            st_rel(&g_bar_gen, g + 1);
        } else {
            while (ld_acq(&g_bar_gen) == g) { __nanosleep(16); }
        }
    }
    __syncthreads();
}

__global__ __launch_bounds__(256) void gru_kernel(
    const float* __restrict__ GI,
    const float* __restrict__ whh_f, const float* __restrict__ whh_b,
    const float* __restrict__ bhh_f, const float* __restrict__ bhh_b,
    const float* __restrict__ bpack,
    const int*   __restrict__ count,
    float* __restrict__ feats)
{
    extern __shared__ float4 sm4[];
    float4* sW4 = sm4;
    float4* hS4 = sm4 + 12 * 65;

    int d  = blockIdx.x >> 6;
    int hc = blockIdx.x & 63;
    int tid = threadIdx.x;
    int b = tid >> 2;
    int u = tid & 3;
    int i = hc * 4 + u;

    const float* whh = d ? whh_b : whh_f;
    const float* bhh = d ? bhh_b : bhh_f;

    for (int t = tid; t < 12 * 64; t += 256) {
        int rr = t >> 6;
        int k4 = t & 63;
        int g  = rr >> 2, uu = rr & 3;
        int row = g * H + hc * 4 + uu;
        sW4[rr * 65 + k4] = ((const float4*)(whh + (size_t)row * H))[k4];
    }
    float br = bhh[i], bz = bhh[H + i], bn = bhh[2 * H + i];
    float ir0 = bpack[d * 768 + i];
    float iz0 = bpack[d * 768 + 256 + i];
    float in0 = bpack[d * 768 + 512 + i];
    int cnt_b = count[b];
    __syncthreads();

    float h = 0.f;

    for (int t = 0; t < T; t++) {
        float ar = 0.f, az = 0.f, an = 0.f;
        if (t > 0) {
            int p = t & 1;
            const float4* hp4 = (const float4*)(g_hbuf + p * (2 * B * H) + d * (B * H));
            for (int idx = tid; idx < B * (H / 4); idx += 256)
                hS4[(idx >> 6) * 65 + (idx & 63)] = __ldcg(&hp4[idx]);
            __syncthreads();

            const float4* hb = &hS4[b * 65];
            const float4* wr = &sW4[(0 + u) * 65];
            const float4* wz = &sW4[(4 + u) * 65];
            const float4* wn = &sW4[(8 + u) * 65];
#pragma unroll 16
            for (int k4 = 0; k4 < 64; k4++) {
                float4 hv = hb[k4];
                float4 a  = wr[k4];
                ar = fmaf(hv.x, a.x, fmaf(hv.y, a.y, fmaf(hv.z, a.z, fmaf(hv.w, a.w, ar))));
                float4 zz = wz[k4];
                az = fmaf(hv.x, zz.x, fmaf(hv.y, zz.y, fmaf(hv.z, zz.z, fmaf(hv.w, zz.w, az))));
                float4 nn = wn[k4];
                an = fmaf(hv.x, nn.x, fmaf(hv.y, nn.y, fmaf(hv.z, nn.z, fmaf(hv.w, nn.w, an))));
            }
        }

        int s = d ? (T - 1 - t) : t;
        float ir = ir0, iz = iz0, in_ = in0;
        if (s < cnt_b) {
            const float* gi = GI + ((size_t)b * T + s) * GI_W + d * 768;
            ir  = gi[i];
            iz  = gi[H + i];
            in_ = gi[2 * H + i];
        }

        float r = 1.f / (1.f + expf(-(ir + ar + br)));
        float z = 1.f / (1.f + expf(-(iz + az + bz)));
        float n = tanhf(in_ + r * (an + bn));
        h = (1.f - z) * n + z * h;

        feats[((size_t)b * T + s) * 512 + d * H + i] = h;
        if (t < T - 1) {
            g_hbuf[((t & 1) ^ 1) * (2 * B * H) + d * (B * H) + b * H + i] = h;
            grid_barrier();
        }
    }
}

// ---------------------------------------------------------------------------
// 4) Relation head, bf16 3-split tensor cores (proven, byte-identical)
// ---------------------------------------------------------------------------
__global__ __launch_bounds__(256, 2) void relation_bf16(
    const float* __restrict__ feats,
    const float* __restrict__ attr2,
    const __nv_bfloat16* __restrict__ w3hi,
    const __nv_bfloat16* __restrict__ w3lo,
    const float* __restrict__ b3,
    const float* __restrict__ w4,
    const float* __restrict__ b4,
    float* __restrict__ logits)
{
    __shared__ uint32_t Dh_s[64 * 12], Dl_s[64 * 12];
    __shared__ uint32_t Wh_s[256 * 12], Wl_s[256 * 12];
    __shared__ float aS[2 * 512];
    __shared__ float part[64][5];

    int c0 = blockIdx.x * 2;
    int b  = blockIdx.y;
    int tid  = threadIdx.x;
    int lane = tid & 31, warp = tid >> 5;
    int wm = warp >> 2, wn = warp & 3;
    int g  = lane >> 2, tg = lane & 3;

    for (int t = tid; t < 1024; t += 256)
        aS[t] = attr2[(size_t)(c0 + (t >> 9)) * 512 + (t & 511)];
    __syncthreads();

    float c[2][8][4];
#pragma unroll
    for (int mt = 0; mt < 2; mt++)
#pragma unroll
        for (int nt = 0; nt < 8; nt++)
#pragma unroll
            for (int r = 0; r < 4; r++) c[mt][nt][r] = 0.f;

    int dm = tid >> 2;
    int dk = (tid & 3) * 4;
    int ds = dm & 31, dc = dm >> 5;
    const float* frow = feats + ((size_t)b * T + ds) * 512;
    const __nv_bfloat16* w3h_row = w3hi + (size_t)tid * 512;
    const __nv_bfloat16* w3l_row = w3lo + (size_t)tid * 512;

    for (int k0 = 0; k0 < 512; k0 += 16) {
        {
            float4 f = *(const float4*)(frow + k0 + dk);
            float4 a = *(const float4*)(aS + dc * 512 + k0 + dk);
            float d0 = f.x - a.x, d1 = f.y - a.y;
            float d2 = f.z - a.z, d3 = f.w - a.w;
            uint32_t h0, l0, h1, l1;
            bsplit2(d0 * d0, d1 * d1, h0, l0);
            bsplit2(d2 * d2, d3 * d3, h1, l1);
            int w = (tid & 3) * 2;
            Dh_s[dm * 12 + w]     = h0;
            Dh_s[dm * 12 + w + 1] = h1;
            Dl_s[dm * 12 + w]     = l0;
            Dl_s[dm * 12 + w + 1] = l1;
        }
        {
            uint4 wh0 = ((const uint4*)(w3h_row + k0))[0];
            uint4 wh1 = ((const uint4*)(w3h_row + k0))[1];
            uint4 wl0 = ((const uint4*)(w3l_row + k0))[0];
            uint4 wl1 = ((const uint4*)(w3l_row + k0))[1];
            *(uint4*)&Wh_s[tid * 12 + 0] = wh0;
            *(uint4*)&Wh_s[tid * 12 + 4] = wh1;
            *(uint4*)&Wl_s[tid * 12 + 0] = wl0;
            *(uint4*)&Wl_s[tid * 12 + 4] = wl1;
        }
        __syncthreads();

        uint32_t a_h[2][4], a_l[2][4];
#pragma unroll
        for (int mt = 0; mt < 2; mt++) {
            int m0 = wm * 32 + mt * 16;
            a_h[mt][0] = Dh_s[(m0 + g) * 12 + tg];
            a_h[mt][1] = Dh_s[(m0 + g + 8) * 12 + tg];
            a_h[mt][2] = Dh_s[(m0 + g) * 12 + tg + 4];
            a_h[mt][3] = Dh_s[(m0 + g + 8) * 12 + tg + 4];
            a_l[mt][0] = Dl_s[(m0 + g) * 12 + tg];
            a_l[mt][1] = Dl_s[(m0 + g + 8) * 12 + tg];
            a_l[mt][2] = Dl_s[(m0 + g) * 12 + tg + 4];
            a_l[mt][3] = Dl_s[(m0 + g + 8) * 12 + tg + 4];
        }
#pragma unroll
        for (int nt = 0; nt < 8; nt++) {
            int n0 = wn * 64 + nt * 8;
            uint32_t bh[2], bl[2];
            bh[0] = Wh_s[(n0 + g) * 12 + tg];
            bh[1] = Wh_s[(n0 + g) * 12 + tg + 4];
            bl[0] = Wl_s[(n0 + g) * 12 + tg];
            bl[1] = Wl_s[(n0 + g) * 12 + tg + 4];
#pragma unroll
            for (int mt = 0; mt < 2; mt++) {
                mma16(c[mt][nt], a_h[mt], bh);
                mma16(c[mt][nt], a_l[mt], bh);
                mma16(c[mt][nt], a_h[mt], bl);
            }
        }
        __syncthreads();
    }

    float rs[2][2] = {{0.f, 0.f}, {0.f, 0.f}};
#pragma unroll
    for (int nt = 0; nt < 8; nt++) {
        int col = wn * 64 + nt * 8 + 2 * tg;
        float w40 = w4[col], w41 = w4[col + 1];
        float b30 = b3[col], b31 = b3[col + 1];
#pragma unroll
        for (int mt = 0; mt < 2; mt++) {
            rs[mt][0] += fmaxf(c[mt][nt][0] + b30, 0.f) * w40
                       + fmaxf(c[mt][nt][1] + b31, 0.f) * w41;
            rs[mt][1] += fmaxf(c[mt][nt][2] + b30, 0.f) * w40
                       + fmaxf(c[mt][nt][3] + b31, 0.f) * w41;
        }
    }
#pragma unroll
    for (int mt = 0; mt < 2; mt++)
#pragma unroll
        for (int hf2 = 0; hf2 < 2; hf2++) {
            float v = rs[mt][hf2];
            v += __shfl_xor_sync(0xffffffffu, v, 1);
            v += __shfl_xor_sync(0xffffffffu, v, 2);
            if (tg == 0)
                part[wm * 32 + mt * 16 + g + hf2 * 8][wn] = v;
        }
    __syncthreads();
    if (tid < 64) {
        float s = b4[0] + part[tid][0] + part[tid][1] + part[tid][2] + part[tid][3];
        int cc = c0 + (tid >> 5), ss = tid & 31;
        logits[((size_t)b * C + cc) * T + ss] = s;
    }
}

// ---------------------------------------------------------------------------
// 5) Softmax over dim-0 per column, mean over columns (proven)
// ---------------------------------------------------------------------------
__global__ __launch_bounds__(256) void softmax_colreduce(
    const float* __restrict__ logits, float* __restrict__ cmax, float* __restrict__ csum)
{
    int t = blockIdx.x;
    int tid = threadIdx.x;
    __shared__ float red[256];
    float m = -1e30f;
    for (int i = tid; i < B * C; i += 256) m = fmaxf(m, logits[(size_t)i * T + t]);
    red[tid] = m; __syncthreads();
    for (int s = 128; s > 0; s >>= 1) {
        if (tid < s) red[tid] = fmaxf(red[tid], red[tid + s]);
        __syncthreads();
    }
    float mx = red[0];
    __syncthreads();
    float sum = 0.f;
    for (int i = tid; i < B * C; i += 256) sum += expf(logits[(size_t)i * T + t] - mx);
    red[tid] = sum; __syncthreads();
    for (int s = 128; s > 0; s >>= 1) {
        if (tid < s) red[tid] += red[tid + s];
        __syncthreads();
    }
    if (tid == 0) { cmax[t] = mx; csum[t] = red[0]; }
}

__global__ __launch_bounds__(256) void softmax_out(
    const float* __restrict__ logits, const float* __restrict__ cmax,
    const float* __restrict__ csum, float* __restrict__ out)
{
    __shared__ float mS[T], sS[T];
    int tid = threadIdx.x;
    if (tid < T) { mS[tid] = cmax[tid]; sS[tid] = csum[tid]; }
    __syncthreads();
    int i = blockIdx.x * 256 + tid;
    if (i < B * C) {
        float a = 0.f;
        const float* row = logits + (size_t)i * T;
#pragma unroll
        for (int t = 0; t < T; t++) a += expf(row[t] - mS[t]) / sS[t];
        out[i] = a * (1.f / (float)T);
    }
}

// ---------------------------------------------------------------------------
// Launch
// ---------------------------------------------------------------------------
extern "C" void kernel_launch(void* const* d_in, const int* in_sizes, int n_in,
                              void* d_out, int out_size)
{
    const float* batch_features  = (const float*)d_in[0];
    const float* batch_att       = (const float*)d_in[1];
    const float* batch_attrs     = (const float*)d_in[2];
    const float* fc1_w = (const float*)d_in[3];
    const float* fc1_b = (const float*)d_in[4];
    const float* fc2_w = (const float*)d_in[5];
    const float* fc2_b = (const float*)d_in[6];
    const float* fc3_w = (const float*)d_in[7];
    const float* fc3_b = (const float*)d_in[8];
    const float* fc4_w = (const float*)d_in[9];
    const float* fc4_b = (const float*)d_in[10];
    const float* gru_wih_f = (const float*)d_in[11];
    const float* gru_whh_f = (const float*)d_in[12];
    const float* gru_bih_f = (const float*)d_in[13];
    const float* gru_bhh_f = (const float*)d_in[14];
    const float* gru_wih_b = (const float*)d_in[15];
    const float* gru_whh_b = (const float*)d_in[16];
    const float* gru_bih_b = (const float*)d_in[17];
    const float* gru_bhh_b = (const float*)d_in[18];
    float* out = (float*)d_out;

    float* GI;     cudaGetSymbolAddress((void**)&GI,     g_GI);
    float* feats;  cudaGetSymbolAddress((void**)&feats,  g_feats);
    float* attr1;  cudaGetSymbolAddress((void**)&attr1,  g_attr1);
    float* attr2;  cudaGetSymbolAddress((void**)&attr2,  g_attr2);
    float* logits; cudaGetSymbolAddress((void**)&logits, g_logits);
    float* cmax;   cudaGetSymbolAddress((void**)&cmax,   g_cmax);
    float* csum;   cudaGetSymbolAddress((void**)&csum,   g_csum);
    float* wpack;  cudaGetSymbolAddress((void**)&wpack,  g_wih_pack);
    float* bpack;  cudaGetSymbolAddress((void**)&bpack,  g_bih_pack);
    __nv_bfloat16* w3hi; cudaGetSymbolAddress((void**)&w3hi, g_w3hi);
    __nv_bfloat16* w3lo; cudaGetSymbolAddress((void**)&w3lo, g_w3lo);
    float* fc2p;   cudaGetSymbolAddress((void**)&fc2p,   g_fc2part);
    int* rmin;     cudaGetSymbolAddress((void**)&rmin,   g_rmin);
    int* rmout;    cudaGetSymbolAddress((void**)&rmout,  g_rmout);
    int* cnt;      cudaGetSymbolAddress((void**)&cnt,    g_count);
    int* mnz;      cudaGetSymbolAddress((void**)&mnz,    g_mnz);

    build_maps<<<1, 64>>>(batch_att, rmin, rmout, cnt, mnz);
    pack_wih<<<(GI_W * D / 4 + 255) / 256, 256>>>(gru_wih_f, gru_wih_b,
                                                  gru_bih_f, gru_bih_b, wpack, bpack);
    split_w3_bf16<<<(256 * 512 / 2 + 255) / 256, 256>>>(fc3_w, w3hi, w3lo);

    // GI projection (bf16 3-split, no prefetch, 128x64 tiles, compacted rows)
    {
        dim3 grid(GI_W / 64, (B * T) / 128);   // (24, 16); ~half exit early
        gemm_bf16_gi<<<grid, 256>>>(batch_features, wpack, bpack, GI, rmin, rmout, mnz);
    }

    // GRU recurrence
    {
        int smem = (12 * 65 + 64 * 65) * (int)sizeof(float4);
        cudaFuncSetAttribute(gru_kernel, cudaFuncAttributeMaxDynamicSharedMemorySize, smem);
        gru_kernel<<<GRU_BLOCKS, 256, smem>>>(GI, gru_whh_f, gru_whh_b,
                                              gru_bhh_f, gru_bhh_b, bpack, cnt, feats);
    }

    // semantic net
    gemm_tn<true><<<dim3(4096 / 64, 1), 256>>>(batch_attrs, A_, fc1_w, A_, fc1_b,
                                               attr1, 4096, C, 4096, A_);
    fc2_part<<<dim3(8, 4), 256>>>(attr1, fc2_w, fc2p);
    fc2_reduce<<<(C * 512 + 255) / 256, 256>>>(fc2p, fc2_b, attr2);

    // relation head (bf16 3-split, proven)
    relation_bf16<<<dim3(C / 2, B), 256>>>(feats, attr2, w3hi, w3lo,
                                           fc3_b, fc4_w, fc4_b, logits);

    softmax_colreduce<<<T, 256>>>(logits, cmax, csum);
    softmax_out<<<(B * C + 255) / 256, 256>>>(logits, cmax, csum, out);
}

// round 12
// speedup vs baseline: 1.1411x; 1.0194x over previous
#include <cuda_runtime.h>
#include <cuda_bf16.h>
#include <math.h>
#include <stdint.h>

#define B    64
#define T    32
#define D    4096
#define C    50
#define A_   300
#define H    256
#define GI_W 1536

// ---------------------------------------------------------------------------
// Scratch
// ---------------------------------------------------------------------------
__device__ float g_GI[B * T * GI_W];
__device__ float g_feats[B * T * 512];
__device__ float g_attr1[C * 4096];
__device__ float g_attr2[C * 512];
__device__ float g_logits[B * C * T];
__device__ float g_cmax[T];
__device__ float g_csum[T];
__device__ float g_hbuf[2 * 2 * B * H];
__device__ float g_bih_pack[GI_W];
__device__ __nv_bfloat16 g_Whi[GI_W * D];   // packed GRU wih bf16 hi
__device__ __nv_bfloat16 g_Wlo[GI_W * D];   // bf16 lo residual
__device__ __nv_bfloat16 g_Ahi[B * T * D];  // gathered/compacted A rows, bf16 hi
__device__ __nv_bfloat16 g_Alo[B * T * D];
__device__ __nv_bfloat16 g_w3hi[256 * 512];
__device__ __nv_bfloat16 g_w3lo[256 * 512];
__device__ float g_fc2part[4 * 64 * 512];
__device__ int   g_rmin[B * T];
__device__ int   g_rmout[B * T];
__device__ int   g_count[B];
__device__ int   g_mnz[1];
__device__ int          g_bar_count;
__device__ unsigned int g_bar_gen;

// ---------------------------------------------------------------------------
// bf16 / sync helpers (proven)
// ---------------------------------------------------------------------------
__device__ __forceinline__ void mma16(float* c, const uint32_t* a, const uint32_t* b)
{
    asm volatile(
        "mma.sync.aligned.m16n8k16.row.col.f32.bf16.bf16.f32 "
        "{%0,%1,%2,%3},{%4,%5,%6,%7},{%8,%9},{%0,%1,%2,%3};"
        : "+f"(c[0]), "+f"(c[1]), "+f"(c[2]), "+f"(c[3])
        : "r"(a[0]), "r"(a[1]), "r"(a[2]), "r"(a[3]), "r"(b[0]), "r"(b[1]));
}

__device__ __forceinline__ void bsplit2(float x, float y, uint32_t& hw, uint32_t& lw)
{
    __nv_bfloat16 hx = __float2bfloat16(x);
    __nv_bfloat16 hy = __float2bfloat16(y);
    float rx = x - __bfloat162float(hx);
    float ry = y - __bfloat162float(hy);
    __nv_bfloat162 hp; hp.x = hx; hp.y = hy;
    __nv_bfloat162 lp; lp.x = __float2bfloat16(rx); lp.y = __float2bfloat16(ry);
    hw = *reinterpret_cast<uint32_t*>(&hp);
    lw = *reinterpret_cast<uint32_t*>(&lp);
}

__device__ __forceinline__ unsigned ld_acq(const unsigned* p)
{
    unsigned v;
    asm volatile("ld.acquire.gpu.u32 %0,[%1];" : "=r"(v) : "l"(p) : "memory");
    return v;
}
__device__ __forceinline__ void st_rel(unsigned* p, unsigned v)
{
    asm volatile("st.release.gpu.u32 [%0],%1;" :: "l"(p), "r"(v) : "memory");
}

// ---------------------------------------------------------------------------
// 0a) Pack GRU input weights to bf16 hi/lo + fp32 bias
// ---------------------------------------------------------------------------
__global__ __launch_bounds__(256) void pack_wih_bf16(
    const float* __restrict__ wf, const float* __restrict__ wb,
    const float* __restrict__ bf, const float* __restrict__ bb,
    __nv_bfloat16* __restrict__ whi, __nv_bfloat16* __restrict__ wlo,
    float* __restrict__ bp)
{
    int i = blockIdx.x * 256 + threadIdx.x;           // float4 index
    const int TOT4 = GI_W * D / 4;
    if (i < TOT4) {
        int row = (i * 4) / D;
        float4 v = (row < 768) ? ((const float4*)wf)[i]
                               : ((const float4*)wb)[i - 768 * (D / 4)];
        uint32_t h0, l0, h1, l1;
        bsplit2(v.x, v.y, h0, l0);
        bsplit2(v.z, v.w, h1, l1);
        ((uint2*)whi)[i] = make_uint2(h0, h1);
        ((uint2*)wlo)[i] = make_uint2(l0, l1);
    }
    if (i < GI_W) bp[i] = (i < 768) ? bf[i] : bb[i - 768];
}

// 0b) Pre-split w3 to bf16 hi/lo (proven)
__global__ __launch_bounds__(256) void split_w3_bf16(
    const float* __restrict__ w3,
    __nv_bfloat16* __restrict__ hh, __nv_bfloat16* __restrict__ ll)
{
    int i = blockIdx.x * 256 + threadIdx.x;
    if (i < 256 * 512 / 2) {
        float2 v = ((const float2*)w3)[i];
        uint32_t h, l;
        bsplit2(v.x, v.y, h, l);
        ((uint32_t*)hh)[i] = h;
        ((uint32_t*)ll)[i] = l;
    }
}

// ---------------------------------------------------------------------------
// 1) Bookkeeping (proven)
// ---------------------------------------------------------------------------
__global__ void build_maps(
    const float* __restrict__ att,
    int* __restrict__ rmin, int* __restrict__ rmout,
    int* __restrict__ count, int* __restrict__ mnz)
{
    __shared__ int cnts[B], offs[B];
    int b = threadIdx.x;   // 64 threads
    float a[T];
    float s = 0.f;
#pragma unroll
    for (int t = 0; t < T; t++) { a[t] = att[b * T + t]; s += a[t]; }
    float thr = s / (float)T;
    int ord[T];
    int c = 0;
#pragma unroll
    for (int t = 0; t < T; t++) if (a[t] >= thr) ord[c++] = t;
    cnts[b] = c;
    __syncthreads();
    if (b == 0) {
        int acc = 0;
        for (int i = 0; i < B; i++) { offs[i] = acc; acc += cnts[i]; }
        *mnz = acc;
    }
    __syncthreads();
    int o = offs[b];
    for (int s2 = 0; s2 < c; s2++) {
        rmin[o + s2]  = b * T + ord[s2];
        rmout[o + s2] = b * T + s2;
    }
    count[b] = c;
}

// ---------------------------------------------------------------------------
// 1b) Gather selected rows, convert to bf16 hi/lo; zero-fill tail rows
// ---------------------------------------------------------------------------
__global__ __launch_bounds__(128) void conv_feats(
    const float* __restrict__ bf,
    const int* __restrict__ rmin, const int* __restrict__ mnzp,
    __nv_bfloat16* __restrict__ Ahi, __nv_bfloat16* __restrict__ Alo)
{
    int i = blockIdx.x;               // 0..2047 compacted row
    int tid = threadIdx.x;
    int Mnz = *mnzp;
    uint2* oh = (uint2*)(Ahi + (size_t)i * D);
    uint2* ol = (uint2*)(Alo + (size_t)i * D);
    if (i < Mnz) {
        const float4* src = (const float4*)(bf + (size_t)rmin[i] * D);
        for (int j = tid; j < D / 4; j += 128) {
            float4 v = src[j];
            uint32_t h0, l0, h1, l1;
            bsplit2(v.x, v.y, h0, l0);
            bsplit2(v.z, v.w, h1, l1);
            oh[j] = make_uint2(h0, h1);
            ol[j] = make_uint2(l0, l1);
        }
    } else {
        uint2 z = make_uint2(0u, 0u);
        for (int j = tid; j < D / 4; j += 128) { oh[j] = z; ol[j] = z; }
    }
}

// ---------------------------------------------------------------------------
// 2) GI projection: bf16 3-split, pre-converted operands, NO prefetch —
//    R11-proven skeleton with the in-loop cvt work removed entirely.
// ---------------------------------------------------------------------------
__global__ __launch_bounds__(256, 2) void gemm_bf16_gi(
    const __nv_bfloat16* __restrict__ Ahi, const __nv_bfloat16* __restrict__ Alo,
    const __nv_bfloat16* __restrict__ Whi, const __nv_bfloat16* __restrict__ Wlo,
    const float* __restrict__ bias,
    float* __restrict__ Cg,
    const int* __restrict__ rmout,
    const int* __restrict__ mnzp)
{
    int Mnz = *mnzp;
    int row0 = blockIdx.y * 128, col0 = blockIdx.x * 64;
    if (row0 >= Mnz) return;

    __shared__ uint32_t Ah_s[128 * 12], Al_s[128 * 12];
    __shared__ uint32_t Wh_s[64 * 12],  Wl_s[64 * 12];

    int tid  = threadIdx.x;
    int lane = tid & 31, warp = tid >> 5;
    int wm = warp >> 1, wn = warp & 1;
    int g  = lane >> 2, tg = lane & 3;

    float c[2][4][4];
#pragma unroll
    for (int mt = 0; mt < 2; mt++)
#pragma unroll
        for (int nt = 0; nt < 4; nt++)
#pragma unroll
            for (int r = 0; r < 4; r++) c[mt][nt][r] = 0.f;

    int lr = tid >> 1;            // 0..127
    int hf = tid & 1;             // k half (8 bf16)
    const __nv_bfloat16* arh = Ahi + (size_t)(row0 + lr) * D;
    const __nv_bfloat16* arl = Alo + (size_t)(row0 + lr) * D;
    int wr = (tid < 128) ? (tid >> 1) : 0;
    const __nv_bfloat16* wrh = Whi + (size_t)(col0 + wr) * D;
    const __nv_bfloat16* wrl = Wlo + (size_t)(col0 + wr) * D;

    for (int k0 = 0; k0 < D; k0 += 16) {
        int off = lr * 12 + hf * 4;
        *(uint4*)&Ah_s[off] = ((const uint4*)(arh + k0))[hf];
        *(uint4*)&Al_s[off] = ((const uint4*)(arl + k0))[hf];
        if (tid < 128) {
            int woff = wr * 12 + hf * 4;
            *(uint4*)&Wh_s[woff] = ((const uint4*)(wrh + k0))[hf];
            *(uint4*)&Wl_s[woff] = ((const uint4*)(wrl + k0))[hf];
        }
        __syncthreads();

        uint32_t a_h[2][4], a_l[2][4];
#pragma unroll
        for (int mt = 0; mt < 2; mt++) {
            int m0 = wm * 32 + mt * 16;
            a_h[mt][0] = Ah_s[(m0 + g) * 12 + tg];
            a_h[mt][1] = Ah_s[(m0 + g + 8) * 12 + tg];
            a_h[mt][2] = Ah_s[(m0 + g) * 12 + tg + 4];
            a_h[mt][3] = Ah_s[(m0 + g + 8) * 12 + tg + 4];
            a_l[mt][0] = Al_s[(m0 + g) * 12 + tg];
            a_l[mt][1] = Al_s[(m0 + g + 8) * 12 + tg];
            a_l[mt][2] = Al_s[(m0 + g) * 12 + tg + 4];
            a_l[mt][3] = Al_s[(m0 + g + 8) * 12 + tg + 4];
        }
#pragma unroll
        for (int nt = 0; nt < 4; nt++) {
            int n0 = wn * 32 + nt * 8;
            uint32_t bh[2], bl[2];
            bh[0] = Wh_s[(n0 + g) * 12 + tg];
            bh[1] = Wh_s[(n0 + g) * 12 + tg + 4];
            bl[0] = Wl_s[(n0 + g) * 12 + tg];
            bl[1] = Wl_s[(n0 + g) * 12 + tg + 4];
#pragma unroll
            for (int mt = 0; mt < 2; mt++) {
                mma16(c[mt][nt], a_h[mt], bh);
                mma16(c[mt][nt], a_l[mt], bh);
                mma16(c[mt][nt], a_h[mt], bl);
            }
        }
        __syncthreads();
    }

#pragma unroll
    for (int mt = 0; mt < 2; mt++) {
        int mrow1 = row0 + wm * 32 + mt * 16 + g;
        int mrow2 = mrow1 + 8;
        int ro1 = (mrow1 < Mnz) ? rmout[mrow1] : -1;
        int ro2 = (mrow2 < Mnz) ? rmout[mrow2] : -1;
#pragma unroll
        for (int nt = 0; nt < 4; nt++) {
            int col = col0 + wn * 32 + nt * 8 + 2 * tg;
            float b0 = bias[col], b1 = bias[col + 1];
            if (ro1 >= 0)
                *(float2*)(Cg + (size_t)ro1 * GI_W + col) =
                    make_float2(c[mt][nt][0] + b0, c[mt][nt][1] + b1);
            if (ro2 >= 0)
                *(float2*)(Cg + (size_t)ro2 * GI_W + col) =
                    make_float2(c[mt][nt][2] + b0, c[mt][nt][3] + b1);
        }
    }
}

// ---------------------------------------------------------------------------
// 2b) Small-M GEMM (fc1) and fc2 K-split (proven)
// ---------------------------------------------------------------------------
template <bool RELU>
__global__ __launch_bounds__(256) void gemm_tn(
    const float* __restrict__ Ag, int lda,
    const float* __restrict__ Wg, int ldw,
    const float* __restrict__ bias,
    float* __restrict__ Cg, int ldc,
    int M, int N, int K)
{
    __shared__ float As[16][65];
    __shared__ float Ws[16][65];
    int tid  = threadIdx.x;
    int row0 = blockIdx.y * 64;
    int col0 = blockIdx.x * 64;
    int lm = tid >> 2;
    int lk = (tid & 3) * 4;
    int ty = tid >> 4;
    int tx = tid & 15;
    float acc[4][4];
#pragma unroll
    for (int i = 0; i < 4; i++)
#pragma unroll
        for (int j = 0; j < 4; j++) acc[i][j] = 0.f;

    for (int k0 = 0; k0 < K; k0 += 16) {
        int r = row0 + lm;
        int cc = col0 + lm;
#pragma unroll
        for (int i = 0; i < 4; i++) {
            int k = k0 + lk + i;
            As[lk + i][lm] = (r < M && k < K) ? Ag[(size_t)r * lda + k] : 0.f;
            Ws[lk + i][lm] = (cc < N && k < K) ? Wg[(size_t)cc * ldw + k] : 0.f;
        }
        __syncthreads();
#pragma unroll
        for (int kk = 0; kk < 16; kk++) {
            float a[4], w[4];
#pragma unroll
            for (int i = 0; i < 4; i++) a[i] = As[kk][ty + 16 * i];
#pragma unroll
            for (int j = 0; j < 4; j++) w[j] = Ws[kk][tx + 16 * j];
#pragma unroll
            for (int i = 0; i < 4; i++)
#pragma unroll
                for (int j = 0; j < 4; j++)
                    acc[i][j] = fmaf(a[i], w[j], acc[i][j]);
        }
        __syncthreads();
    }

#pragma unroll
    for (int i = 0; i < 4; i++) {
        int r = row0 + ty + 16 * i;
        if (r >= M) continue;
#pragma unroll
        for (int j = 0; j < 4; j++) {
            int cc = col0 + tx + 16 * j;
            if (cc >= N) continue;
            float v = acc[i][j] + bias[cc];
            if (RELU) v = fmaxf(v, 0.f);
            Cg[(size_t)r * ldc + cc] = v;
        }
    }
}

__global__ __launch_bounds__(256) void fc2_part(
    const float* __restrict__ Ag,
    const float* __restrict__ Wg,
    float* __restrict__ Pout)
{
    __shared__ float As[16][65];
    __shared__ float Ws[16][65];
    int tid  = threadIdx.x;
    int col0 = blockIdx.x * 64;
    int kbeg = blockIdx.y * 1024;
    int lm = tid >> 2;
    int lk = (tid & 3) * 4;
    int ty = tid >> 4;
    int tx = tid & 15;
    float acc[4][4];
#pragma unroll
    for (int i = 0; i < 4; i++)
#pragma unroll
        for (int j = 0; j < 4; j++) acc[i][j] = 0.f;

    for (int k0 = kbeg; k0 < kbeg + 1024; k0 += 16) {
        int cc = col0 + lm;
#pragma unroll
        for (int i = 0; i < 4; i++) {
            int k = k0 + lk + i;
            As[lk + i][lm] = (lm < C) ? Ag[(size_t)lm * 4096 + k] : 0.f;
            Ws[lk + i][lm] = Wg[(size_t)cc * 4096 + k];
        }
        __syncthreads();
#pragma unroll
        for (int kk = 0; kk < 16; kk++) {
            float a[4], w[4];
#pragma unroll
            for (int i = 0; i < 4; i++) a[i] = As[kk][ty + 16 * i];
#pragma unroll
            for (int j = 0; j < 4; j++) w[j] = Ws[kk][tx + 16 * j];
#pragma unroll
            for (int i = 0; i < 4; i++)
#pragma unroll
                for (int j = 0; j < 4; j++)
                    acc[i][j] = fmaf(a[i], w[j], acc[i][j]);
        }
        __syncthreads();
    }

    float* base = Pout + (size_t)blockIdx.y * (64 * 512);
#pragma unroll
    for (int i = 0; i < 4; i++) {
        int r = ty + 16 * i;
        if (r >= C) continue;
#pragma unroll
        for (int j = 0; j < 4; j++) {
            int cc = col0 + tx + 16 * j;
            base[(size_t)r * 512 + cc] = acc[i][j];
        }
    }
}

__global__ __launch_bounds__(256) void fc2_reduce(
    const float* __restrict__ P, const float* __restrict__ bias,
    float* __restrict__ attr2)
{
    int idx = blockIdx.x * 256 + threadIdx.x;
    if (idx < C * 512) {
        int r = idx >> 9, cc = idx & 511;
        float v = bias[cc];
#pragma unroll
        for (int kc = 0; kc < 4; kc++)
            v += P[(size_t)kc * (64 * 512) + r * 512 + cc];
        attr2[idx] = fmaxf(v, 0.f);
    }
}

// ---------------------------------------------------------------------------
// 3) GRU recurrence (proven, byte-identical)
// ---------------------------------------------------------------------------
#define GRU_BLOCKS 128

__device__ __forceinline__ void grid_barrier()
{
    __syncthreads();
    if (threadIdx.x == 0) {
        __threadfence();
        unsigned g = ld_acq(&g_bar_gen);
        if (atomicAdd(&g_bar_count, 1) == GRU_BLOCKS - 1) {
            g_bar_count = 0;
            st_rel(&g_bar_gen, g + 1);
        } else {
            while (ld_acq(&g_bar_gen) == g) { __nanosleep(16); }
        }
    }
    __syncthreads();
}

__global__ __launch_bounds__(256) void gru_kernel(
    const float* __restrict__ GI,
    const float* __restrict__ whh_f, const float* __restrict__ whh_b,
    const float* __restrict__ bhh_f, const float* __restrict__ bhh_b,
    const float* __restrict__ bpack,
    const int*   __restrict__ count,
    float* __restrict__ feats)
{
    extern __shared__ float4 sm4[];
    float4* sW4 = sm4;
    float4* hS4 = sm4 + 12 * 65;

    int d  = blockIdx.x >> 6;
    int hc = blockIdx.x & 63;
    int tid = threadIdx.x;
    int b = tid >> 2;
    int u = tid & 3;
    int i = hc * 4 + u;

    const float* whh = d ? whh_b : whh_f;
    const float* bhh = d ? bhh_b : bhh_f;

    for (int t = tid; t < 12 * 64; t += 256) {
        int rr = t >> 6;
        int k4 = t & 63;
        int g  = rr >> 2, uu = rr & 3;
        int row = g * H + hc * 4 + uu;
        sW4[rr * 65 + k4] = ((const float4*)(whh + (size_t)row * H))[k4];
    }
    float br = bhh[i], bz = bhh[H + i], bn = bhh[2 * H + i];
    float ir0 = bpack[d * 768 + i];
    float iz0 = bpack[d * 768 + 256 + i];
    float in0 = bpack[d * 768 + 512 + i];
    int cnt_b = count[b];
    __syncthreads();

    float h = 0.f;

    for (int t = 0; t < T; t++) {
        float ar = 0.f, az = 0.f, an = 0.f;
        if (t > 0) {
            int p = t & 1;
            const float4* hp4 = (const float4*)(g_hbuf + p * (2 * B * H) + d * (B * H));
            for (int idx = tid; idx < B * (H / 4); idx += 256)
                hS4[(idx >> 6) * 65 + (idx & 63)] = __ldcg(&hp4[idx]);
            __syncthreads();

            const float4* hb = &hS4[b * 65];
            const float4* wr = &sW4[(0 + u) * 65];
            const float4* wz = &sW4[(4 + u) * 65];
            const float4* wn = &sW4[(8 + u) * 65];
#pragma unroll 16
            for (int k4 = 0; k4 < 64; k4++) {
                float4 hv = hb[k4];
                float4 a  = wr[k4];
                ar = fmaf(hv.x, a.x, fmaf(hv.y, a.y, fmaf(hv.z, a.z, fmaf(hv.w, a.w, ar))));
                float4 zz = wz[k4];
                az = fmaf(hv.x, zz.x, fmaf(hv.y, zz.y, fmaf(hv.z, zz.z, fmaf(hv.w, zz.w, az))));
                float4 nn = wn[k4];
                an = fmaf(hv.x, nn.x, fmaf(hv.y, nn.y, fmaf(hv.z, nn.z, fmaf(hv.w, nn.w, an))));
            }
        }

        int s = d ? (T - 1 - t) : t;
        float ir = ir0, iz = iz0, in_ = in0;
        if (s < cnt_b) {
            const float* gi = GI + ((size_t)b * T + s) * GI_W + d * 768;
            ir  = gi[i];
            iz  = gi[H + i];
            in_ = gi[2 * H + i];
        }

        float r = 1.f / (1.f + expf(-(ir + ar + br)));
        float z = 1.f / (1.f + expf(-(iz + az + bz)));
        float n = tanhf(in_ + r * (an + bn));
        h = (1.f - z) * n + z * h;

        feats[((size_t)b * T + s) * 512 + d * H + i] = h;
        if (t < T - 1) {
            g_hbuf[((t & 1) ^ 1) * (2 * B * H) + d * (B * H) + b * H + i] = h;
            grid_barrier();
        }
    }
}

// ---------------------------------------------------------------------------
// 4) Relation head, bf16 3-split tensor cores (proven, byte-identical)
// ---------------------------------------------------------------------------
__global__ __launch_bounds__(256, 2) void relation_bf16(
    const float* __restrict__ feats,
    const float* __restrict__ attr2,
    const __nv_bfloat16* __restrict__ w3hi,
    const __nv_bfloat16* __restrict__ w3lo,
    const float* __restrict__ b3,
    const float* __restrict__ w4,
    const float* __restrict__ b4,
    float* __restrict__ logits)
{
    __shared__ uint32_t Dh_s[64 * 12], Dl_s[64 * 12];
    __shared__ uint32_t Wh_s[256 * 12], Wl_s[256 * 12];
    __shared__ float aS[2 * 512];
    __shared__ float part[64][5];

    int c0 = blockIdx.x * 2;
    int b  = blockIdx.y;
    int tid  = threadIdx.x;
    int lane = tid & 31, warp = tid >> 5;
    int wm = warp >> 2, wn = warp & 3;
    int g  = lane >> 2, tg = lane & 3;

    for (int t = tid; t < 1024; t += 256)
        aS[t] = attr2[(size_t)(c0 + (t >> 9)) * 512 + (t & 511)];
    __syncthreads();

    float c[2][8][4];
#pragma unroll
    for (int mt = 0; mt < 2; mt++)
#pragma unroll
        for (int nt = 0; nt < 8; nt++)
#pragma unroll
            for (int r = 0; r < 4; r++) c[mt][nt][r] = 0.f;

    int dm = tid >> 2;
    int dk = (tid & 3) * 4;
    int ds = dm & 31, dc = dm >> 5;
    const float* frow = feats + ((size_t)b * T + ds) * 512;
    const __nv_bfloat16* w3h_row = w3hi + (size_t)tid * 512;
    const __nv_bfloat16* w3l_row = w3lo + (size_t)tid * 512;

    for (int k0 = 0; k0 < 512; k0 += 16) {
        {
            float4 f = *(const float4*)(frow + k0 + dk);
            float4 a = *(const float4*)(aS + dc * 512 + k0 + dk);
            float d0 = f.x - a.x, d1 = f.y - a.y;
            float d2 = f.z - a.z, d3 = f.w - a.w;
            uint32_t h0, l0, h1, l1;
            bsplit2(d0 * d0, d1 * d1, h0, l0);
            bsplit2(d2 * d2, d3 * d3, h1, l1);
            int w = (tid & 3) * 2;
            Dh_s[dm * 12 + w]     = h0;
            Dh_s[dm * 12 + w + 1] = h1;
            Dl_s[dm * 12 + w]     = l0;
            Dl_s[dm * 12 + w + 1] = l1;
        }
        {
            uint4 wh0 = ((const uint4*)(w3h_row + k0))[0];
            uint4 wh1 = ((const uint4*)(w3h_row + k0))[1];
            uint4 wl0 = ((const uint4*)(w3l_row + k0))[0];
            uint4 wl1 = ((const uint4*)(w3l_row + k0))[1];
            *(uint4*)&Wh_s[tid * 12 + 0] = wh0;
            *(uint4*)&Wh_s[tid * 12 + 4] = wh1;
            *(uint4*)&Wl_s[tid * 12 + 0] = wl0;
            *(uint4*)&Wl_s[tid * 12 + 4] = wl1;
        }
        __syncthreads();

        uint32_t a_h[2][4], a_l[2][4];
#pragma unroll
        for (int mt = 0; mt < 2; mt++) {
            int m0 = wm * 32 + mt * 16;
            a_h[mt][0] = Dh_s[(m0 + g) * 12 + tg];
            a_h[mt][1] = Dh_s[(m0 + g + 8) * 12 + tg];
            a_h[mt][2] = Dh_s[(m0 + g) * 12 + tg + 4];
            a_h[mt][3] = Dh_s[(m0 + g + 8) * 12 + tg + 4];
            a_l[mt][0] = Dl_s[(m0 + g) * 12 + tg];
            a_l[mt][1] = Dl_s[(m0 + g + 8) * 12 + tg];
            a_l[mt][2] = Dl_s[(m0 + g) * 12 + tg + 4];
            a_l[mt][3] = Dl_s[(m0 + g + 8) * 12 + tg + 4];
        }
#pragma unroll
        for (int nt = 0; nt < 8; nt++) {
            int n0 = wn * 64 + nt * 8;
            uint32_t bh[2], bl[2];
            bh[0] = Wh_s[(n0 + g) * 12 + tg];
            bh[1] = Wh_s[(n0 + g) * 12 + tg + 4];
            bl[0] = Wl_s[(n0 + g) * 12 + tg];
            bl[1] = Wl_s[(n0 + g) * 12 + tg + 4];
#pragma unroll
            for (int mt = 0; mt < 2; mt++) {
                mma16(c[mt][nt], a_h[mt], bh);
                mma16(c[mt][nt], a_l[mt], bh);
                mma16(c[mt][nt], a_h[mt], bl);
            }
        }
        __syncthreads();
    }

    float rs[2][2] = {{0.f, 0.f}, {0.f, 0.f}};
#pragma unroll
    for (int nt = 0; nt < 8; nt++) {
        int col = wn * 64 + nt * 8 + 2 * tg;
        float w40 = w4[col], w41 = w4[col + 1];
        float b30 = b3[col], b31 = b3[col + 1];
#pragma unroll
        for (int mt = 0; mt < 2; mt++) {
            rs[mt][0] += fmaxf(c[mt][nt][0] + b30, 0.f) * w40
                       + fmaxf(c[mt][nt][1] + b31, 0.f) * w41;
            rs[mt][1] += fmaxf(c[mt][nt][2] + b30, 0.f) * w40
                       + fmaxf(c[mt][nt][3] + b31, 0.f) * w41;
        }
    }
#pragma unroll
    for (int mt = 0; mt < 2; mt++)
#pragma unroll
        for (int hf2 = 0; hf2 < 2; hf2++) {
            float v = rs[mt][hf2];
            v += __shfl_xor_sync(0xffffffffu, v, 1);
            v += __shfl_xor_sync(0xffffffffu, v, 2);
            if (tg == 0)
                part[wm * 32 + mt * 16 + g + hf2 * 8][wn] = v;
        }
    __syncthreads();
    if (tid < 64) {
        float s = b4[0] + part[tid][0] + part[tid][1] + part[tid][2] + part[tid][3];
        int cc = c0 + (tid >> 5), ss = tid & 31;
        logits[((size_t)b * C + cc) * T + ss] = s;
    }
}

// ---------------------------------------------------------------------------
// 5) Softmax over dim-0 per column, mean over columns (proven)
// ---------------------------------------------------------------------------
__global__ __launch_bounds__(256) void softmax_colreduce(
    const float* __restrict__ logits, float* __restrict__ cmax, float* __restrict__ csum)
{
    int t = blockIdx.x;
    int tid = threadIdx.x;
    __shared__ float red[256];
    float m = -1e30f;
    for (int i = tid; i < B * C; i += 256) m = fmaxf(m, logits[(size_t)i * T + t]);
    red[tid] = m; __syncthreads();
    for (int s = 128; s > 0; s >>= 1) {
        if (tid < s) red[tid] = fmaxf(red[tid], red[tid + s]);
        __syncthreads();
    }
    float mx = red[0];
    __syncthreads();
    float sum = 0.f;
    for (int i = tid; i < B * C; i += 256) sum += expf(logits[(size_t)i * T + t] - mx);
    red[tid] = sum; __syncthreads();
    for (int s = 128; s > 0; s >>= 1) {
        if (tid < s) red[tid] += red[tid + s];
        __syncthreads();
    }
    if (tid == 0) { cmax[t] = mx; csum[t] = red[0]; }
}

__global__ __launch_bounds__(256) void softmax_out(
    const float* __restrict__ logits, const float* __restrict__ cmax,
    const float* __restrict__ csum, float* __restrict__ out)
{
    __shared__ float mS[T], sS[T];
    int tid = threadIdx.x;
    if (tid < T) { mS[tid] = cmax[tid]; sS[tid] = csum[tid]; }
    __syncthreads();
    int i = blockIdx.x * 256 + tid;
    if (i < B * C) {
        float a = 0.f;
        const float* row = logits + (size_t)i * T;
#pragma unroll
        for (int t = 0; t < T; t++) a += expf(row[t] - mS[t]) / sS[t];
        out[i] = a * (1.f / (float)T);
    }
}

// ---------------------------------------------------------------------------
// Launch
// ---------------------------------------------------------------------------
extern "C" void kernel_launch(void* const* d_in, const int* in_sizes, int n_in,
                              void* d_out, int out_size)
{
    const float* batch_features  = (const float*)d_in[0];
    const float* batch_att       = (const float*)d_in[1];
    const float* batch_attrs     = (const float*)d_in[2];
    const float* fc1_w = (const float*)d_in[3];
    const float* fc1_b = (const float*)d_in[4];
    const float* fc2_w = (const float*)d_in[5];
    const float* fc2_b = (const float*)d_in[6];
    const float* fc3_w = (const float*)d_in[7];
    const float* fc3_b = (const float*)d_in[8];
    const float* fc4_w = (const float*)d_in[9];
    const float* fc4_b = (const float*)d_in[10];
    const float* gru_wih_f = (const float*)d_in[11];
    const float* gru_whh_f = (const float*)d_in[12];
    const float* gru_bih_f = (const float*)d_in[13];
    const float* gru_bhh_f = (const float*)d_in[14];
    const float* gru_wih_b = (const float*)d_in[15];
    const float* gru_whh_b = (const float*)d_in[16];
    const float* gru_bih_b = (const float*)d_in[17];
    const float* gru_bhh_b = (const float*)d_in[18];
    float* out = (float*)d_out;

    float* GI;     cudaGetSymbolAddress((void**)&GI,     g_GI);
    float* feats;  cudaGetSymbolAddress((void**)&feats,  g_feats);
    float* attr1;  cudaGetSymbolAddress((void**)&attr1,  g_attr1);
    float* attr2;  cudaGetSymbolAddress((void**)&attr2,  g_attr2);
    float* logits; cudaGetSymbolAddress((void**)&logits, g_logits);
    float* cmax;   cudaGetSymbolAddress((void**)&cmax,   g_cmax);
    float* csum;   cudaGetSymbolAddress((void**)&csum,   g_csum);
    float* bpack;  cudaGetSymbolAddress((void**)&bpack,  g_bih_pack);
    __nv_bfloat16* Whi; cudaGetSymbolAddress((void**)&Whi, g_Whi);
    __nv_bfloat16* Wlo; cudaGetSymbolAddress((void**)&Wlo, g_Wlo);
    __nv_bfloat16* Ahi; cudaGetSymbolAddress((void**)&Ahi, g_Ahi);
    __nv_bfloat16* Alo; cudaGetSymbolAddress((void**)&Alo, g_Alo);
    __nv_bfloat16* w3hi; cudaGetSymbolAddress((void**)&w3hi, g_w3hi);
    __nv_bfloat16* w3lo; cudaGetSymbolAddress((void**)&w3lo, g_w3lo);
    float* fc2p;   cudaGetSymbolAddress((void**)&fc2p,   g_fc2part);
    int* rmin;     cudaGetSymbolAddress((void**)&rmin,   g_rmin);
    int* rmout;    cudaGetSymbolAddress((void**)&rmout,  g_rmout);
    int* cnt;      cudaGetSymbolAddress((void**)&cnt,    g_count);
    int* mnz;      cudaGetSymbolAddress((void**)&mnz,    g_mnz);

    build_maps<<<1, 64>>>(batch_att, rmin, rmout, cnt, mnz);
    pack_wih_bf16<<<(GI_W * D / 4 + 255) / 256, 256>>>(gru_wih_f, gru_wih_b,
                                                       gru_bih_f, gru_bih_b,
                                                       Whi, Wlo, bpack);
    split_w3_bf16<<<(256 * 512 / 2 + 255) / 256, 256>>>(fc3_w, w3hi, w3lo);
    conv_feats<<<B * T, 128>>>(batch_features, rmin, mnz, Ahi, Alo);

    // GI projection (bf16 3-split, pre-converted, no prefetch)
    {
        dim3 grid(GI_W / 64, (B * T) / 128);   // (24, 16); ~half exit early
        gemm_bf16_gi<<<grid, 256>>>(Ahi, Alo, Whi, Wlo, bpack, GI, rmout, mnz);
    }

    // GRU recurrence
    {
        int smem = (12 * 65 + 64 * 65) * (int)sizeof(float4);
        cudaFuncSetAttribute(gru_kernel, cudaFuncAttributeMaxDynamicSharedMemorySize, smem);
        gru_kernel<<<GRU_BLOCKS, 256, smem>>>(GI, gru_whh_f, gru_whh_b,
                                              gru_bhh_f, gru_bhh_b, bpack, cnt, feats);
    }

    // semantic net
    gemm_tn<true><<<dim3(4096 / 64, 1), 256>>>(batch_attrs, A_, fc1_w, A_, fc1_b,
                                               attr1, 4096, C, 4096, A_);
    fc2_part<<<dim3(8, 4), 256>>>(attr1, fc2_w, fc2p);
    fc2_reduce<<<(C * 512 + 255) / 256, 256>>>(fc2p, fc2_b, attr2);

    // relation head (bf16 3-split, proven)
    relation_bf16<<<dim3(C / 2, B), 256>>>(feats, attr2, w3hi, w3lo,
                                           fc3_b, fc4_w, fc4_b, logits);

    softmax_colreduce<<<T, 256>>>(logits, cmax, csum);
    softmax_out<<<(B * C + 255) / 256, 256>>>(logits, cmax, csum, out);
}

// round 14
// speedup vs baseline: 1.1793x; 1.0335x over previous
#include <cuda_runtime.h>
#include <cuda_bf16.h>
#include <math.h>
#include <stdint.h>

#define B    64
#define T    32
#define D    4096
#define C    50
#define A_   300
#define H    256
#define GI_W 1536

// ---------------------------------------------------------------------------
// Scratch
// ---------------------------------------------------------------------------
__device__ float g_GI[B * T * GI_W];
__device__ float g_feats[B * T * 512];
__device__ float g_attr1[C * 4096];
__device__ float g_attr2[C * 512];
__device__ float g_logits[B * C * T];
__device__ float g_cmax[T];
__device__ float g_csum[T];
__device__ float g_hbuf[2 * 2 * B * H];
__device__ float g_bih_pack[GI_W];
__device__ __nv_bfloat16 g_Whi[GI_W * D];
__device__ __nv_bfloat16 g_Wlo[GI_W * D];
__device__ __nv_bfloat16 g_Ahi[B * T * D];
__device__ __nv_bfloat16 g_Alo[B * T * D];
__device__ __nv_bfloat16 g_w3hi[256 * 512];
__device__ __nv_bfloat16 g_w3lo[256 * 512];
__device__ float g_fc2part[4 * 64 * 512];
__device__ int   g_rmin[B * T];
__device__ int   g_rmout[B * T];
__device__ int   g_count[B];
__device__ int   g_mnz[1];
__device__ int          g_bar_count;
__device__ unsigned int g_bar_gen;

// ---------------------------------------------------------------------------
// bf16 / sync helpers (proven)
// ---------------------------------------------------------------------------
__device__ __forceinline__ void mma16(float* c, const uint32_t* a, const uint32_t* b)
{
    asm volatile(
        "mma.sync.aligned.m16n8k16.row.col.f32.bf16.bf16.f32 "
        "{%0,%1,%2,%3},{%4,%5,%6,%7},{%8,%9},{%0,%1,%2,%3};"
        : "+f"(c[0]), "+f"(c[1]), "+f"(c[2]), "+f"(c[3])
        : "r"(a[0]), "r"(a[1]), "r"(a[2]), "r"(a[3]), "r"(b[0]), "r"(b[1]));
}

__device__ __forceinline__ void bsplit2(float x, float y, uint32_t& hw, uint32_t& lw)
{
    __nv_bfloat16 hx = __float2bfloat16(x);
    __nv_bfloat16 hy = __float2bfloat16(y);
    float rx = x - __bfloat162float(hx);
    float ry = y - __bfloat162float(hy);
    __nv_bfloat162 hp; hp.x = hx; hp.y = hy;
    __nv_bfloat162 lp; lp.x = __float2bfloat16(rx); lp.y = __float2bfloat16(ry);
    hw = *reinterpret_cast<uint32_t*>(&hp);
    lw = *reinterpret_cast<uint32_t*>(&lp);
}

__device__ __forceinline__ unsigned ld_acq(const unsigned* p)
{
    unsigned v;
    asm volatile("ld.acquire.gpu.u32 %0,[%1];" : "=r"(v) : "l"(p) : "memory");
    return v;
}
__device__ __forceinline__ void st_rel(unsigned* p, unsigned v)
{
    asm volatile("st.release.gpu.u32 [%0],%1;" :: "l"(p), "r"(v) : "memory");
}

// ---------------------------------------------------------------------------
// 0a) Pack GRU input weights to bf16 hi/lo + fp32 bias (proven)
// ---------------------------------------------------------------------------
__global__ __launch_bounds__(256) void pack_wih_bf16(
    const float* __restrict__ wf, const float* __restrict__ wb,
    const float* __restrict__ bf, const float* __restrict__ bb,
    __nv_bfloat16* __restrict__ whi, __nv_bfloat16* __restrict__ wlo,
    float* __restrict__ bp)
{
    int i = blockIdx.x * 256 + threadIdx.x;
    const int TOT4 = GI_W * D / 4;
    if (i < TOT4) {
        int row = (i * 4) / D;
        float4 v = (row < 768) ? ((const float4*)wf)[i]
                               : ((const float4*)wb)[i - 768 * (D / 4)];
        uint32_t h0, l0, h1, l1;
        bsplit2(v.x, v.y, h0, l0);
        bsplit2(v.z, v.w, h1, l1);
        ((uint2*)whi)[i] = make_uint2(h0, h1);
        ((uint2*)wlo)[i] = make_uint2(l0, l1);
    }
    if (i < GI_W) bp[i] = (i < 768) ? bf[i] : bb[i - 768];
}

// 0b) Pre-split w3 to bf16 hi/lo (proven)
__global__ __launch_bounds__(256) void split_w3_bf16(
    const float* __restrict__ w3,
    __nv_bfloat16* __restrict__ hh, __nv_bfloat16* __restrict__ ll)
{
    int i = blockIdx.x * 256 + threadIdx.x;
    if (i < 256 * 512 / 2) {
        float2 v = ((const float2*)w3)[i];
        uint32_t h, l;
        bsplit2(v.x, v.y, h, l);
        ((uint32_t*)hh)[i] = h;
        ((uint32_t*)ll)[i] = l;
    }
}

// ---------------------------------------------------------------------------
// 1) Bookkeeping (proven)
// ---------------------------------------------------------------------------
__global__ void build_maps(
    const float* __restrict__ att,
    int* __restrict__ rmin, int* __restrict__ rmout,
    int* __restrict__ count, int* __restrict__ mnz)
{
    __shared__ int cnts[B], offs[B];
    int b = threadIdx.x;
    float a[T];
    float s = 0.f;
#pragma unroll
    for (int t = 0; t < T; t++) { a[t] = att[b * T + t]; s += a[t]; }
    float thr = s / (float)T;
    int ord[T];
    int c = 0;
#pragma unroll
    for (int t = 0; t < T; t++) if (a[t] >= thr) ord[c++] = t;
    cnts[b] = c;
    __syncthreads();
    if (b == 0) {
        int acc = 0;
        for (int i = 0; i < B; i++) { offs[i] = acc; acc += cnts[i]; }
        *mnz = acc;
    }
    __syncthreads();
    int o = offs[b];
    for (int s2 = 0; s2 < c; s2++) {
        rmin[o + s2]  = b * T + ord[s2];
        rmout[o + s2] = b * T + s2;
    }
    count[b] = c;
}

// ---------------------------------------------------------------------------
// 1b) Gather + convert selected rows (proven; zero-fills all 2048 rows)
// ---------------------------------------------------------------------------
__global__ __launch_bounds__(128) void conv_feats(
    const float* __restrict__ bf,
    const int* __restrict__ rmin, const int* __restrict__ mnzp,
    __nv_bfloat16* __restrict__ Ahi, __nv_bfloat16* __restrict__ Alo)
{
    int i = blockIdx.x;
    int tid = threadIdx.x;
    int Mnz = *mnzp;
    uint2* oh = (uint2*)(Ahi + (size_t)i * D);
    uint2* ol = (uint2*)(Alo + (size_t)i * D);
    if (i < Mnz) {
        const float4* src = (const float4*)(bf + (size_t)rmin[i] * D);
        for (int j = tid; j < D / 4; j += 128) {
            float4 v = src[j];
            uint32_t h0, l0, h1, l1;
            bsplit2(v.x, v.y, h0, l0);
            bsplit2(v.z, v.w, h1, l1);
            oh[j] = make_uint2(h0, h1);
            ol[j] = make_uint2(l0, l1);
        }
    } else {
        uint2 z = make_uint2(0u, 0u);
        for (int j = tid; j < D / 4; j += 128) { oh[j] = z; ol[j] = z; }
    }
}

// ---------------------------------------------------------------------------
// 2) GI projection: bf16 3-split, 128x96 tiles (128 active CTAs = 1/SM),
//    single-buffer load->sync->compute->sync (the ONLY proven-safe structure).
// ---------------------------------------------------------------------------
__global__ __launch_bounds__(256, 2) void gemm_bf16_gi(
    const __nv_bfloat16* __restrict__ Ahi, const __nv_bfloat16* __restrict__ Alo,
    const __nv_bfloat16* __restrict__ Whi, const __nv_bfloat16* __restrict__ Wlo,
    const float* __restrict__ bias,
    float* __restrict__ Cg,
    const int* __restrict__ rmout,
    const int* __restrict__ mnzp)
{
    int Mnz = *mnzp;
    int row0 = blockIdx.y * 128, col0 = blockIdx.x * 96;
    if (row0 >= Mnz) return;

    __shared__ uint32_t Ah_s[128 * 12], Al_s[128 * 12];
    __shared__ uint32_t Wh_s[96 * 12],  Wl_s[96 * 12];

    int tid  = threadIdx.x;
    int lane = tid & 31, warp = tid >> 5;
    int wm = warp >> 1, wn = warp & 1;     // warp tile 32(M) x 48(N)
    int g  = lane >> 2, tg = lane & 3;

    float c[2][6][4];
#pragma unroll
    for (int mt = 0; mt < 2; mt++)
#pragma unroll
        for (int nt = 0; nt < 6; nt++)
#pragma unroll
            for (int r = 0; r < 4; r++) c[mt][nt][r] = 0.f;

    int lr = tid >> 1;            // 0..127 (A row)
    int hf = tid & 1;             // k half (8 bf16)
    const __nv_bfloat16* arh = Ahi + (size_t)(row0 + lr) * D;
    const __nv_bfloat16* arl = Alo + (size_t)(row0 + lr) * D;
    int wr = (tid < 192) ? (tid >> 1) : 0;   // W row 0..95
    const __nv_bfloat16* wrh = Whi + (size_t)(col0 + wr) * D;
    const __nv_bfloat16* wrl = Wlo + (size_t)(col0 + wr) * D;

    for (int k0 = 0; k0 < D; k0 += 16) {
        int off = lr * 12 + hf * 4;
        *(uint4*)&Ah_s[off] = ((const uint4*)(arh + k0))[hf];
        *(uint4*)&Al_s[off] = ((const uint4*)(arl + k0))[hf];
        if (tid < 192) {
            int woff = wr * 12 + hf * 4;
            *(uint4*)&Wh_s[woff] = ((const uint4*)(wrh + k0))[hf];
            *(uint4*)&Wl_s[woff] = ((const uint4*)(wrl + k0))[hf];
        }
        __syncthreads();

        uint32_t a_h[2][4], a_l[2][4];
#pragma unroll
        for (int mt = 0; mt < 2; mt++) {
            int m0 = wm * 32 + mt * 16;
            a_h[mt][0] = Ah_s[(m0 + g) * 12 + tg];
            a_h[mt][1] = Ah_s[(m0 + g + 8) * 12 + tg];
            a_h[mt][2] = Ah_s[(m0 + g) * 12 + tg + 4];
            a_h[mt][3] = Ah_s[(m0 + g + 8) * 12 + tg + 4];
            a_l[mt][0] = Al_s[(m0 + g) * 12 + tg];
            a_l[mt][1] = Al_s[(m0 + g + 8) * 12 + tg];
            a_l[mt][2] = Al_s[(m0 + g) * 12 + tg + 4];
            a_l[mt][3] = Al_s[(m0 + g + 8) * 12 + tg + 4];
        }
#pragma unroll
        for (int nt = 0; nt < 6; nt++) {
            int n0 = wn * 48 + nt * 8;
            uint32_t bh[2], bl[2];
            bh[0] = Wh_s[(n0 + g) * 12 + tg];
            bh[1] = Wh_s[(n0 + g) * 12 + tg + 4];
            bl[0] = Wl_s[(n0 + g) * 12 + tg];
            bl[1] = Wl_s[(n0 + g) * 12 + tg + 4];
#pragma unroll
            for (int mt = 0; mt < 2; mt++) {
                mma16(c[mt][nt], a_h[mt], bh);
                mma16(c[mt][nt], a_l[mt], bh);
                mma16(c[mt][nt], a_h[mt], bl);
            }
        }
        __syncthreads();
    }

#pragma unroll
    for (int mt = 0; mt < 2; mt++) {
        int mrow1 = row0 + wm * 32 + mt * 16 + g;
        int mrow2 = mrow1 + 8;
        int ro1 = (mrow1 < Mnz) ? rmout[mrow1] : -1;
        int ro2 = (mrow2 < Mnz) ? rmout[mrow2] : -1;
#pragma unroll
        for (int nt = 0; nt < 6; nt++) {
            int col = col0 + wn * 48 + nt * 8 + 2 * tg;
            float b0 = bias[col], b1 = bias[col + 1];
            if (ro1 >= 0)
                *(float2*)(Cg + (size_t)ro1 * GI_W + col) =
                    make_float2(c[mt][nt][0] + b0, c[mt][nt][1] + b1);
            if (ro2 >= 0)
                *(float2*)(Cg + (size_t)ro2 * GI_W + col) =
                    make_float2(c[mt][nt][2] + b0, c[mt][nt][3] + b1);
        }
    }
}

// ---------------------------------------------------------------------------
// 2b) Small-M GEMM (fc1) and fc2 K-split (proven)
// ---------------------------------------------------------------------------
template <bool RELU>
__global__ __launch_bounds__(256) void gemm_tn(
    const float* __restrict__ Ag, int lda,
    const float* __restrict__ Wg, int ldw,
    const float* __restrict__ bias,
    float* __restrict__ Cg, int ldc,
    int M, int N, int K)
{
    __shared__ float As[16][65];
    __shared__ float Ws[16][65];
    int tid  = threadIdx.x;
    int row0 = blockIdx.y * 64;
    int col0 = blockIdx.x * 64;
    int lm = tid >> 2;
    int lk = (tid & 3) * 4;
    int ty = tid >> 4;
    int tx = tid & 15;
    float acc[4][4];
#pragma unroll
    for (int i = 0; i < 4; i++)
#pragma unroll
        for (int j = 0; j < 4; j++) acc[i][j] = 0.f;

    for (int k0 = 0; k0 < K; k0 += 16) {
        int r = row0 + lm;
        int cc = col0 + lm;
#pragma unroll
        for (int i = 0; i < 4; i++) {
            int k = k0 + lk + i;
            As[lk + i][lm] = (r < M && k < K) ? Ag[(size_t)r * lda + k] : 0.f;
            Ws[lk + i][lm] = (cc < N && k < K) ? Wg[(size_t)cc * ldw + k] : 0.f;
        }
        __syncthreads();
#pragma unroll
        for (int kk = 0; kk < 16; kk++) {
            float a[4], w[4];
#pragma unroll
            for (int i = 0; i < 4; i++) a[i] = As[kk][ty + 16 * i];
#pragma unroll
            for (int j = 0; j < 4; j++) w[j] = Ws[kk][tx + 16 * j];
#pragma unroll
            for (int i = 0; i < 4; i++)
#pragma unroll
                for (int j = 0; j < 4; j++)
                    acc[i][j] = fmaf(a[i], w[j], acc[i][j]);
        }
        __syncthreads();
    }

#pragma unroll
    for (int i = 0; i < 4; i++) {
        int r = row0 + ty + 16 * i;
        if (r >= M) continue;
#pragma unroll
        for (int j = 0; j < 4; j++) {
            int cc = col0 + tx + 16 * j;
            if (cc >= N) continue;
            float v = acc[i][j] + bias[cc];
            if (RELU) v = fmaxf(v, 0.f);
            Cg[(size_t)r * ldc + cc] = v;
        }
    }
}

__global__ __launch_bounds__(256) void fc2_part(
    const float* __restrict__ Ag,
    const float* __restrict__ Wg,
    float* __restrict__ Pout)
{
    __shared__ float As[16][65];
    __shared__ float Ws[16][65];
    int tid  = threadIdx.x;
    int col0 = blockIdx.x * 64;
    int kbeg = blockIdx.y * 1024;
    int lm = tid >> 2;
    int lk = (tid & 3) * 4;
    int ty = tid >> 4;
    int tx = tid & 15;
    float acc[4][4];
#pragma unroll
    for (int i = 0; i < 4; i++)
#pragma unroll
        for (int j = 0; j < 4; j++) acc[i][j] = 0.f;

    for (int k0 = kbeg; k0 < kbeg + 1024; k0 += 16) {
        int cc = col0 + lm;
#pragma unroll
        for (int i = 0; i < 4; i++) {
            int k = k0 + lk + i;
            As[lk + i][lm] = (lm < C) ? Ag[(size_t)lm * 4096 + k] : 0.f;
            Ws[lk + i][lm] = Wg[(size_t)cc * 4096 + k];
        }
        __syncthreads();
#pragma unroll
        for (int kk = 0; kk < 16; kk++) {
            float a[4], w[4];
#pragma unroll
            for (int i = 0; i < 4; i++) a[i] = As[kk][ty + 16 * i];
#pragma unroll
            for (int j = 0; j < 4; j++) w[j] = Ws[kk][tx + 16 * j];
#pragma unroll
            for (int i = 0; i < 4; i++)
#pragma unroll
                for (int j = 0; j < 4; j++)
                    acc[i][j] = fmaf(a[i], w[j], acc[i][j]);
        }
        __syncthreads();
    }

    float* base = Pout + (size_t)blockIdx.y * (64 * 512);
#pragma unroll
    for (int i = 0; i < 4; i++) {
        int r = ty + 16 * i;
        if (r >= C) continue;
#pragma unroll
        for (int j = 0; j < 4; j++) {
            int cc = col0 + tx + 16 * j;
            base[(size_t)r * 512 + cc] = acc[i][j];
        }
    }
}

__global__ __launch_bounds__(256) void fc2_reduce(
    const float* __restrict__ P, const float* __restrict__ bias,
    float* __restrict__ attr2)
{
    int idx = blockIdx.x * 256 + threadIdx.x;
    if (idx < C * 512) {
        int r = idx >> 9, cc = idx & 511;
        float v = bias[cc];
#pragma unroll
        for (int kc = 0; kc < 4; kc++)
            v += P[(size_t)kc * (64 * 512) + r * 512 + cc];
        attr2[idx] = fmaxf(v, 0.f);
    }
}

// ---------------------------------------------------------------------------
// 3) GRU recurrence (proven, byte-identical)
// ---------------------------------------------------------------------------
#define GRU_BLOCKS 128

__device__ __forceinline__ void grid_barrier()
{
    __syncthreads();
    if (threadIdx.x == 0) {
        __threadfence();
        unsigned g = ld_acq(&g_bar_gen);
        if (atomicAdd(&g_bar_count, 1) == GRU_BLOCKS - 1) {
            g_bar_count = 0;
            st_rel(&g_bar_gen, g + 1);
        } else {
            while (ld_acq(&g_bar_gen) == g) { __nanosleep(16); }
        }
    }
    __syncthreads();
}

__global__ __launch_bounds__(256) void gru_kernel(
    const float* __restrict__ GI,
    const float* __restrict__ whh_f, const float* __restrict__ whh_b,
    const float* __restrict__ bhh_f, const float* __restrict__ bhh_b,
    const float* __restrict__ bpack,
    const int*   __restrict__ count,
    float* __restrict__ feats)
{
    extern __shared__ float4 sm4[];
    float4* sW4 = sm4;
    float4* hS4 = sm4 + 12 * 65;

    int d  = blockIdx.x >> 6;
    int hc = blockIdx.x & 63;
    int tid = threadIdx.x;
    int b = tid >> 2;
    int u = tid & 3;
    int i = hc * 4 + u;

    const float* whh = d ? whh_b : whh_f;
    const float* bhh = d ? bhh_b : bhh_f;

    for (int t = tid; t < 12 * 64; t += 256) {
        int rr = t >> 6;
        int k4 = t & 63;
        int g  = rr >> 2, uu = rr & 3;
        int row = g * H + hc * 4 + uu;
        sW4[rr * 65 + k4] = ((const float4*)(whh + (size_t)row * H))[k4];
    }
    float br = bhh[i], bz = bhh[H + i], bn = bhh[2 * H + i];
    float ir0 = bpack[d * 768 + i];
    float iz0 = bpack[d * 768 + 256 + i];
    float in0 = bpack[d * 768 + 512 + i];
    int cnt_b = count[b];
    __syncthreads();

    float h = 0.f;

    for (int t = 0; t < T; t++) {
        float ar = 0.f, az = 0.f, an = 0.f;
        if (t > 0) {
            int p = t & 1;
            const float4* hp4 = (const float4*)(g_hbuf + p * (2 * B * H) + d * (B * H));
            for (int idx = tid; idx < B * (H / 4); idx += 256)
                hS4[(idx >> 6) * 65 + (idx & 63)] = __ldcg(&hp4[idx]);
            __syncthreads();

            const float4* hb = &hS4[b * 65];
            const float4* wr = &sW4[(0 + u) * 65];
            const float4* wz = &sW4[(4 + u) * 65];
            const float4* wn = &sW4[(8 + u) * 65];
#pragma unroll 16
            for (int k4 = 0; k4 < 64; k4++) {
                float4 hv = hb[k4];
                float4 a  = wr[k4];
                ar = fmaf(hv.x, a.x, fmaf(hv.y, a.y, fmaf(hv.z, a.z, fmaf(hv.w, a.w, ar))));
                float4 zz = wz[k4];
                az = fmaf(hv.x, zz.x, fmaf(hv.y, zz.y, fmaf(hv.z, zz.z, fmaf(hv.w, zz.w, az))));
                float4 nn = wn[k4];
                an = fmaf(hv.x, nn.x, fmaf(hv.y, nn.y, fmaf(hv.z, nn.z, fmaf(hv.w, nn.w, an))));
            }
        }

        int s = d ? (T - 1 - t) : t;
        float ir = ir0, iz = iz0, in_ = in0;
        if (s < cnt_b) {
            const float* gi = GI + ((size_t)b * T + s) * GI_W + d * 768;
            ir  = gi[i];
            iz  = gi[H + i];
            in_ = gi[2 * H + i];
        }

        float r = 1.f / (1.f + expf(-(ir + ar + br)));
        float z = 1.f / (1.f + expf(-(iz + az + bz)));
        float n = tanhf(in_ + r * (an + bn));
        h = (1.f - z) * n + z * h;

        feats[((size_t)b * T + s) * 512 + d * H + i] = h;
        if (t < T - 1) {
            g_hbuf[((t & 1) ^ 1) * (2 * B * H) + d * (B * H) + b * H + i] = h;
            grid_barrier();
        }
    }
}

// ---------------------------------------------------------------------------
// 4) Relation head, bf16 3-split tensor cores (proven, byte-identical)
// ---------------------------------------------------------------------------
__global__ __launch_bounds__(256, 2) void relation_bf16(
    const float* __restrict__ feats,
    const float* __restrict__ attr2,
    const __nv_bfloat16* __restrict__ w3hi,
    const __nv_bfloat16* __restrict__ w3lo,
    const float* __restrict__ b3,
    const float* __restrict__ w4,
    const float* __restrict__ b4,
    float* __restrict__ logits)
{
    __shared__ uint32_t Dh_s[64 * 12], Dl_s[64 * 12];
    __shared__ uint32_t Wh_s[256 * 12], Wl_s[256 * 12];
    __shared__ float aS[2 * 512];
    __shared__ float part[64][5];

    int c0 = blockIdx.x * 2;
    int b  = blockIdx.y;
    int tid  = threadIdx.x;
    int lane = tid & 31, warp = tid >> 5;
    int wm = warp >> 2, wn = warp & 3;
    int g  = lane >> 2, tg = lane & 3;

    for (int t = tid; t < 1024; t += 256)
        aS[t] = attr2[(size_t)(c0 + (t >> 9)) * 512 + (t & 511)];
    __syncthreads();

    float c[2][8][4];
#pragma unroll
    for (int mt = 0; mt < 2; mt++)
#pragma unroll
        for (int nt = 0; nt < 8; nt++)
#pragma unroll
            for (int r = 0; r < 4; r++) c[mt][nt][r] = 0.f;

    int dm = tid >> 2;
    int dk = (tid & 3) * 4;
    int ds = dm & 31, dc = dm >> 5;
    const float* frow = feats + ((size_t)b * T + ds) * 512;
    const __nv_bfloat16* w3h_row = w3hi + (size_t)tid * 512;
    const __nv_bfloat16* w3l_row = w3lo + (size_t)tid * 512;

    for (int k0 = 0; k0 < 512; k0 += 16) {
        {
            float4 f = *(const float4*)(frow + k0 + dk);
            float4 a = *(const float4*)(aS + dc * 512 + k0 + dk);
            float d0 = f.x - a.x, d1 = f.y - a.y;
            float d2 = f.z - a.z, d3 = f.w - a.w;
            uint32_t h0, l0, h1, l1;
            bsplit2(d0 * d0, d1 * d1, h0, l0);
            bsplit2(d2 * d2, d3 * d3, h1, l1);
            int w = (tid & 3) * 2;
            Dh_s[dm * 12 + w]     = h0;
            Dh_s[dm * 12 + w + 1] = h1;
            Dl_s[dm * 12 + w]     = l0;
            Dl_s[dm * 12 + w + 1] = l1;
        }
        {
            uint4 wh0 = ((const uint4*)(w3h_row + k0))[0];
            uint4 wh1 = ((const uint4*)(w3h_row + k0))[1];
            uint4 wl0 = ((const uint4*)(w3l_row + k0))[0];
            uint4 wl1 = ((const uint4*)(w3l_row + k0))[1];
            *(uint4*)&Wh_s[tid * 12 + 0] = wh0;
            *(uint4*)&Wh_s[tid * 12 + 4] = wh1;
            *(uint4*)&Wl_s[tid * 12 + 0] = wl0;
            *(uint4*)&Wl_s[tid * 12 + 4] = wl1;
        }
        __syncthreads();

        uint32_t a_h[2][4], a_l[2][4];
#pragma unroll
        for (int mt = 0; mt < 2; mt++) {
            int m0 = wm * 32 + mt * 16;
            a_h[mt][0] = Dh_s[(m0 + g) * 12 + tg];
            a_h[mt][1] = Dh_s[(m0 + g + 8) * 12 + tg];
            a_h[mt][2] = Dh_s[(m0 + g) * 12 + tg + 4];
            a_h[mt][3] = Dh_s[(m0 + g + 8) * 12 + tg + 4];
            a_l[mt][0] = Dl_s[(m0 + g) * 12 + tg];
            a_l[mt][1] = Dl_s[(m0 + g + 8) * 12 + tg];
            a_l[mt][2] = Dl_s[(m0 + g) * 12 + tg + 4];
            a_l[mt][3] = Dl_s[(m0 + g + 8) * 12 + tg + 4];
        }
#pragma unroll
        for (int nt = 0; nt < 8; nt++) {
            int n0 = wn * 64 + nt * 8;
            uint32_t bh[2], bl[2];
            bh[0] = Wh_s[(n0 + g) * 12 + tg];
            bh[1] = Wh_s[(n0 + g) * 12 + tg + 4];
            bl[0] = Wl_s[(n0 + g) * 12 + tg];
            bl[1] = Wl_s[(n0 + g) * 12 + tg + 4];
#pragma unroll
            for (int mt = 0; mt < 2; mt++) {
                mma16(c[mt][nt], a_h[mt], bh);
                mma16(c[mt][nt], a_l[mt], bh);
                mma16(c[mt][nt], a_h[mt], bl);
            }
        }
        __syncthreads();
    }

    float rs[2][2] = {{0.f, 0.f}, {0.f, 0.f}};
#pragma unroll
    for (int nt = 0; nt < 8; nt++) {
        int col = wn * 64 + nt * 8 + 2 * tg;
        float w40 = w4[col], w41 = w4[col + 1];
        float b30 = b3[col], b31 = b3[col + 1];
#pragma unroll
        for (int mt = 0; mt < 2; mt++) {
            rs[mt][0] += fmaxf(c[mt][nt][0] + b30, 0.f) * w40
                       + fmaxf(c[mt][nt][1] + b31, 0.f) * w41;
            rs[mt][1] += fmaxf(c[mt][nt][2] + b30, 0.f) * w40
                       + fmaxf(c[mt][nt][3] + b31, 0.f) * w41;
        }
    }
#pragma unroll
    for (int mt = 0; mt < 2; mt++)
#pragma unroll
        for (int hf2 = 0; hf2 < 2; hf2++) {
            float v = rs[mt][hf2];
            v += __shfl_xor_sync(0xffffffffu, v, 1);
            v += __shfl_xor_sync(0xffffffffu, v, 2);
            if (tg == 0)
                part[wm * 32 + mt * 16 + g + hf2 * 8][wn] = v;
        }
    __syncthreads();
    if (tid < 64) {
        float s = b4[0] + part[tid][0] + part[tid][1] + part[tid][2] + part[tid][3];
        int cc = c0 + (tid >> 5), ss = tid & 31;
        logits[((size_t)b * C + cc) * T + ss] = s;
    }
}

// ---------------------------------------------------------------------------
// 5) Softmax over dim-0 per column, mean over columns (proven)
// ---------------------------------------------------------------------------
__global__ __launch_bounds__(256) void softmax_colreduce(
    const float* __restrict__ logits, float* __restrict__ cmax, float* __restrict__ csum)
{
    int t = blockIdx.x;
    int tid = threadIdx.x;
    __shared__ float red[256];
    float m = -1e30f;
    for (int i = tid; i < B * C; i += 256) m = fmaxf(m, logits[(size_t)i * T + t]);
    red[tid] = m; __syncthreads();
    for (int s = 128; s > 0; s >>= 1) {
        if (tid < s) red[tid] = fmaxf(red[tid], red[tid + s]);
        __syncthreads();
    }
    float mx = red[0];
    __syncthreads();
    float sum = 0.f;
    for (int i = tid; i < B * C; i += 256) sum += expf(logits[(size_t)i * T + t] - mx);
    red[tid] = sum; __syncthreads();
    for (int s = 128; s > 0; s >>= 1) {
        if (tid < s) red[tid] += red[tid + s];
        __syncthreads();
    }
    if (tid == 0) { cmax[t] = mx; csum[t] = red[0]; }
}

__global__ __launch_bounds__(256) void softmax_out(
    const float* __restrict__ logits, const float* __restrict__ cmax,
    const float* __restrict__ csum, float* __restrict__ out)
{
    __shared__ float mS[T], sS[T];
    int tid = threadIdx.x;
    if (tid < T) { mS[tid] = cmax[tid]; sS[tid] = csum[tid]; }
    __syncthreads();
    int i = blockIdx.x * 256 + tid;
    if (i < B * C) {
        float a = 0.f;
        const float* row = logits + (size_t)i * T;
#pragma unroll
        for (int t = 0; t < T; t++) a += expf(row[t] - mS[t]) / sS[t];
        out[i] = a * (1.f / (float)T);
    }
}

// ---------------------------------------------------------------------------
// Launch
// ---------------------------------------------------------------------------
extern "C" void kernel_launch(void* const* d_in, const int* in_sizes, int n_in,
                              void* d_out, int out_size)
{
    const float* batch_features  = (const float*)d_in[0];
    const float* batch_att       = (const float*)d_in[1];
    const float* batch_attrs     = (const float*)d_in[2];
    const float* fc1_w = (const float*)d_in[3];
    const float* fc1_b = (const float*)d_in[4];
    const float* fc2_w = (const float*)d_in[5];
    const float* fc2_b = (const float*)d_in[6];
    const float* fc3_w = (const float*)d_in[7];
    const float* fc3_b = (const float*)d_in[8];
    const float* fc4_w = (const float*)d_in[9];
    const float* fc4_b = (const float*)d_in[10];
    const float* gru_wih_f = (const float*)d_in[11];
    const float* gru_whh_f = (const float*)d_in[12];
    const float* gru_bih_f = (const float*)d_in[13];
    const float* gru_bhh_f = (const float*)d_in[14];
    const float* gru_wih_b = (const float*)d_in[15];
    const float* gru_whh_b = (const float*)d_in[16];
    const float* gru_bih_b = (const float*)d_in[17];
    const float* gru_bhh_b = (const float*)d_in[18];
    float* out = (float*)d_out;

    float* GI;     cudaGetSymbolAddress((void**)&GI,     g_GI);
    float* feats;  cudaGetSymbolAddress((void**)&feats,  g_feats);
    float* attr1;  cudaGetSymbolAddress((void**)&attr1,  g_attr1);
    float* attr2;  cudaGetSymbolAddress((void**)&attr2,  g_attr2);
    float* logits; cudaGetSymbolAddress((void**)&logits, g_logits);
    float* cmax;   cudaGetSymbolAddress((void**)&cmax,   g_cmax);
    float* csum;   cudaGetSymbolAddress((void**)&csum,   g_csum);
    float* bpack;  cudaGetSymbolAddress((void**)&bpack,  g_bih_pack);
    __nv_bfloat16* Whi; cudaGetSymbolAddress((void**)&Whi, g_Whi);
    __nv_bfloat16* Wlo; cudaGetSymbolAddress((void**)&Wlo, g_Wlo);
    __nv_bfloat16* Ahi; cudaGetSymbolAddress((void**)&Ahi, g_Ahi);
    __nv_bfloat16* Alo; cudaGetSymbolAddress((void**)&Alo, g_Alo);
    __nv_bfloat16* w3hi; cudaGetSymbolAddress((void**)&w3hi, g_w3hi);
    __nv_bfloat16* w3lo; cudaGetSymbolAddress((void**)&w3lo, g_w3lo);
    float* fc2p;   cudaGetSymbolAddress((void**)&fc2p,   g_fc2part);
    int* rmin;     cudaGetSymbolAddress((void**)&rmin,   g_rmin);
    int* rmout;    cudaGetSymbolAddress((void**)&rmout,  g_rmout);
    int* cnt;      cudaGetSymbolAddress((void**)&cnt,    g_count);
    int* mnz;      cudaGetSymbolAddress((void**)&mnz,    g_mnz);

    build_maps<<<1, 64>>>(batch_att, rmin, rmout, cnt, mnz);
    pack_wih_bf16<<<(GI_W * D / 4 + 255) / 256, 256>>>(gru_wih_f, gru_wih_b,
                                                       gru_bih_f, gru_bih_b,
                                                       Whi, Wlo, bpack);
    split_w3_bf16<<<(256 * 512 / 2 + 255) / 256, 256>>>(fc3_w, w3hi, w3lo);
    conv_feats<<<B * T, 128>>>(batch_features, rmin, mnz, Ahi, Alo);

    // GI projection (bf16 3-split, 128x96 tiles, single-buffer, no pipelining)
    {
        dim3 grid(GI_W / 96, (B * T) / 128);   // (16, 16); ~half exit early
        gemm_bf16_gi<<<grid, 256>>>(Ahi, Alo, Whi, Wlo, bpack, GI, rmout, mnz);
    }

    // GRU recurrence
    {
        int smem = (12 * 65 + 64 * 65) * (int)sizeof(float4);
        cudaFuncSetAttribute(gru_kernel, cudaFuncAttributeMaxDynamicSharedMemorySize, smem);
        gru_kernel<<<GRU_BLOCKS, 256, smem>>>(GI, gru_whh_f, gru_whh_b,
                                              gru_bhh_f, gru_bhh_b, bpack, cnt, feats);
    }

    // semantic net
    gemm_tn<true><<<dim3(4096 / 64, 1), 256>>>(batch_attrs, A_, fc1_w, A_, fc1_b,
                                               attr1, 4096, C, 4096, A_);
    fc2_part<<<dim3(8, 4), 256>>>(attr1, fc2_w, fc2p);
    fc2_reduce<<<(C * 512 + 255) / 256, 256>>>(fc2p, fc2_b, attr2);

    // relation head (bf16 3-split, proven)
    relation_bf16<<<dim3(C / 2, B), 256>>>(feats, attr2, w3hi, w3lo,
                                           fc3_b, fc4_w, fc4_b, logits);

    softmax_colreduce<<<T, 256>>>(logits, cmax, csum);
    softmax_out<<<(B * C + 255) / 256, 256>>>(logits, cmax, csum, out);
}

// round 16
// speedup vs baseline: 1.1930x; 1.0116x over previous
#include <cuda_runtime.h>
#include <cuda_bf16.h>
#include <math.h>
#include <stdint.h>

#define B    64
#define T    32
#define D    4096
#define C    50
#define A_   300
#define H    256
#define GI_W 1536

// ---------------------------------------------------------------------------
// Scratch
// ---------------------------------------------------------------------------
__device__ float g_GI[B * T * GI_W];
__device__ float g_feats[B * T * 512];
__device__ float g_attr1[C * 4096];
__device__ float g_attr2[C * 512];
__device__ float g_logits[B * C * T];
__device__ float g_cmax[T];
__device__ float g_csum[T];
__device__ float g_hbuf[2 * 2 * B * H];
__device__ float g_bih_pack[GI_W];
__device__ __nv_bfloat16 g_Whi[GI_W * D];
__device__ __nv_bfloat16 g_Wlo[GI_W * D];
__device__ __nv_bfloat16 g_Ahi[B * T * D];
__device__ __nv_bfloat16 g_Alo[B * T * D];
__device__ __nv_bfloat16 g_w3hi[256 * 512];
__device__ __nv_bfloat16 g_w3lo[256 * 512];
__device__ float g_fc2part[4 * 64 * 512];
__device__ int   g_rmin[B * T];
__device__ int   g_rmout[B * T];
__device__ int   g_count[B];
__device__ int   g_mnz[1];
__device__ int          g_bar_count2[2 * 32];   // per-direction, 128 B apart
__device__ unsigned int g_bar_gen2[2 * 32];

// ---------------------------------------------------------------------------
// bf16 / sync helpers (proven)
// ---------------------------------------------------------------------------
__device__ __forceinline__ void mma16(float* c, const uint32_t* a, const uint32_t* b)
{
    asm volatile(
        "mma.sync.aligned.m16n8k16.row.col.f32.bf16.bf16.f32 "
        "{%0,%1,%2,%3},{%4,%5,%6,%7},{%8,%9},{%0,%1,%2,%3};"
        : "+f"(c[0]), "+f"(c[1]), "+f"(c[2]), "+f"(c[3])
        : "r"(a[0]), "r"(a[1]), "r"(a[2]), "r"(a[3]), "r"(b[0]), "r"(b[1]));
}

__device__ __forceinline__ void bsplit2(float x, float y, uint32_t& hw, uint32_t& lw)
{
    __nv_bfloat16 hx = __float2bfloat16(x);
    __nv_bfloat16 hy = __float2bfloat16(y);
    float rx = x - __bfloat162float(hx);
    float ry = y - __bfloat162float(hy);
    __nv_bfloat162 hp; hp.x = hx; hp.y = hy;
    __nv_bfloat162 lp; lp.x = __float2bfloat16(rx); lp.y = __float2bfloat16(ry);
    hw = *reinterpret_cast<uint32_t*>(&hp);
    lw = *reinterpret_cast<uint32_t*>(&lp);
}

__device__ __forceinline__ unsigned ld_acq(const unsigned* p)
{
    unsigned v;
    asm volatile("ld.acquire.gpu.u32 %0,[%1];" : "=r"(v) : "l"(p) : "memory");
    return v;
}
__device__ __forceinline__ void st_rel(unsigned* p, unsigned v)
{
    asm volatile("st.release.gpu.u32 [%0],%1;" :: "l"(p), "r"(v) : "memory");
}

// ---------------------------------------------------------------------------
// 0a) Pack GRU input weights to bf16 hi/lo + fp32 bias (proven)
// ---------------------------------------------------------------------------
__global__ __launch_bounds__(256) void pack_wih_bf16(
    const float* __restrict__ wf, const float* __restrict__ wb,
    const float* __restrict__ bf, const float* __restrict__ bb,
    __nv_bfloat16* __restrict__ whi, __nv_bfloat16* __restrict__ wlo,
    float* __restrict__ bp)
{
    int i = blockIdx.x * 256 + threadIdx.x;
    const int TOT4 = GI_W * D / 4;
    if (i < TOT4) {
        int row = (i * 4) / D;
        float4 v = (row < 768) ? ((const float4*)wf)[i]
                               : ((const float4*)wb)[i - 768 * (D / 4)];
        uint32_t h0, l0, h1, l1;
        bsplit2(v.x, v.y, h0, l0);
        bsplit2(v.z, v.w, h1, l1);
        ((uint2*)whi)[i] = make_uint2(h0, h1);
        ((uint2*)wlo)[i] = make_uint2(l0, l1);
    }
    if (i < GI_W) bp[i] = (i < 768) ? bf[i] : bb[i - 768];
}

// 0b) Pre-split w3 to bf16 hi/lo (proven)
__global__ __launch_bounds__(256) void split_w3_bf16(
    const float* __restrict__ w3,
    __nv_bfloat16* __restrict__ hh, __nv_bfloat16* __restrict__ ll)
{
    int i = blockIdx.x * 256 + threadIdx.x;
    if (i < 256 * 512 / 2) {
        float2 v = ((const float2*)w3)[i];
        uint32_t h, l;
        bsplit2(v.x, v.y, h, l);
        ((uint32_t*)hh)[i] = h;
        ((uint32_t*)ll)[i] = l;
    }
}

// ---------------------------------------------------------------------------
// 1) Bookkeeping (proven)
// ---------------------------------------------------------------------------
__global__ void build_maps(
    const float* __restrict__ att,
    int* __restrict__ rmin, int* __restrict__ rmout,
    int* __restrict__ count, int* __restrict__ mnz)
{
    __shared__ int cnts[B], offs[B];
    int b = threadIdx.x;
    float a[T];
    float s = 0.f;
#pragma unroll
    for (int t = 0; t < T; t++) { a[t] = att[b * T + t]; s += a[t]; }
    float thr = s / (float)T;
    int ord[T];
    int c = 0;
#pragma unroll
    for (int t = 0; t < T; t++) if (a[t] >= thr) ord[c++] = t;
    cnts[b] = c;
    __syncthreads();
    if (b == 0) {
        int acc = 0;
        for (int i = 0; i < B; i++) { offs[i] = acc; acc += cnts[i]; }
        *mnz = acc;
    }
    __syncthreads();
    int o = offs[b];
    for (int s2 = 0; s2 < c; s2++) {
        rmin[o + s2]  = b * T + ord[s2];
        rmout[o + s2] = b * T + s2;
    }
    count[b] = c;
}

// ---------------------------------------------------------------------------
// 1b) Gather + convert selected rows (proven; zero-fills all 2048 rows)
// ---------------------------------------------------------------------------
__global__ __launch_bounds__(128) void conv_feats(
    const float* __restrict__ bf,
    const int* __restrict__ rmin, const int* __restrict__ mnzp,
    __nv_bfloat16* __restrict__ Ahi, __nv_bfloat16* __restrict__ Alo)
{
    int i = blockIdx.x;
    int tid = threadIdx.x;
    int Mnz = *mnzp;
    uint2* oh = (uint2*)(Ahi + (size_t)i * D);
    uint2* ol = (uint2*)(Alo + (size_t)i * D);
    if (i < Mnz) {
        const float4* src = (const float4*)(bf + (size_t)rmin[i] * D);
        for (int j = tid; j < D / 4; j += 128) {
            float4 v = src[j];
            uint32_t h0, l0, h1, l1;
            bsplit2(v.x, v.y, h0, l0);
            bsplit2(v.z, v.w, h1, l1);
            oh[j] = make_uint2(h0, h1);
            ol[j] = make_uint2(l0, l1);
        }
    } else {
        uint2 z = make_uint2(0u, 0u);
        for (int j = tid; j < D / 4; j += 128) { oh[j] = z; ol[j] = z; }
    }
}

// ---------------------------------------------------------------------------
// 2) GI projection: bf16 3-split, 128x96 tiles (R14-proven, byte-identical)
// ---------------------------------------------------------------------------
__global__ __launch_bounds__(256, 2) void gemm_bf16_gi(
    const __nv_bfloat16* __restrict__ Ahi, const __nv_bfloat16* __restrict__ Alo,
    const __nv_bfloat16* __restrict__ Whi, const __nv_bfloat16* __restrict__ Wlo,
    const float* __restrict__ bias,
    float* __restrict__ Cg,
    const int* __restrict__ rmout,
    const int* __restrict__ mnzp)
{
    int Mnz = *mnzp;
    int row0 = blockIdx.y * 128, col0 = blockIdx.x * 96;
    if (row0 >= Mnz) return;

    __shared__ uint32_t Ah_s[128 * 12], Al_s[128 * 12];
    __shared__ uint32_t Wh_s[96 * 12],  Wl_s[96 * 12];

    int tid  = threadIdx.x;
    int lane = tid & 31, warp = tid >> 5;
    int wm = warp >> 1, wn = warp & 1;     // warp tile 32(M) x 48(N)
    int g  = lane >> 2, tg = lane & 3;

    float c[2][6][4];
#pragma unroll
    for (int mt = 0; mt < 2; mt++)
#pragma unroll
        for (int nt = 0; nt < 6; nt++)
#pragma unroll
            for (int r = 0; r < 4; r++) c[mt][nt][r] = 0.f;

    int lr = tid >> 1;            // 0..127 (A row)
    int hf = tid & 1;             // k half (8 bf16)
    const __nv_bfloat16* arh = Ahi + (size_t)(row0 + lr) * D;
    const __nv_bfloat16* arl = Alo + (size_t)(row0 + lr) * D;
    int wr = (tid < 192) ? (tid >> 1) : 0;   // W row 0..95
    const __nv_bfloat16* wrh = Whi + (size_t)(col0 + wr) * D;
    const __nv_bfloat16* wrl = Wlo + (size_t)(col0 + wr) * D;

    for (int k0 = 0; k0 < D; k0 += 16) {
        int off = lr * 12 + hf * 4;
        *(uint4*)&Ah_s[off] = ((const uint4*)(arh + k0))[hf];
        *(uint4*)&Al_s[off] = ((const uint4*)(arl + k0))[hf];
        if (tid < 192) {
            int woff = wr * 12 + hf * 4;
            *(uint4*)&Wh_s[woff] = ((const uint4*)(wrh + k0))[hf];
            *(uint4*)&Wl_s[woff] = ((const uint4*)(wrl + k0))[hf];
        }
        __syncthreads();

        uint32_t a_h[2][4], a_l[2][4];
#pragma unroll
        for (int mt = 0; mt < 2; mt++) {
            int m0 = wm * 32 + mt * 16;
            a_h[mt][0] = Ah_s[(m0 + g) * 12 + tg];
            a_h[mt][1] = Ah_s[(m0 + g + 8) * 12 + tg];
            a_h[mt][2] = Ah_s[(m0 + g) * 12 + tg + 4];
            a_h[mt][3] = Ah_s[(m0 + g + 8) * 12 + tg + 4];
            a_l[mt][0] = Al_s[(m0 + g) * 12 + tg];
            a_l[mt][1] = Al_s[(m0 + g + 8) * 12 + tg];
            a_l[mt][2] = Al_s[(m0 + g) * 12 + tg + 4];
            a_l[mt][3] = Al_s[(m0 + g + 8) * 12 + tg + 4];
        }
#pragma unroll
        for (int nt = 0; nt < 6; nt++) {
            int n0 = wn * 48 + nt * 8;
            uint32_t bh[2], bl[2];
            bh[0] = Wh_s[(n0 + g) * 12 + tg];
            bh[1] = Wh_s[(n0 + g) * 12 + tg + 4];
            bl[0] = Wl_s[(n0 + g) * 12 + tg];
            bl[1] = Wl_s[(n0 + g) * 12 + tg + 4];
#pragma unroll
            for (int mt = 0; mt < 2; mt++) {
                mma16(c[mt][nt], a_h[mt], bh);
                mma16(c[mt][nt], a_l[mt], bh);
                mma16(c[mt][nt], a_h[mt], bl);
            }
        }
        __syncthreads();
    }

#pragma unroll
    for (int mt = 0; mt < 2; mt++) {
        int mrow1 = row0 + wm * 32 + mt * 16 + g;
        int mrow2 = mrow1 + 8;
        int ro1 = (mrow1 < Mnz) ? rmout[mrow1] : -1;
        int ro2 = (mrow2 < Mnz) ? rmout[mrow2] : -1;
#pragma unroll
        for (int nt = 0; nt < 6; nt++) {
            int col = col0 + wn * 48 + nt * 8 + 2 * tg;
            float b0 = bias[col], b1 = bias[col + 1];
            if (ro1 >= 0)
                *(float2*)(Cg + (size_t)ro1 * GI_W + col) =
                    make_float2(c[mt][nt][0] + b0, c[mt][nt][1] + b1);
            if (ro2 >= 0)
                *(float2*)(Cg + (size_t)ro2 * GI_W + col) =
                    make_float2(c[mt][nt][2] + b0, c[mt][nt][3] + b1);
        }
    }
}

// ---------------------------------------------------------------------------
// 2b) Small-M GEMM (fc1) and fc2 K-split (proven)
// ---------------------------------------------------------------------------
template <bool RELU>
__global__ __launch_bounds__(256) void gemm_tn(
    const float* __restrict__ Ag, int lda,
    const float* __restrict__ Wg, int ldw,
    const float* __restrict__ bias,
    float* __restrict__ Cg, int ldc,
    int M, int N, int K)
{
    __shared__ float As[16][65];
    __shared__ float Ws[16][65];
    int tid  = threadIdx.x;
    int row0 = blockIdx.y * 64;
    int col0 = blockIdx.x * 64;
    int lm = tid >> 2;
    int lk = (tid & 3) * 4;
    int ty = tid >> 4;
    int tx = tid & 15;
    float acc[4][4];
#pragma unroll
    for (int i = 0; i < 4; i++)
#pragma unroll
        for (int j = 0; j < 4; j++) acc[i][j] = 0.f;

    for (int k0 = 0; k0 < K; k0 += 16) {
        int r = row0 + lm;
        int cc = col0 + lm;
#pragma unroll
        for (int i = 0; i < 4; i++) {
            int k = k0 + lk + i;
            As[lk + i][lm] = (r < M && k < K) ? Ag[(size_t)r * lda + k] : 0.f;
            Ws[lk + i][lm] = (cc < N && k < K) ? Wg[(size_t)cc * ldw + k] : 0.f;
        }
        __syncthreads();
#pragma unroll
        for (int kk = 0; kk < 16; kk++) {
            float a[4], w[4];
#pragma unroll
            for (int i = 0; i < 4; i++) a[i] = As[kk][ty + 16 * i];
#pragma unroll
            for (int j = 0; j < 4; j++) w[j] = Ws[kk][tx + 16 * j];
#pragma unroll
            for (int i = 0; i < 4; i++)
#pragma unroll
                for (int j = 0; j < 4; j++)
                    acc[i][j] = fmaf(a[i], w[j], acc[i][j]);
        }
        __syncthreads();
    }

#pragma unroll
    for (int i = 0; i < 4; i++) {
        int r = row0 + ty + 16 * i;
        if (r >= M) continue;
#pragma unroll
        for (int j = 0; j < 4; j++) {
            int cc = col0 + tx + 16 * j;
            if (cc >= N) continue;
            float v = acc[i][j] + bias[cc];
            if (RELU) v = fmaxf(v, 0.f);
            Cg[(size_t)r * ldc + cc] = v;
        }
    }
}

__global__ __launch_bounds__(256) void fc2_part(
    const float* __restrict__ Ag,
    const float* __restrict__ Wg,
    float* __restrict__ Pout)
{
    __shared__ float As[16][65];
    __shared__ float Ws[16][65];
    int tid  = threadIdx.x;
    int col0 = blockIdx.x * 64;
    int kbeg = blockIdx.y * 1024;
    int lm = tid >> 2;
    int lk = (tid & 3) * 4;
    int ty = tid >> 4;
    int tx = tid & 15;
    float acc[4][4];
#pragma unroll
    for (int i = 0; i < 4; i++)
#pragma unroll
        for (int j = 0; j < 4; j++) acc[i][j] = 0.f;

    for (int k0 = kbeg; k0 < kbeg + 1024; k0 += 16) {
        int cc = col0 + lm;
#pragma unroll
        for (int i = 0; i < 4; i++) {
            int k = k0 + lk + i;
            As[lk + i][lm] = (lm < C) ? Ag[(size_t)lm * 4096 + k] : 0.f;
            Ws[lk + i][lm] = Wg[(size_t)cc * 4096 + k];
        }
        __syncthreads();
#pragma unroll
        for (int kk = 0; kk < 16; kk++) {
            float a[4], w[4];
#pragma unroll
            for (int i = 0; i < 4; i++) a[i] = As[kk][ty + 16 * i];
#pragma unroll
            for (int j = 0; j < 4; j++) w[j] = Ws[kk][tx + 16 * j];
#pragma unroll
            for (int i = 0; i < 4; i++)
#pragma unroll
                for (int j = 0; j < 4; j++)
                    acc[i][j] = fmaf(a[i], w[j], acc[i][j]);
        }
        __syncthreads();
    }

    float* base = Pout + (size_t)blockIdx.y * (64 * 512);
#pragma unroll
    for (int i = 0; i < 4; i++) {
        int r = ty + 16 * i;
        if (r >= C) continue;
#pragma unroll
        for (int j = 0; j < 4; j++) {
            int cc = col0 + tx + 16 * j;
            base[(size_t)r * 512 + cc] = acc[i][j];
        }
    }
}

__global__ __launch_bounds__(256) void fc2_reduce(
    const float* __restrict__ P, const float* __restrict__ bias,
    float* __restrict__ attr2)
{
    int idx = blockIdx.x * 256 + threadIdx.x;
    if (idx < C * 512) {
        int r = idx >> 9, cc = idx & 511;
        float v = bias[cc];
#pragma unroll
        for (int kc = 0; kc < 4; kc++)
            v += P[(size_t)kc * (64 * 512) + r * 512 + cc];
        attr2[idx] = fmaxf(v, 0.f);
    }
}

// ---------------------------------------------------------------------------
// 3) GRU recurrence: per-direction barrier (64 arrivals each) + GI prefetch
//    hoisted before the barrier. Otherwise byte-identical to the proven R14.
// ---------------------------------------------------------------------------
#define GRU_BLOCKS 128

__device__ __forceinline__ void grid_barrier_dir(int d)
{
    __syncthreads();
    if (threadIdx.x == 0) {
        __threadfence();
        int* cnt = &g_bar_count2[d * 32];
        unsigned* gen = &g_bar_gen2[d * 32];
        unsigned g = ld_acq(gen);
        if (atomicAdd(cnt, 1) == 64 - 1) {
            *cnt = 0;
            st_rel(gen, g + 1);
        } else {
            while (ld_acq(gen) == g) { __nanosleep(16); }
        }
    }
    __syncthreads();
}

__global__ __launch_bounds__(256) void gru_kernel(
    const float* __restrict__ GI,
    const float* __restrict__ whh_f, const float* __restrict__ whh_b,
    const float* __restrict__ bhh_f, const float* __restrict__ bhh_b,
    const float* __restrict__ bpack,
    const int*   __restrict__ count,
    float* __restrict__ feats)
{
    extern __shared__ float4 sm4[];
    float4* sW4 = sm4;
    float4* hS4 = sm4 + 12 * 65;

    int d  = blockIdx.x >> 6;
    int hc = blockIdx.x & 63;
    int tid = threadIdx.x;
    int b = tid >> 2;
    int u = tid & 3;
    int i = hc * 4 + u;

    const float* whh = d ? whh_b : whh_f;
    const float* bhh = d ? bhh_b : bhh_f;

    for (int t = tid; t < 12 * 64; t += 256) {
        int rr = t >> 6;
        int k4 = t & 63;
        int g  = rr >> 2, uu = rr & 3;
        int row = g * H + hc * 4 + uu;
        sW4[rr * 65 + k4] = ((const float4*)(whh + (size_t)row * H))[k4];
    }
    float br = bhh[i], bz = bhh[H + i], bn = bhh[2 * H + i];
    float ir0 = bpack[d * 768 + i];
    float iz0 = bpack[d * 768 + 256 + i];
    float in0 = bpack[d * 768 + 512 + i];
    int cnt_b = count[b];
    __syncthreads();

    float h = 0.f;

    // preload GI for t = 0 (GI is constant input — always safe to read early)
    float ir, iz, in_;
    {
        int s0 = d ? (T - 1) : 0;
        if (s0 < cnt_b) {
            const float* gi = GI + ((size_t)b * T + s0) * GI_W + d * 768;
            ir = gi[i]; iz = gi[H + i]; in_ = gi[2 * H + i];
        } else { ir = ir0; iz = iz0; in_ = in0; }
    }

    for (int t = 0; t < T; t++) {
        float ar = 0.f, az = 0.f, an = 0.f;
        if (t > 0) {
            int p = t & 1;
            const float4* hp4 = (const float4*)(g_hbuf + p * (2 * B * H) + d * (B * H));
            for (int idx = tid; idx < B * (H / 4); idx += 256)
                hS4[(idx >> 6) * 65 + (idx & 63)] = __ldcg(&hp4[idx]);
            __syncthreads();

            const float4* hb = &hS4[b * 65];
            const float4* wr = &sW4[(0 + u) * 65];
            const float4* wz = &sW4[(4 + u) * 65];
            const float4* wn = &sW4[(8 + u) * 65];
#pragma unroll 16
            for (int k4 = 0; k4 < 64; k4++) {
                float4 hv = hb[k4];
                float4 a  = wr[k4];
                ar = fmaf(hv.x, a.x, fmaf(hv.y, a.y, fmaf(hv.z, a.z, fmaf(hv.w, a.w, ar))));
                float4 zz = wz[k4];
                az = fmaf(hv.x, zz.x, fmaf(hv.y, zz.y, fmaf(hv.z, zz.z, fmaf(hv.w, zz.w, az))));
                float4 nn = wn[k4];
                an = fmaf(hv.x, nn.x, fmaf(hv.y, nn.y, fmaf(hv.z, nn.z, fmaf(hv.w, nn.w, an))));
            }
        }

        int s = d ? (T - 1 - t) : t;
        float r = 1.f / (1.f + expf(-(ir + ar + br)));
        float z = 1.f / (1.f + expf(-(iz + az + bz)));
        float n = tanhf(in_ + r * (an + bn));
        h = (1.f - z) * n + z * h;

        feats[((size_t)b * T + s) * 512 + d * H + i] = h;
        if (t < T - 1) {
            g_hbuf[((t & 1) ^ 1) * (2 * B * H) + d * (B * H) + b * H + i] = h;
            // prefetch GI for t+1 BEFORE the barrier (hidden under the wait)
            int s2 = d ? (T - 2 - t) : (t + 1);
            if (s2 < cnt_b) {
                const float* gi = GI + ((size_t)b * T + s2) * GI_W + d * 768;
                ir = gi[i]; iz = gi[H + i]; in_ = gi[2 * H + i];
            } else { ir = ir0; iz = iz0; in_ = in0; }
            grid_barrier_dir(d);
        }
    }
}

// ---------------------------------------------------------------------------
// 4) Relation head, bf16 3-split tensor cores (proven, byte-identical)
// ---------------------------------------------------------------------------
__global__ __launch_bounds__(256, 2) void relation_bf16(
    const float* __restrict__ feats,
    const float* __restrict__ attr2,
    const __nv_bfloat16* __restrict__ w3hi,
    const __nv_bfloat16* __restrict__ w3lo,
    const float* __restrict__ b3,
    const float* __restrict__ w4,
    const float* __restrict__ b4,
    float* __restrict__ logits)
{
    __shared__ uint32_t Dh_s[64 * 12], Dl_s[64 * 12];
    __shared__ uint32_t Wh_s[256 * 12], Wl_s[256 * 12];
    __shared__ float aS[2 * 512];
    __shared__ float part[64][5];

    int c0 = blockIdx.x * 2;
    int b  = blockIdx.y;
    int tid  = threadIdx.x;
    int lane = tid & 31, warp = tid >> 5;
    int wm = warp >> 2, wn = warp & 3;
    int g  = lane >> 2, tg = lane & 3;

    for (int t = tid; t < 1024; t += 256)
        aS[t] = attr2[(size_t)(c0 + (t >> 9)) * 512 + (t & 511)];
    __syncthreads();

    float c[2][8][4];
#pragma unroll
    for (int mt = 0; mt < 2; mt++)
#pragma unroll
        for (int nt = 0; nt < 8; nt++)
#pragma unroll
            for (int r = 0; r < 4; r++) c[mt][nt][r] = 0.f;

    int dm = tid >> 2;
    int dk = (tid & 3) * 4;
    int ds = dm & 31, dc = dm >> 5;
    const float* frow = feats + ((size_t)b * T + ds) * 512;
    const __nv_bfloat16* w3h_row = w3hi + (size_t)tid * 512;
    const __nv_bfloat16* w3l_row = w3lo + (size_t)tid * 512;

    for (int k0 = 0; k0 < 512; k0 += 16) {
        {
            float4 f = *(const float4*)(frow + k0 + dk);
            float4 a = *(const float4*)(aS + dc * 512 + k0 + dk);
            float d0 = f.x - a.x, d1 = f.y - a.y;
            float d2 = f.z - a.z, d3 = f.w - a.w;
            uint32_t h0, l0, h1, l1;
            bsplit2(d0 * d0, d1 * d1, h0, l0);
            bsplit2(d2 * d2, d3 * d3, h1, l1);
            int w = (tid & 3) * 2;
            Dh_s[dm * 12 + w]     = h0;
            Dh_s[dm * 12 + w + 1] = h1;
            Dl_s[dm * 12 + w]     = l0;
            Dl_s[dm * 12 + w + 1] = l1;
        }
        {
            uint4 wh0 = ((const uint4*)(w3h_row + k0))[0];
            uint4 wh1 = ((const uint4*)(w3h_row + k0))[1];
            uint4 wl0 = ((const uint4*)(w3l_row + k0))[0];
            uint4 wl1 = ((const uint4*)(w3l_row + k0))[1];
            *(uint4*)&Wh_s[tid * 12 + 0] = wh0;
            *(uint4*)&Wh_s[tid * 12 + 4] = wh1;
            *(uint4*)&Wl_s[tid * 12 + 0] = wl0;
            *(uint4*)&Wl_s[tid * 12 + 4] = wl1;
        }
        __syncthreads();

        uint32_t a_h[2][4], a_l[2][4];
#pragma unroll
        for (int mt = 0; mt < 2; mt++) {
            int m0 = wm * 32 + mt * 16;
            a_h[mt][0] = Dh_s[(m0 + g) * 12 + tg];
            a_h[mt][1] = Dh_s[(m0 + g + 8) * 12 + tg];
            a_h[mt][2] = Dh_s[(m0 + g) * 12 + tg + 4];
            a_h[mt][3] = Dh_s[(m0 + g + 8) * 12 + tg + 4];
            a_l[mt][0] = Dl_s[(m0 + g) * 12 + tg];
            a_l[mt][1] = Dl_s[(m0 + g + 8) * 12 + tg];
            a_l[mt][2] = Dl_s[(m0 + g) * 12 + tg + 4];
            a_l[mt][3] = Dl_s[(m0 + g + 8) * 12 + tg + 4];
        }
#pragma unroll
        for (int nt = 0; nt < 8; nt++) {
            int n0 = wn * 64 + nt * 8;
            uint32_t bh[2], bl[2];
            bh[0] = Wh_s[(n0 + g) * 12 + tg];
            bh[1] = Wh_s[(n0 + g) * 12 + tg + 4];
            bl[0] = Wl_s[(n0 + g) * 12 + tg];
            bl[1] = Wl_s[(n0 + g) * 12 + tg + 4];
#pragma unroll
            for (int mt = 0; mt < 2; mt++) {
                mma16(c[mt][nt], a_h[mt], bh);
                mma16(c[mt][nt], a_l[mt], bh);
                mma16(c[mt][nt], a_h[mt], bl);
            }
        }
        __syncthreads();
    }

    float rs[2][2] = {{0.f, 0.f}, {0.f, 0.f}};
#pragma unroll
    for (int nt = 0; nt < 8; nt++) {
        int col = wn * 64 + nt * 8 + 2 * tg;
        float w40 = w4[col], w41 = w4[col + 1];
        float b30 = b3[col], b31 = b3[col + 1];
#pragma unroll
        for (int mt = 0; mt < 2; mt++) {
            rs[mt][0] += fmaxf(c[mt][nt][0] + b30, 0.f) * w40
                       + fmaxf(c[mt][nt][1] + b31, 0.f) * w41;
            rs[mt][1] += fmaxf(c[mt][nt][2] + b30, 0.f) * w40
                       + fmaxf(c[mt][nt][3] + b31, 0.f) * w41;
        }
    }
#pragma unroll
    for (int mt = 0; mt < 2; mt++)
#pragma unroll
        for (int hf2 = 0; hf2 < 2; hf2++) {
            float v = rs[mt][hf2];
            v += __shfl_xor_sync(0xffffffffu, v, 1);
            v += __shfl_xor_sync(0xffffffffu, v, 2);
            if (tg == 0)
                part[wm * 32 + mt * 16 + g + hf2 * 8][wn] = v;
        }
    __syncthreads();
    if (tid < 64) {
        float s = b4[0] + part[tid][0] + part[tid][1] + part[tid][2] + part[tid][3];
        int cc = c0 + (tid >> 5), ss = tid & 31;
        logits[((size_t)b * C + cc) * T + ss] = s;
    }
}

// ---------------------------------------------------------------------------
// 5) Softmax over dim-0 per column, mean over columns (proven)
// ---------------------------------------------------------------------------
__global__ __launch_bounds__(256) void softmax_colreduce(
    const float* __restrict__ logits, float* __restrict__ cmax, float* __restrict__ csum)
{
    int t = blockIdx.x;
    int tid = threadIdx.x;
    __shared__ float red[256];
    float m = -1e30f;
    for (int i = tid; i < B * C; i += 256) m = fmaxf(m, logits[(size_t)i * T + t]);
    red[tid] = m; __syncthreads();
    for (int s = 128; s > 0; s >>= 1) {
        if (tid < s) red[tid] = fmaxf(red[tid], red[tid + s]);
        __syncthreads();
    }
    float mx = red[0];
    __syncthreads();
    float sum = 0.f;
    for (int i = tid; i < B * C; i += 256) sum += expf(logits[(size_t)i * T + t] - mx);
    red[tid] = sum; __syncthreads();
    for (int s = 128; s > 0; s >>= 1) {
        if (tid < s) red[tid] += red[tid + s];
        __syncthreads();
    }
    if (tid == 0) { cmax[t] = mx; csum[t] = red[0]; }
}

__global__ __launch_bounds__(256) void softmax_out(
    const float* __restrict__ logits, const float* __restrict__ cmax,
    const float* __restrict__ csum, float* __restrict__ out)
{
    __shared__ float mS[T], sS[T];
    int tid = threadIdx.x;
    if (tid < T) { mS[tid] = cmax[tid]; sS[tid] = csum[tid]; }
    __syncthreads();
    int i = blockIdx.x * 256 + tid;
    if (i < B * C) {
        float a = 0.f;
        const float* row = logits + (size_t)i * T;
#pragma unroll
        for (int t = 0; t < T; t++) a += expf(row[t] - mS[t]) / sS[t];
        out[i] = a * (1.f / (float)T);
    }
}

// ---------------------------------------------------------------------------
// Launch
// ---------------------------------------------------------------------------
extern "C" void kernel_launch(void* const* d_in, const int* in_sizes, int n_in,
                              void* d_out, int out_size)
{
    const float* batch_features  = (const float*)d_in[0];
    const float* batch_att       = (const float*)d_in[1];
    const float* batch_attrs     = (const float*)d_in[2];
    const float* fc1_w = (const float*)d_in[3];
    const float* fc1_b = (const float*)d_in[4];
    const float* fc2_w = (const float*)d_in[5];
    const float* fc2_b = (const float*)d_in[6];
    const float* fc3_w = (const float*)d_in[7];
    const float* fc3_b = (const float*)d_in[8];
    const float* fc4_w = (const float*)d_in[9];
    const float* fc4_b = (const float*)d_in[10];
    const float* gru_wih_f = (const float*)d_in[11];
    const float* gru_whh_f = (const float*)d_in[12];
    const float* gru_bih_f = (const float*)d_in[13];
    const float* gru_bhh_f = (const float*)d_in[14];
    const float* gru_wih_b = (const float*)d_in[15];
    const float* gru_whh_b = (const float*)d_in[16];
    const float* gru_bih_b = (const float*)d_in[17];
    const float* gru_bhh_b = (const float*)d_in[18];
    float* out = (float*)d_out;

    float* GI;     cudaGetSymbolAddress((void**)&GI,     g_GI);
    float* feats;  cudaGetSymbolAddress((void**)&feats,  g_feats);
    float* attr1;  cudaGetSymbolAddress((void**)&attr1,  g_attr1);
    float* attr2;  cudaGetSymbolAddress((void**)&attr2,  g_attr2);
    float* logits; cudaGetSymbolAddress((void**)&logits, g_logits);
    float* cmax;   cudaGetSymbolAddress((void**)&cmax,   g_cmax);
    float* csum;   cudaGetSymbolAddress((void**)&csum,   g_csum);
    float* bpack;  cudaGetSymbolAddress((void**)&bpack,  g_bih_pack);
    __nv_bfloat16* Whi; cudaGetSymbolAddress((void**)&Whi, g_Whi);
    __nv_bfloat16* Wlo; cudaGetSymbolAddress((void**)&Wlo, g_Wlo);
    __nv_bfloat16* Ahi; cudaGetSymbolAddress((void**)&Ahi, g_Ahi);
    __nv_bfloat16* Alo; cudaGetSymbolAddress((void**)&Alo, g_Alo);
    __nv_bfloat16* w3hi; cudaGetSymbolAddress((void**)&w3hi, g_w3hi);
    __nv_bfloat16* w3lo; cudaGetSymbolAddress((void**)&w3lo, g_w3lo);
    float* fc2p;   cudaGetSymbolAddress((void**)&fc2p,   g_fc2part);
    int* rmin;     cudaGetSymbolAddress((void**)&rmin,   g_rmin);
    int* rmout;    cudaGetSymbolAddress((void**)&rmout,  g_rmout);
    int* cnt;      cudaGetSymbolAddress((void**)&cnt,    g_count);
    int* mnz;      cudaGetSymbolAddress((void**)&mnz,    g_mnz);

    build_maps<<<1, 64>>>(batch_att, rmin, rmout, cnt, mnz);
    pack_wih_bf16<<<(GI_W * D / 4 + 255) / 256, 256>>>(gru_wih_f, gru_wih_b,
                                                       gru_bih_f, gru_bih_b,
                                                       Whi, Wlo, bpack);
    split_w3_bf16<<<(256 * 512 / 2 + 255) / 256, 256>>>(fc3_w, w3hi, w3lo);
    conv_feats<<<B * T, 128>>>(batch_features, rmin, mnz, Ahi, Alo);

    // GI projection (bf16 3-split, 128x96 tiles — R14-proven)
    {
        dim3 grid(GI_W / 96, (B * T) / 128);   // (16, 16); ~half exit early
        gemm_bf16_gi<<<grid, 256>>>(Ahi, Alo, Whi, Wlo, bpack, GI, rmout, mnz);
    }

    // GRU recurrence (per-direction barrier + GI prefetch)
    {
        int smem = (12 * 65 + 64 * 65) * (int)sizeof(float4);
        cudaFuncSetAttribute(gru_kernel, cudaFuncAttributeMaxDynamicSharedMemorySize, smem);
        gru_kernel<<<GRU_BLOCKS, 256, smem>>>(GI, gru_whh_f, gru_whh_b,
                                              gru_bhh_f, gru_bhh_b, bpack, cnt, feats);
    }

    // semantic net
    gemm_tn<true><<<dim3(4096 / 64, 1), 256>>>(batch_attrs, A_, fc1_w, A_, fc1_b,
                                               attr1, 4096, C, 4096, A_);
    fc2_part<<<dim3(8, 4), 256>>>(attr1, fc2_w, fc2p);
    fc2_reduce<<<(C * 512 + 255) / 256, 256>>>(fc2p, fc2_b, attr2);

    // relation head (bf16 3-split, proven)
    relation_bf16<<<dim3(C / 2, B), 256>>>(feats, attr2, w3hi, w3lo,
                                           fc3_b, fc4_w, fc4_b, logits);

    softmax_colreduce<<<T, 256>>>(logits, cmax, csum);
    softmax_out<<<(B * C + 255) / 256, 256>>>(logits, cmax, csum, out);
}

// round 17
// speedup vs baseline: 1.2680x; 1.0628x over previous
#include <cuda_runtime.h>
#include <cuda_bf16.h>
#include <math.h>
#include <stdint.h>

#define B    64
#define T    32
#define D    4096
#define C    50
#define A_   300
#define H    256
#define GI_W 1536

// ---------------------------------------------------------------------------
// Scratch
// ---------------------------------------------------------------------------
__device__ float g_GI[B * T * GI_W];
__device__ float g_GIp[2][B * T * GI_W];    // K-split partials
__device__ float g_feats[B * T * 512];
__device__ float g_attr1[C * 4096];
__device__ float g_attr2[C * 512];
__device__ float g_logits[B * C * T];
__device__ float g_cmax[T];
__device__ float g_csum[T];
__device__ float g_hbuf[2 * 2 * B * H];
__device__ float g_bih_pack[GI_W];
__device__ __nv_bfloat16 g_Whi[GI_W * D];
__device__ __nv_bfloat16 g_Wlo[GI_W * D];
__device__ __nv_bfloat16 g_Ahi[B * T * D];
__device__ __nv_bfloat16 g_Alo[B * T * D];
__device__ __nv_bfloat16 g_w3hi[256 * 512];
__device__ __nv_bfloat16 g_w3lo[256 * 512];
__device__ float g_fc2part[4 * 64 * 512];
__device__ int   g_rmin[B * T];
__device__ int   g_rmout[B * T];
__device__ int   g_count[B];
__device__ int   g_mnz[1];
__device__ int          g_bar_count2[2 * 32];   // per-direction, 128 B apart
__device__ unsigned int g_bar_gen2[2 * 32];

// ---------------------------------------------------------------------------
// bf16 / sync helpers (proven)
// ---------------------------------------------------------------------------
__device__ __forceinline__ void mma16(float* c, const uint32_t* a, const uint32_t* b)
{
    asm volatile(
        "mma.sync.aligned.m16n8k16.row.col.f32.bf16.bf16.f32 "
        "{%0,%1,%2,%3},{%4,%5,%6,%7},{%8,%9},{%0,%1,%2,%3};"
        : "+f"(c[0]), "+f"(c[1]), "+f"(c[2]), "+f"(c[3])
        : "r"(a[0]), "r"(a[1]), "r"(a[2]), "r"(a[3]), "r"(b[0]), "r"(b[1]));
}

__device__ __forceinline__ void bsplit2(float x, float y, uint32_t& hw, uint32_t& lw)
{
    __nv_bfloat16 hx = __float2bfloat16(x);
    __nv_bfloat16 hy = __float2bfloat16(y);
    float rx = x - __bfloat162float(hx);
    float ry = y - __bfloat162float(hy);
    __nv_bfloat162 hp; hp.x = hx; hp.y = hy;
    __nv_bfloat162 lp; lp.x = __float2bfloat16(rx); lp.y = __float2bfloat16(ry);
    hw = *reinterpret_cast<uint32_t*>(&hp);
    lw = *reinterpret_cast<uint32_t*>(&lp);
}

__device__ __forceinline__ unsigned ld_acq(const unsigned* p)
{
    unsigned v;
    asm volatile("ld.acquire.gpu.u32 %0,[%1];" : "=r"(v) : "l"(p) : "memory");
    return v;
}
__device__ __forceinline__ void st_rel(unsigned* p, unsigned v)
{
    asm volatile("st.release.gpu.u32 [%0],%1;" :: "l"(p), "r"(v) : "memory");
}

// ---------------------------------------------------------------------------
// 0a) Pack GRU input weights to bf16 hi/lo + fp32 bias (proven)
// ---------------------------------------------------------------------------
__global__ __launch_bounds__(256) void pack_wih_bf16(
    const float* __restrict__ wf, const float* __restrict__ wb,
    const float* __restrict__ bf, const float* __restrict__ bb,
    __nv_bfloat16* __restrict__ whi, __nv_bfloat16* __restrict__ wlo,
    float* __restrict__ bp)
{
    int i = blockIdx.x * 256 + threadIdx.x;
    const int TOT4 = GI_W * D / 4;
    if (i < TOT4) {
        int row = (i * 4) / D;
        float4 v = (row < 768) ? ((const float4*)wf)[i]
                               : ((const float4*)wb)[i - 768 * (D / 4)];
        uint32_t h0, l0, h1, l1;
        bsplit2(v.x, v.y, h0, l0);
        bsplit2(v.z, v.w, h1, l1);
        ((uint2*)whi)[i] = make_uint2(h0, h1);
        ((uint2*)wlo)[i] = make_uint2(l0, l1);
    }
    if (i < GI_W) bp[i] = (i < 768) ? bf[i] : bb[i - 768];
}

// 0b) Pre-split w3 to bf16 hi/lo (proven)
__global__ __launch_bounds__(256) void split_w3_bf16(
    const float* __restrict__ w3,
    __nv_bfloat16* __restrict__ hh, __nv_bfloat16* __restrict__ ll)
{
    int i = blockIdx.x * 256 + threadIdx.x;
    if (i < 256 * 512 / 2) {
        float2 v = ((const float2*)w3)[i];
        uint32_t h, l;
        bsplit2(v.x, v.y, h, l);
        ((uint32_t*)hh)[i] = h;
        ((uint32_t*)ll)[i] = l;
    }
}

// ---------------------------------------------------------------------------
// 1) Bookkeeping (proven)
// ---------------------------------------------------------------------------
__global__ void build_maps(
    const float* __restrict__ att,
    int* __restrict__ rmin, int* __restrict__ rmout,
    int* __restrict__ count, int* __restrict__ mnz)
{
    __shared__ int cnts[B], offs[B];
    int b = threadIdx.x;
    float a[T];
    float s = 0.f;
#pragma unroll
    for (int t = 0; t < T; t++) { a[t] = att[b * T + t]; s += a[t]; }
    float thr = s / (float)T;
    int ord[T];
    int c = 0;
#pragma unroll
    for (int t = 0; t < T; t++) if (a[t] >= thr) ord[c++] = t;
    cnts[b] = c;
    __syncthreads();
    if (b == 0) {
        int acc = 0;
        for (int i = 0; i < B; i++) { offs[i] = acc; acc += cnts[i]; }
        *mnz = acc;
    }
    __syncthreads();
    int o = offs[b];
    for (int s2 = 0; s2 < c; s2++) {
        rmin[o + s2]  = b * T + ord[s2];
        rmout[o + s2] = b * T + s2;
    }
    count[b] = c;
}

// ---------------------------------------------------------------------------
// 1b) Gather + convert selected rows (proven; zero-fills all 2048 rows)
// ---------------------------------------------------------------------------
__global__ __launch_bounds__(128) void conv_feats(
    const float* __restrict__ bf,
    const int* __restrict__ rmin, const int* __restrict__ mnzp,
    __nv_bfloat16* __restrict__ Ahi, __nv_bfloat16* __restrict__ Alo)
{
    int i = blockIdx.x;
    int tid = threadIdx.x;
    int Mnz = *mnzp;
    uint2* oh = (uint2*)(Ahi + (size_t)i * D);
    uint2* ol = (uint2*)(Alo + (size_t)i * D);
    if (i < Mnz) {
        const float4* src = (const float4*)(bf + (size_t)rmin[i] * D);
        for (int j = tid; j < D / 4; j += 128) {
            float4 v = src[j];
            uint32_t h0, l0, h1, l1;
            bsplit2(v.x, v.y, h0, l0);
            bsplit2(v.z, v.w, h1, l1);
            oh[j] = make_uint2(h0, h1);
            ol[j] = make_uint2(l0, l1);
        }
    } else {
        uint2 z = make_uint2(0u, 0u);
        for (int j = tid; j < D / 4; j += 128) { oh[j] = z; ol[j] = z; }
    }
}

// ---------------------------------------------------------------------------
// 2) GI projection: bf16 3-split, 128x96 tiles, K-split x2 via blockIdx.z
//    (2 CTAs/SM co-residency hides the load latency). Loop body identical
//    to the proven R16 kernel; epilogue writes raw partials (fc2_part pattern).
// ---------------------------------------------------------------------------
__global__ __launch_bounds__(256, 2) void gemm_bf16_gi(
    const __nv_bfloat16* __restrict__ Ahi, const __nv_bfloat16* __restrict__ Alo,
    const __nv_bfloat16* __restrict__ Whi, const __nv_bfloat16* __restrict__ Wlo,
    float* __restrict__ Pg,            // [2][B*T*GI_W] partials
    const int* __restrict__ rmout,
    const int* __restrict__ mnzp)
{
    int Mnz = *mnzp;
    int row0 = blockIdx.y * 128, col0 = blockIdx.x * 96;
    if (row0 >= Mnz) return;
    int kz   = blockIdx.z;             // 0 or 1
    int kbeg = kz * (D / 2);
    int kend = kbeg + (D / 2);
    float* Pout = Pg + (size_t)kz * (B * T * GI_W);

    __shared__ uint32_t Ah_s[128 * 12], Al_s[128 * 12];
    __shared__ uint32_t Wh_s[96 * 12],  Wl_s[96 * 12];

    int tid  = threadIdx.x;
    int lane = tid & 31, warp = tid >> 5;
    int wm = warp >> 1, wn = warp & 1;     // warp tile 32(M) x 48(N)
    int g  = lane >> 2, tg = lane & 3;

    float c[2][6][4];
#pragma unroll
    for (int mt = 0; mt < 2; mt++)
#pragma unroll
        for (int nt = 0; nt < 6; nt++)
#pragma unroll
            for (int r = 0; r < 4; r++) c[mt][nt][r] = 0.f;

    int lr = tid >> 1;            // 0..127 (A row)
    int hf = tid & 1;             // k half (8 bf16)
    const __nv_bfloat16* arh = Ahi + (size_t)(row0 + lr) * D;
    const __nv_bfloat16* arl = Alo + (size_t)(row0 + lr) * D;
    int wr = (tid < 192) ? (tid >> 1) : 0;   // W row 0..95
    const __nv_bfloat16* wrh = Whi + (size_t)(col0 + wr) * D;
    const __nv_bfloat16* wrl = Wlo + (size_t)(col0 + wr) * D;

    for (int k0 = kbeg; k0 < kend; k0 += 16) {
        int off = lr * 12 + hf * 4;
        *(uint4*)&Ah_s[off] = ((const uint4*)(arh + k0))[hf];
        *(uint4*)&Al_s[off] = ((const uint4*)(arl + k0))[hf];
        if (tid < 192) {
            int woff = wr * 12 + hf * 4;
            *(uint4*)&Wh_s[woff] = ((const uint4*)(wrh + k0))[hf];
            *(uint4*)&Wl_s[woff] = ((const uint4*)(wrl + k0))[hf];
        }
        __syncthreads();

        uint32_t a_h[2][4], a_l[2][4];
#pragma unroll
        for (int mt = 0; mt < 2; mt++) {
            int m0 = wm * 32 + mt * 16;
            a_h[mt][0] = Ah_s[(m0 + g) * 12 + tg];
            a_h[mt][1] = Ah_s[(m0 + g + 8) * 12 + tg];
            a_h[mt][2] = Ah_s[(m0 + g) * 12 + tg + 4];
            a_h[mt][3] = Ah_s[(m0 + g + 8) * 12 + tg + 4];
            a_l[mt][0] = Al_s[(m0 + g) * 12 + tg];
            a_l[mt][1] = Al_s[(m0 + g + 8) * 12 + tg];
            a_l[mt][2] = Al_s[(m0 + g) * 12 + tg + 4];
            a_l[mt][3] = Al_s[(m0 + g + 8) * 12 + tg + 4];
        }
#pragma unroll
        for (int nt = 0; nt < 6; nt++) {
            int n0 = wn * 48 + nt * 8;
            uint32_t bh[2], bl[2];
            bh[0] = Wh_s[(n0 + g) * 12 + tg];
            bh[1] = Wh_s[(n0 + g) * 12 + tg + 4];
            bl[0] = Wl_s[(n0 + g) * 12 + tg];
            bl[1] = Wl_s[(n0 + g) * 12 + tg + 4];
#pragma unroll
            for (int mt = 0; mt < 2; mt++) {
                mma16(c[mt][nt], a_h[mt], bh);
                mma16(c[mt][nt], a_l[mt], bh);
                mma16(c[mt][nt], a_h[mt], bl);
            }
        }
        __syncthreads();
    }

#pragma unroll
    for (int mt = 0; mt < 2; mt++) {
        int mrow1 = row0 + wm * 32 + mt * 16 + g;
        int mrow2 = mrow1 + 8;
        int ro1 = (mrow1 < Mnz) ? rmout[mrow1] : -1;
        int ro2 = (mrow2 < Mnz) ? rmout[mrow2] : -1;
#pragma unroll
        for (int nt = 0; nt < 6; nt++) {
            int col = col0 + wn * 48 + nt * 8 + 2 * tg;
            if (ro1 >= 0)
                *(float2*)(Pout + (size_t)ro1 * GI_W + col) =
                    make_float2(c[mt][nt][0], c[mt][nt][1]);
            if (ro2 >= 0)
                *(float2*)(Pout + (size_t)ro2 * GI_W + col) =
                    make_float2(c[mt][nt][2], c[mt][nt][3]);
        }
    }
}

// K-split reduce: GI = P0 + P1 + bias (rows beyond count never read by GRU)
__global__ __launch_bounds__(256) void gi_reduce(
    const float* __restrict__ Pg, const float* __restrict__ bias,
    float* __restrict__ GI)
{
    int idx = blockIdx.x * 256 + threadIdx.x;
    const int TOT = B * T * GI_W;
    if (idx < TOT) {
        int col = idx % GI_W;
        GI[idx] = Pg[idx] + Pg[TOT + idx] + bias[col];
    }
}

// ---------------------------------------------------------------------------
// 2b) Small-M GEMM (fc1) and fc2 K-split (proven)
// ---------------------------------------------------------------------------
template <bool RELU>
__global__ __launch_bounds__(256) void gemm_tn(
    const float* __restrict__ Ag, int lda,
    const float* __restrict__ Wg, int ldw,
    const float* __restrict__ bias,
    float* __restrict__ Cg, int ldc,
    int M, int N, int K)
{
    __shared__ float As[16][65];
    __shared__ float Ws[16][65];
    int tid  = threadIdx.x;
    int row0 = blockIdx.y * 64;
    int col0 = blockIdx.x * 64;
    int lm = tid >> 2;
    int lk = (tid & 3) * 4;
    int ty = tid >> 4;
    int tx = tid & 15;
    float acc[4][4];
#pragma unroll
    for (int i = 0; i < 4; i++)
#pragma unroll
        for (int j = 0; j < 4; j++) acc[i][j] = 0.f;

    for (int k0 = 0; k0 < K; k0 += 16) {
        int r = row0 + lm;
        int cc = col0 + lm;
#pragma unroll
        for (int i = 0; i < 4; i++) {
            int k = k0 + lk + i;
            As[lk + i][lm] = (r < M && k < K) ? Ag[(size_t)r * lda + k] : 0.f;
            Ws[lk + i][lm] = (cc < N && k < K) ? Wg[(size_t)cc * ldw + k] : 0.f;
        }
        __syncthreads();
#pragma unroll
        for (int kk = 0; kk < 16; kk++) {
            float a[4], w[4];
#pragma unroll
            for (int i = 0; i < 4; i++) a[i] = As[kk][ty + 16 * i];
#pragma unroll
            for (int j = 0; j < 4; j++) w[j] = Ws[kk][tx + 16 * j];
#pragma unroll
            for (int i = 0; i < 4; i++)
#pragma unroll
                for (int j = 0; j < 4; j++)
                    acc[i][j] = fmaf(a[i], w[j], acc[i][j]);
        }
        __syncthreads();
    }

#pragma unroll
    for (int i = 0; i < 4; i++) {
        int r = row0 + ty + 16 * i;
        if (r >= M) continue;
#pragma unroll
        for (int j = 0; j < 4; j++) {
            int cc = col0 + tx + 16 * j;
            if (cc >= N) continue;
            float v = acc[i][j] + bias[cc];
            if (RELU) v = fmaxf(v, 0.f);
            Cg[(size_t)r * ldc + cc] = v;
        }
    }
}

__global__ __launch_bounds__(256) void fc2_part(
    const float* __restrict__ Ag,
    const float* __restrict__ Wg,
    float* __restrict__ Pout)
{
    __shared__ float As[16][65];
    __shared__ float Ws[16][65];
    int tid  = threadIdx.x;
    int col0 = blockIdx.x * 64;
    int kbeg = blockIdx.y * 1024;
    int lm = tid >> 2;
    int lk = (tid & 3) * 4;
    int ty = tid >> 4;
    int tx = tid & 15;
    float acc[4][4];
#pragma unroll
    for (int i = 0; i < 4; i++)
#pragma unroll
        for (int j = 0; j < 4; j++) acc[i][j] = 0.f;

    for (int k0 = kbeg; k0 < kbeg + 1024; k0 += 16) {
        int cc = col0 + lm;
#pragma unroll
        for (int i = 0; i < 4; i++) {
            int k = k0 + lk + i;
            As[lk + i][lm] = (lm < C) ? Ag[(size_t)lm * 4096 + k] : 0.f;
            Ws[lk + i][lm] = Wg[(size_t)cc * 4096 + k];
        }
        __syncthreads();
#pragma unroll
        for (int kk = 0; kk < 16; kk++) {
            float a[4], w[4];
#pragma unroll
            for (int i = 0; i < 4; i++) a[i] = As[kk][ty + 16 * i];
#pragma unroll
            for (int j = 0; j < 4; j++) w[j] = Ws[kk][tx + 16 * j];
#pragma unroll
            for (int i = 0; i < 4; i++)
#pragma unroll
                for (int j = 0; j < 4; j++)
                    acc[i][j] = fmaf(a[i], w[j], acc[i][j]);
        }
        __syncthreads();
    }

    float* base = Pout + (size_t)blockIdx.y * (64 * 512);
#pragma unroll
    for (int i = 0; i < 4; i++) {
        int r = ty + 16 * i;
        if (r >= C) continue;
#pragma unroll
        for (int j = 0; j < 4; j++) {
            int cc = col0 + tx + 16 * j;
            base[(size_t)r * 512 + cc] = acc[i][j];
        }
    }
}

__global__ __launch_bounds__(256) void fc2_reduce(
    const float* __restrict__ P, const float* __restrict__ bias,
    float* __restrict__ attr2)
{
    int idx = blockIdx.x * 256 + threadIdx.x;
    if (idx < C * 512) {
        int r = idx >> 9, cc = idx & 511;
        float v = bias[cc];
#pragma unroll
        for (int kc = 0; kc < 4; kc++)
            v += P[(size_t)kc * (64 * 512) + r * 512 + cc];
        attr2[idx] = fmaxf(v, 0.f);
    }
}

// ---------------------------------------------------------------------------
// 3) GRU recurrence (R16-proven: per-direction barrier + GI prefetch)
// ---------------------------------------------------------------------------
#define GRU_BLOCKS 128

__device__ __forceinline__ void grid_barrier_dir(int d)
{
    __syncthreads();
    if (threadIdx.x == 0) {
        __threadfence();
        int* cnt = &g_bar_count2[d * 32];
        unsigned* gen = &g_bar_gen2[d * 32];
        unsigned g = ld_acq(gen);
        if (atomicAdd(cnt, 1) == 64 - 1) {
            *cnt = 0;
            st_rel(gen, g + 1);
        } else {
            while (ld_acq(gen) == g) { __nanosleep(16); }
        }
    }
    __syncthreads();
}

__global__ __launch_bounds__(256) void gru_kernel(
    const float* __restrict__ GI,
    const float* __restrict__ whh_f, const float* __restrict__ whh_b,
    const float* __restrict__ bhh_f, const float* __restrict__ bhh_b,
    const float* __restrict__ bpack,
    const int*   __restrict__ count,
    float* __restrict__ feats)
{
    extern __shared__ float4 sm4[];
    float4* sW4 = sm4;
    float4* hS4 = sm4 + 12 * 65;

    int d  = blockIdx.x >> 6;
    int hc = blockIdx.x & 63;
    int tid = threadIdx.x;
    int b = tid >> 2;
    int u = tid & 3;
    int i = hc * 4 + u;

    const float* whh = d ? whh_b : whh_f;
    const float* bhh = d ? bhh_b : bhh_f;

    for (int t = tid; t < 12 * 64; t += 256) {
        int rr = t >> 6;
        int k4 = t & 63;
        int g  = rr >> 2, uu = rr & 3;
        int row = g * H + hc * 4 + uu;
        sW4[rr * 65 + k4] = ((const float4*)(whh + (size_t)row * H))[k4];
    }
    float br = bhh[i], bz = bhh[H + i], bn = bhh[2 * H + i];
    float ir0 = bpack[d * 768 + i];
    float iz0 = bpack[d * 768 + 256 + i];
    float in0 = bpack[d * 768 + 512 + i];
    int cnt_b = count[b];
    __syncthreads();

    float h = 0.f;

    float ir, iz, in_;
    {
        int s0 = d ? (T - 1) : 0;
        if (s0 < cnt_b) {
            const float* gi = GI + ((size_t)b * T + s0) * GI_W + d * 768;
            ir = gi[i]; iz = gi[H + i]; in_ = gi[2 * H + i];
        } else { ir = ir0; iz = iz0; in_ = in0; }
    }

    for (int t = 0; t < T; t++) {
        float ar = 0.f, az = 0.f, an = 0.f;
        if (t > 0) {
            int p = t & 1;
            const float4* hp4 = (const float4*)(g_hbuf + p * (2 * B * H) + d * (B * H));
            for (int idx = tid; idx < B * (H / 4); idx += 256)
                hS4[(idx >> 6) * 65 + (idx & 63)] = __ldcg(&hp4[idx]);
            __syncthreads();

            const float4* hb = &hS4[b * 65];
            const float4* wr = &sW4[(0 + u) * 65];
            const float4* wz = &sW4[(4 + u) * 65];
            const float4* wn = &sW4[(8 + u) * 65];
#pragma unroll 16
            for (int k4 = 0; k4 < 64; k4++) {
                float4 hv = hb[k4];
                float4 a  = wr[k4];
                ar = fmaf(hv.x, a.x, fmaf(hv.y, a.y, fmaf(hv.z, a.z, fmaf(hv.w, a.w, ar))));
                float4 zz = wz[k4];
                az = fmaf(hv.x, zz.x, fmaf(hv.y, zz.y, fmaf(hv.z, zz.z, fmaf(hv.w, zz.w, az))));
                float4 nn = wn[k4];
                an = fmaf(hv.x, nn.x, fmaf(hv.y, nn.y, fmaf(hv.z, nn.z, fmaf(hv.w, nn.w, an))));
            }
        }

        int s = d ? (T - 1 - t) : t;
        float r = 1.f / (1.f + expf(-(ir + ar + br)));
        float z = 1.f / (1.f + expf(-(iz + az + bz)));
        float n = tanhf(in_ + r * (an + bn));
        h = (1.f - z) * n + z * h;

        feats[((size_t)b * T + s) * 512 + d * H + i] = h;
        if (t < T - 1) {
            g_hbuf[((t & 1) ^ 1) * (2 * B * H) + d * (B * H) + b * H + i] = h;
            int s2 = d ? (T - 2 - t) : (t + 1);
            if (s2 < cnt_b) {
                const float* gi = GI + ((size_t)b * T + s2) * GI_W + d * 768;
                ir = gi[i]; iz = gi[H + i]; in_ = gi[2 * H + i];
            } else { ir = ir0; iz = iz0; in_ = in0; }
            grid_barrier_dir(d);
        }
    }
}

// ---------------------------------------------------------------------------
// 4) Relation head, bf16 3-split tensor cores (proven, byte-identical)
// ---------------------------------------------------------------------------
__global__ __launch_bounds__(256, 2) void relation_bf16(
    const float* __restrict__ feats,
    const float* __restrict__ attr2,
    const __nv_bfloat16* __restrict__ w3hi,
    const __nv_bfloat16* __restrict__ w3lo,
    const float* __restrict__ b3,
    const float* __restrict__ w4,
    const float* __restrict__ b4,
    float* __restrict__ logits)
{
    __shared__ uint32_t Dh_s[64 * 12], Dl_s[64 * 12];
    __shared__ uint32_t Wh_s[256 * 12], Wl_s[256 * 12];
    __shared__ float aS[2 * 512];
    __shared__ float part[64][5];

    int c0 = blockIdx.x * 2;
    int b  = blockIdx.y;
    int tid  = threadIdx.x;
    int lane = tid & 31, warp = tid >> 5;
    int wm = warp >> 2, wn = warp & 3;
    int g  = lane >> 2, tg = lane & 3;

    for (int t = tid; t < 1024; t += 256)
        aS[t] = attr2[(size_t)(c0 + (t >> 9)) * 512 + (t & 511)];
    __syncthreads();

    float c[2][8][4];
#pragma unroll
    for (int mt = 0; mt < 2; mt++)
#pragma unroll
        for (int nt = 0; nt < 8; nt++)
#pragma unroll
            for (int r = 0; r < 4; r++) c[mt][nt][r] = 0.f;

    int dm = tid >> 2;
    int dk = (tid & 3) * 4;
    int ds = dm & 31, dc = dm >> 5;
    const float* frow = feats + ((size_t)b * T + ds) * 512;
    const __nv_bfloat16* w3h_row = w3hi + (size_t)tid * 512;
    const __nv_bfloat16* w3l_row = w3lo + (size_t)tid * 512;

    for (int k0 = 0; k0 < 512; k0 += 16) {
        {
            float4 f = *(const float4*)(frow + k0 + dk);
            float4 a = *(const float4*)(aS + dc * 512 + k0 + dk);
            float d0 = f.x - a.x, d1 = f.y - a.y;
            float d2 = f.z - a.z, d3 = f.w - a.w;
            uint32_t h0, l0, h1, l1;
            bsplit2(d0 * d0, d1 * d1, h0, l0);
            bsplit2(d2 * d2, d3 * d3, h1, l1);
            int w = (tid & 3) * 2;
            Dh_s[dm * 12 + w]     = h0;
            Dh_s[dm * 12 + w + 1] = h1;
            Dl_s[dm * 12 + w]     = l0;
            Dl_s[dm * 12 + w + 1] = l1;
        }
        {
            uint4 wh0 = ((const uint4*)(w3h_row + k0))[0];
            uint4 wh1 = ((const uint4*)(w3h_row + k0))[1];
            uint4 wl0 = ((const uint4*)(w3l_row + k0))[0];
            uint4 wl1 = ((const uint4*)(w3l_row + k0))[1];
            *(uint4*)&Wh_s[tid * 12 + 0] = wh0;
            *(uint4*)&Wh_s[tid * 12 + 4] = wh1;
            *(uint4*)&Wl_s[tid * 12 + 0] = wl0;
            *(uint4*)&Wl_s[tid * 12 + 4] = wl1;
        }
        __syncthreads();

        uint32_t a_h[2][4], a_l[2][4];
#pragma unroll
        for (int mt = 0; mt < 2; mt++) {
            int m0 = wm * 32 + mt * 16;
            a_h[mt][0] = Dh_s[(m0 + g) * 12 + tg];
            a_h[mt][1] = Dh_s[(m0 + g + 8) * 12 + tg];
            a_h[mt][2] = Dh_s[(m0 + g) * 12 + tg + 4];
            a_h[mt][3] = Dh_s[(m0 + g + 8) * 12 + tg + 4];
            a_l[mt][0] = Dl_s[(m0 + g) * 12 + tg];
            a_l[mt][1] = Dl_s[(m0 + g + 8) * 12 + tg];
            a_l[mt][2] = Dl_s[(m0 + g) * 12 + tg + 4];
            a_l[mt][3] = Dl_s[(m0 + g + 8) * 12 + tg + 4];
        }
#pragma unroll
        for (int nt = 0; nt < 8; nt++) {
            int n0 = wn * 64 + nt * 8;
            uint32_t bh[2], bl[2];
            bh[0] = Wh_s[(n0 + g) * 12 + tg];
            bh[1] = Wh_s[(n0 + g) * 12 + tg + 4];
            bl[0] = Wl_s[(n0 + g) * 12 + tg];
            bl[1] = Wl_s[(n0 + g) * 12 + tg + 4];
#pragma unroll
            for (int mt = 0; mt < 2; mt++) {
                mma16(c[mt][nt], a_h[mt], bh);
                mma16(c[mt][nt], a_l[mt], bh);
                mma16(c[mt][nt], a_h[mt], bl);
            }
        }
        __syncthreads();
    }

    float rs[2][2] = {{0.f, 0.f}, {0.f, 0.f}};
#pragma unroll
    for (int nt = 0; nt < 8; nt++) {
        int col = wn * 64 + nt * 8 + 2 * tg;
        float w40 = w4[col], w41 = w4[col + 1];
        float b30 = b3[col], b31 = b3[col + 1];
#pragma unroll
        for (int mt = 0; mt < 2; mt++) {
            rs[mt][0] += fmaxf(c[mt][nt][0] + b30, 0.f) * w40
                       + fmaxf(c[mt][nt][1] + b31, 0.f) * w41;
            rs[mt][1] += fmaxf(c[mt][nt][2] + b30, 0.f) * w40
                       + fmaxf(c[mt][nt][3] + b31, 0.f) * w41;
        }
    }
#pragma unroll
    for (int mt = 0; mt < 2; mt++)
#pragma unroll
        for (int hf2 = 0; hf2 < 2; hf2++) {
            float v = rs[mt][hf2];
            v += __shfl_xor_sync(0xffffffffu, v, 1);
            v += __shfl_xor_sync(0xffffffffu, v, 2);
            if (tg == 0)
                part[wm * 32 + mt * 16 + g + hf2 * 8][wn] = v;
        }
    __syncthreads();
    if (tid < 64) {
        float s = b4[0] + part[tid][0] + part[tid][1] + part[tid][2] + part[tid][3];
        int cc = c0 + (tid >> 5), ss = tid & 31;
        logits[((size_t)b * C + cc) * T + ss] = s;
    }
}

// ---------------------------------------------------------------------------
// 5) Softmax over dim-0 per column, mean over columns (proven)
// ---------------------------------------------------------------------------
__global__ __launch_bounds__(256) void softmax_colreduce(
    const float* __restrict__ logits, float* __restrict__ cmax, float* __restrict__ csum)
{
    int t = blockIdx.x;
    int tid = threadIdx.x;
    __shared__ float red[256];
    float m = -1e30f;
    for (int i = tid; i < B * C; i += 256) m = fmaxf(m, logits[(size_t)i * T + t]);
    red[tid] = m; __syncthreads();
    for (int s = 128; s > 0; s >>= 1) {
        if (tid < s) red[tid] = fmaxf(red[tid], red[tid + s]);
        __syncthreads();
    }
    float mx = red[0];
    __syncthreads();
    float sum = 0.f;
    for (int i = tid; i < B * C; i += 256) sum += expf(logits[(size_t)i * T + t] - mx);
    red[tid] = sum; __syncthreads();
    for (int s = 128; s > 0; s >>= 1) {
        if (tid < s) red[tid] += red[tid + s];
        __syncthreads();
    }
    if (tid == 0) { cmax[t] = mx; csum[t] = red[0]; }
}

__global__ __launch_bounds__(256) void softmax_out(
    const float* __restrict__ logits, const float* __restrict__ cmax,
    const float* __restrict__ csum, float* __restrict__ out)
{
    __shared__ float mS[T], sS[T];
    int tid = threadIdx.x;
    if (tid < T) { mS[tid] = cmax[tid]; sS[tid] = csum[tid]; }
    __syncthreads();
    int i = blockIdx.x * 256 + tid;
    if (i < B * C) {
        float a = 0.f;
        const float* row = logits + (size_t)i * T;
#pragma unroll
        for (int t = 0; t < T; t++) a += expf(row[t] - mS[t]) / sS[t];
        out[i] = a * (1.f / (float)T);
    }
}

// ---------------------------------------------------------------------------
// Launch
// ---------------------------------------------------------------------------
extern "C" void kernel_launch(void* const* d_in, const int* in_sizes, int n_in,
                              void* d_out, int out_size)
{
    const float* batch_features  = (const float*)d_in[0];
    const float* batch_att       = (const float*)d_in[1];
    const float* batch_attrs     = (const float*)d_in[2];
    const float* fc1_w = (const float*)d_in[3];
    const float* fc1_b = (const float*)d_in[4];
    const float* fc2_w = (const float*)d_in[5];
    const float* fc2_b = (const float*)d_in[6];
    const float* fc3_w = (const float*)d_in[7];
    const float* fc3_b = (const float*)d_in[8];
    const float* fc4_w = (const float*)d_in[9];
    const float* fc4_b = (const float*)d_in[10];
    const float* gru_wih_f = (const float*)d_in[11];
    const float* gru_whh_f = (const float*)d_in[12];
    const float* gru_bih_f = (const float*)d_in[13];
    const float* gru_bhh_f = (const float*)d_in[14];
    const float* gru_wih_b = (const float*)d_in[15];
    const float* gru_whh_b = (const float*)d_in[16];
    const float* gru_bih_b = (const float*)d_in[17];
    const float* gru_bhh_b = (const float*)d_in[18];
    float* out = (float*)d_out;

    float* GI;     cudaGetSymbolAddress((void**)&GI,     g_GI);
    float* GIp;    cudaGetSymbolAddress((void**)&GIp,    g_GIp);
    float* feats;  cudaGetSymbolAddress((void**)&feats,  g_feats);
    float* attr1;  cudaGetSymbolAddress((void**)&attr1,  g_attr1);
    float* attr2;  cudaGetSymbolAddress((void**)&attr2,  g_attr2);
    float* logits; cudaGetSymbolAddress((void**)&logits, g_logits);
    float* cmax;   cudaGetSymbolAddress((void**)&cmax,   g_cmax);
    float* csum;   cudaGetSymbolAddress((void**)&csum,   g_csum);
    float* bpack;  cudaGetSymbolAddress((void**)&bpack,  g_bih_pack);
    __nv_bfloat16* Whi; cudaGetSymbolAddress((void**)&Whi, g_Whi);
    __nv_bfloat16* Wlo; cudaGetSymbolAddress((void**)&Wlo, g_Wlo);
    __nv_bfloat16* Ahi; cudaGetSymbolAddress((void**)&Ahi, g_Ahi);
    __nv_bfloat16* Alo; cudaGetSymbolAddress((void**)&Alo, g_Alo);
    __nv_bfloat16* w3hi; cudaGetSymbolAddress((void**)&w3hi, g_w3hi);
    __nv_bfloat16* w3lo; cudaGetSymbolAddress((void**)&w3lo, g_w3lo);
    float* fc2p;   cudaGetSymbolAddress((void**)&fc2p,   g_fc2part);
    int* rmin;     cudaGetSymbolAddress((void**)&rmin,   g_rmin);
    int* rmout;    cudaGetSymbolAddress((void**)&rmout,  g_rmout);
    int* cnt;      cudaGetSymbolAddress((void**)&cnt,    g_count);
    int* mnz;      cudaGetSymbolAddress((void**)&mnz,    g_mnz);

    build_maps<<<1, 64>>>(batch_att, rmin, rmout, cnt, mnz);
    pack_wih_bf16<<<(GI_W * D / 4 + 255) / 256, 256>>>(gru_wih_f, gru_wih_b,
                                                       gru_bih_f, gru_bih_b,
                                                       Whi, Wlo, bpack);
    split_w3_bf16<<<(256 * 512 / 2 + 255) / 256, 256>>>(fc3_w, w3hi, w3lo);
    conv_feats<<<B * T, 128>>>(batch_features, rmin, mnz, Ahi, Alo);

    // GI projection (bf16 3-split, 128x96 tiles, K-split x2 for 2 CTAs/SM)
    {
        dim3 grid(GI_W / 96, (B * T) / 128, 2);   // (16, 16, 2)
        gemm_bf16_gi<<<grid, 256>>>(Ahi, Alo, Whi, Wlo, GIp, rmout, mnz);
        gi_reduce<<<(B * T * GI_W + 255) / 256, 256>>>(GIp, bpack, GI);
    }

    // GRU recurrence (per-direction barrier + GI prefetch — R16-proven)
    {
        int smem = (12 * 65 + 64 * 65) * (int)sizeof(float4);
        cudaFuncSetAttribute(gru_kernel, cudaFuncAttributeMaxDynamicSharedMemorySize, smem);
        gru_kernel<<<GRU_BLOCKS, 256, smem>>>(GI, gru_whh_f, gru_whh_b,
                                              gru_bhh_f, gru_bhh_b, bpack, cnt, feats);
    }

    // semantic net
    gemm_tn<true><<<dim3(4096 / 64, 1), 256>>>(batch_attrs, A_, fc1_w, A_, fc1_b,
                                               attr1, 4096, C, 4096, A_);
    fc2_part<<<dim3(8, 4), 256>>>(attr1, fc2_w, fc2p);
    fc2_reduce<<<(C * 512 + 255) / 256, 256>>>(fc2p, fc2_b, attr2);

    // relation head (bf16 3-split, proven)
    relation_bf16<<<dim3(C / 2, B), 256>>>(feats, attr2, w3hi, w3lo,
                                           fc3_b, fc4_w, fc4_b, logits);

    softmax_colreduce<<<T, 256>>>(logits, cmax, csum);
    softmax_out<<<(B * C + 255) / 256, 256>>>(logits, cmax, csum, out);
}